// round 1
// baseline (speedup 1.0000x reference)
#include <cuda_runtime.h>
#include <cstdint>
#include <cstddef>

// ---------------------------------------------------------------------------
// MIDIMultiInstanceAttention  (B=8, N=512, D=1024, H=16, HD=64, NI=4)
// fp32 baseline: tiled SGEMMs + flash attention + fused gate epilogue
// ---------------------------------------------------------------------------

#define CB 8
#define CN 512
#define CD 1024
#define CH 16
#define CHD 64
#define CM 4096            // B*N
#define ATT_SCALE 0.125f   // HD^-0.5
#define INST_SCALE (0.125f / 16.0f)

// scratch (device globals: allocation-free rule)
__device__ __align__(16) float g_q [CM * CD];
__device__ __align__(16) float g_k [CM * CD];
__device__ __align__(16) float g_v [CM * CD];
__device__ __align__(16) float g_o [CM * CD];   // attention output [B,N,D]
__device__ __align__(16) float g_iq[CM * CD];
__device__ __align__(16) float g_ik[CM * CD];
__device__ __align__(16) float g_e2[4 * CD];    // emb[:4] @ Wik
__device__ float g_gacc[CM];                    // sum_m sigmoid(...)

// ---------------------------------------------------------------------------
// zero the gate accumulator (graph replays need re-zeroing every launch)
// ---------------------------------------------------------------------------
__global__ void zero_gacc_k() {
    int i = blockIdx.x * 256 + threadIdx.x;
    if (i < CM) g_gacc[i] = 0.0f;
}

// ---------------------------------------------------------------------------
// SGEMM: C[M=4096, 1024] = A[4096,1024] @ W[1024,1024] + bias
// 128x128x16 tile, 256 threads, 8x8 per-thread micro-tile.
// GATE: multiply A rows by (1 + gacc[row]/512) on load (final projection).
// ---------------------------------------------------------------------------
template <bool GATE>
__global__ __launch_bounds__(256) void gemm_k(
    const float* __restrict__ A, const float* __restrict__ W,
    const float* __restrict__ bias, float* __restrict__ C)
{
    __shared__ float As[16][132];   // [k][row], padded
    __shared__ float Bs[16][128];   // [k][col]

    const int tid = threadIdx.x;
    const int bm = blockIdx.y * 128;
    const int bn = blockIdx.x * 128;
    const int tr = (tid >> 4) << 3;   // 0..120
    const int tc = (tid & 15) << 3;   // 0..120

    float acc[8][8];
#pragma unroll
    for (int i = 0; i < 8; i++)
#pragma unroll
        for (int j = 0; j < 8; j++) acc[i][j] = 0.0f;

    // rows this thread loads are fixed across k-tiles -> hoist gate values
    float gv[2];
#pragma unroll
    for (int p = 0; p < 2; p++) {
        int row = (p * 256 + tid) >> 2;
        gv[p] = GATE ? (1.0f + g_gacc[bm + row] * (1.0f / 512.0f)) : 1.0f;
    }

    for (int kt = 0; kt < CD; kt += 16) {
#pragma unroll
        for (int p = 0; p < 2; p++) {
            int idx = p * 256 + tid;
            int row = idx >> 2;
            int c4  = (idx & 3) << 2;
            float4 va = *(const float4*)(A + (size_t)(bm + row) * CD + kt + c4);
            if (GATE) { va.x *= gv[p]; va.y *= gv[p]; va.z *= gv[p]; va.w *= gv[p]; }
            As[c4 + 0][row] = va.x;
            As[c4 + 1][row] = va.y;
            As[c4 + 2][row] = va.z;
            As[c4 + 3][row] = va.w;
        }
#pragma unroll
        for (int p = 0; p < 2; p++) {
            int idx = p * 256 + tid;
            int row = idx >> 5;
            int c4  = (idx & 31) << 2;
            *(float4*)&Bs[row][c4] =
                *(const float4*)(W + (size_t)(kt + row) * CD + bn + c4);
        }
        __syncthreads();

#pragma unroll
        for (int kk = 0; kk < 16; kk++) {
            float a[8], b[8];
            *(float4*)&a[0] = *(float4*)&As[kk][tr];
            *(float4*)&a[4] = *(float4*)&As[kk][tr + 4];
            *(float4*)&b[0] = *(float4*)&Bs[kk][tc];
            *(float4*)&b[4] = *(float4*)&Bs[kk][tc + 4];
#pragma unroll
            for (int i = 0; i < 8; i++)
#pragma unroll
                for (int j = 0; j < 8; j++)
                    acc[i][j] = fmaf(a[i], b[j], acc[i][j]);
        }
        __syncthreads();
    }

#pragma unroll
    for (int i = 0; i < 8; i++) {
        size_t crow = (size_t)(bm + tr + i);
#pragma unroll
        for (int j = 0; j < 8; j += 4) {
            float4 r;
            r.x = acc[i][j + 0] + bias[bn + tc + j + 0];
            r.y = acc[i][j + 1] + bias[bn + tc + j + 1];
            r.z = acc[i][j + 2] + bias[bn + tc + j + 2];
            r.w = acc[i][j + 3] + bias[bn + tc + j + 3];
            *(float4*)(C + crow * CD + bn + tc + j) = r;
        }
    }
}

// ---------------------------------------------------------------------------
// per-head RMSNorm over contiguous 64-element chunks of [B,N,D]
// one warp per (b,n,h) group
// ---------------------------------------------------------------------------
__global__ void rms_k(float* __restrict__ t, const float* __restrict__ w) {
    int g    = (blockIdx.x * blockDim.x + threadIdx.x) >> 5;
    int lane = threadIdx.x & 31;
    float* p = t + (size_t)g * 64;
    float a = p[lane];
    float b = p[lane + 32];
    float ss = fmaf(a, a, b * b);
#pragma unroll
    for (int off = 16; off; off >>= 1)
        ss += __shfl_xor_sync(0xffffffffu, ss, off);
    float sc = rsqrtf(ss * (1.0f / 64.0f) + 1e-6f);
    p[lane]      = a * sc * w[lane];
    p[lane + 32] = b * sc * w[lane + 32];
}

// ---------------------------------------------------------------------------
// grouped flash attention.
// grid: (q-tile 8, b 8, h 16). block 256 threads, 64q x 64k chunk, 4x4 tiles.
// queries of batch b attend over keys of batches [4*(b/4) .. 4*(b/4)+3].
// K smem buffer is reused for P (fits 48KB static smem exactly).
// ---------------------------------------------------------------------------
__global__ __launch_bounds__(256) void attn_k(
    const float* __restrict__ q, const float* __restrict__ k,
    const float* __restrict__ v, float* __restrict__ o)
{
    __shared__ float QsT[64 * 64];   // [dim][query]
    __shared__ float KP [64 * 64];   // KsT [dim][key], then P [row][col]
    __shared__ float Vs [64 * 64];   // [key][dim]

    const int bq  = blockIdx.y;
    const int h   = blockIdx.z;
    const int n0  = blockIdx.x * 64;
    const int tid = threadIdx.x;
    const int r0  = (tid >> 4) << 2;  // query row base (4 rows)
    const int c0  = (tid & 15) << 2;  // key-col / out-dim base (4)

    // load Q tile transposed: [dim][query]
    {
        const int nl = tid & 63;
        const int db = (tid >> 6) << 4;
        const float* qp = q + ((size_t)(bq * CN + n0 + nl)) * CD + h * CHD + db;
#pragma unroll
        for (int it = 0; it < 4; it++) {
            float4 t4 = *(const float4*)(qp + it * 4);
            QsT[(db + it * 4 + 0) * 64 + nl] = t4.x;
            QsT[(db + it * 4 + 1) * 64 + nl] = t4.y;
            QsT[(db + it * 4 + 2) * 64 + nl] = t4.z;
            QsT[(db + it * 4 + 3) * 64 + nl] = t4.w;
        }
    }
    float oacc[4][4] = {};
    float mi[4] = {-1e30f, -1e30f, -1e30f, -1e30f};
    float li[4] = {};
    __syncthreads();

    const int gb = (bq >> 2) << 2;   // first batch of this group

    for (int kc = 0; kc < 32; kc++) {
        const int m0 = kc * 64;
        const int kb = gb + (m0 >> 9);
        const int kn = m0 & 511;
        // load K transposed + V natural
        {
            const int kl = tid & 63;
            const int db = (tid >> 6) << 4;
            const float* kp = k + ((size_t)(kb * CN + kn + kl)) * CD + h * CHD + db;
#pragma unroll
            for (int it = 0; it < 4; it++) {
                float4 t4 = *(const float4*)(kp + it * 4);
                KP[(db + it * 4 + 0) * 64 + kl] = t4.x;
                KP[(db + it * 4 + 1) * 64 + kl] = t4.y;
                KP[(db + it * 4 + 2) * 64 + kl] = t4.z;
                KP[(db + it * 4 + 3) * 64 + kl] = t4.w;
            }
#pragma unroll
            for (int p = 0; p < 4; p++) {
                int lin = p * 256 + tid;
                int row = lin >> 4;
                int c4  = (lin & 15) << 2;
                *(float4*)&Vs[row * 64 + c4] =
                    *(const float4*)(v + ((size_t)(kb * CN + kn + row)) * CD + h * CHD + c4);
            }
        }
        __syncthreads();

        // S = Q K^T  (4x4 per thread)
        float s[4][4] = {};
#pragma unroll 8
        for (int kk = 0; kk < 64; kk++) {
            float4 a4 = *(float4*)&QsT[kk * 64 + r0];
            float4 b4 = *(float4*)&KP [kk * 64 + c0];
            float a[4] = {a4.x, a4.y, a4.z, a4.w};
            float b[4] = {b4.x, b4.y, b4.z, b4.w};
#pragma unroll
            for (int i = 0; i < 4; i++)
#pragma unroll
                for (int j = 0; j < 4; j++)
                    s[i][j] = fmaf(a[i], b[j], s[i][j]);
        }

        // online softmax update (row stats shared across the 16-lane group)
#pragma unroll
        for (int i = 0; i < 4; i++) {
#pragma unroll
            for (int j = 0; j < 4; j++) s[i][j] *= ATT_SCALE;
            float mx = fmaxf(fmaxf(s[i][0], s[i][1]), fmaxf(s[i][2], s[i][3]));
#pragma unroll
            for (int off = 8; off; off >>= 1)
                mx = fmaxf(mx, __shfl_xor_sync(0xffffffffu, mx, off));
            float mn = fmaxf(mi[i], mx);
            float corr = __expf(mi[i] - mn);
            mi[i] = mn;
            float rs = 0.0f;
#pragma unroll
            for (int j = 0; j < 4; j++) {
                float pv = __expf(s[i][j] - mn);
                s[i][j] = pv;
                rs += pv;
            }
#pragma unroll
            for (int off = 8; off; off >>= 1)
                rs += __shfl_xor_sync(0xffffffffu, rs, off);
            li[i] = li[i] * corr + rs;
#pragma unroll
            for (int j = 0; j < 4; j++) oacc[i][j] *= corr;
        }

        __syncthreads();   // all S reads of K done -> reuse KP for P
#pragma unroll
        for (int i = 0; i < 4; i++)
#pragma unroll
            for (int j = 0; j < 4; j++)
                KP[(r0 + i) * 64 + c0 + j] = s[i][j];
        __syncthreads();

        // O += P V
#pragma unroll 8
        for (int c = 0; c < 64; c++) {
            float4 v4 = *(float4*)&Vs[c * 64 + c0];
            float vv[4] = {v4.x, v4.y, v4.z, v4.w};
#pragma unroll
            for (int i = 0; i < 4; i++) {
                float pv = KP[(r0 + i) * 64 + c];
#pragma unroll
                for (int j = 0; j < 4; j++)
                    oacc[i][j] = fmaf(pv, vv[j], oacc[i][j]);
            }
        }
        __syncthreads();   // before next chunk overwrites K/V
    }

#pragma unroll
    for (int i = 0; i < 4; i++) {
        float inv = 1.0f / li[i];
        float4 r;
        r.x = oacc[i][0] * inv;
        r.y = oacc[i][1] * inv;
        r.z = oacc[i][2] * inv;
        r.w = oacc[i][3] * inv;
        *(float4*)(o + ((size_t)(bq * CN + n0 + r0 + i)) * CD + h * CHD + c0) = r;
    }
}

// ---------------------------------------------------------------------------
// E2 = emb[:4] @ Wik   (tiny: 4x1024x1024)
// ---------------------------------------------------------------------------
__global__ void e2_k(const float* __restrict__ emb, const float* __restrict__ Wik) {
    int n = blockIdx.x * 256 + threadIdx.x;   // 0..4095
    int i = n >> 10;
    int c = n & 1023;
    const float* ep = emb + i * 1024;
    float acc = 0.0f;
#pragma unroll 4
    for (int kk = 0; kk < 1024; kk++)
        acc = fmaf(ep[kk], Wik[(size_t)kk * 1024 + c], acc);
    g_e2[n] = acc;
}

// ---------------------------------------------------------------------------
// ik[b,n,:] = mask[b,n,:] @ E2 + bik   (memory-bound)
// ---------------------------------------------------------------------------
__global__ void ikb_k(const float* __restrict__ mask, const float* __restrict__ bik,
                      float* __restrict__ ik) {
    int idx = blockIdx.x * 256 + threadIdx.x;   // 0..4M-1
    int d  = idx & 1023;
    int bn = idx >> 10;
    const float* mp = mask + (size_t)bn * 4;
    float acc = bik[d];
    acc = fmaf(mp[0], g_e2[d],        acc);
    acc = fmaf(mp[1], g_e2[1024 + d], acc);
    acc = fmaf(mp[2], g_e2[2048 + d], acc);
    acc = fmaf(mp[3], g_e2[3072 + d], acc);
    ik[idx] = acc;
}

// ---------------------------------------------------------------------------
// instance gate: gacc[b,n] += sum over 64-col chunk of sigmoid(iq.ik * INST_SCALE)
// grid (colchunk 8, rowtile 8, b 8); 64x64x1024 per block, 4x4 micro-tiles
// ---------------------------------------------------------------------------
__global__ __launch_bounds__(256) void instgate_k(
    const float* __restrict__ iq, const float* __restrict__ ikp)
{
    __shared__ float Ast[16][68];
    __shared__ float Bst[16][68];
    const int b    = blockIdx.z;
    const int row0 = blockIdx.y * 64;
    const int col0 = blockIdx.x * 64;
    const int tid  = threadIdx.x;
    const int r0 = (tid >> 4) << 2;
    const int c0 = (tid & 15) << 2;

    float s[4][4] = {};
    for (int kt = 0; kt < 1024; kt += 16) {
        {
            int row = tid >> 2;
            int c4  = (tid & 3) << 2;
            float4 a4 = *(const float4*)(iq  + ((size_t)(b * 512 + row0 + row)) * 1024 + kt + c4);
            float4 b4 = *(const float4*)(ikp + ((size_t)(b * 512 + col0 + row)) * 1024 + kt + c4);
            Ast[c4 + 0][row] = a4.x; Ast[c4 + 1][row] = a4.y;
            Ast[c4 + 2][row] = a4.z; Ast[c4 + 3][row] = a4.w;
            Bst[c4 + 0][row] = b4.x; Bst[c4 + 1][row] = b4.y;
            Bst[c4 + 2][row] = b4.z; Bst[c4 + 3][row] = b4.w;
        }
        __syncthreads();
#pragma unroll
        for (int kk = 0; kk < 16; kk++) {
            float4 a4 = *(float4*)&Ast[kk][r0];
            float4 b4 = *(float4*)&Bst[kk][c0];
            float a[4] = {a4.x, a4.y, a4.z, a4.w};
            float bb[4] = {b4.x, b4.y, b4.z, b4.w};
#pragma unroll
            for (int i = 0; i < 4; i++)
#pragma unroll
                for (int j = 0; j < 4; j++)
                    s[i][j] = fmaf(a[i], bb[j], s[i][j]);
        }
        __syncthreads();
    }

#pragma unroll
    for (int i = 0; i < 4; i++) {
        float rp = 0.0f;
#pragma unroll
        for (int j = 0; j < 4; j++)
            rp += 1.0f / (1.0f + __expf(-s[i][j] * INST_SCALE));
#pragma unroll
        for (int off = 8; off; off >>= 1)
            rp += __shfl_xor_sync(0xffffffffu, rp, off);
        if ((tid & 15) == 0)
            atomicAdd(&g_gacc[b * 512 + row0 + r0 + i], rp);
    }
}

// ---------------------------------------------------------------------------
// launch
// ---------------------------------------------------------------------------
extern "C" void kernel_launch(void* const* d_in, const int* in_sizes, int n_in,
                              void* d_out, int out_size)
{
    (void)in_sizes; (void)n_in; (void)out_size;
    const float* x    = (const float*)d_in[0];
    const float* mask = (const float*)d_in[1];
    const float* Wq   = (const float*)d_in[2];
    const float* bq   = (const float*)d_in[3];
    const float* Wk   = (const float*)d_in[4];
    const float* bk   = (const float*)d_in[5];
    const float* Wv   = (const float*)d_in[6];
    const float* bv   = (const float*)d_in[7];
    const float* Wo   = (const float*)d_in[8];
    const float* bo   = (const float*)d_in[9];
    const float* Wiq  = (const float*)d_in[10];
    const float* biq  = (const float*)d_in[11];
    const float* Wik  = (const float*)d_in[12];
    const float* bik  = (const float*)d_in[13];
    const float* emb  = (const float*)d_in[14];
    const float* qw   = (const float*)d_in[15];
    const float* kw   = (const float*)d_in[16];
    float* out = (float*)d_out;

    float *qp, *kp, *vp, *op, *iqp, *ikp;
    cudaGetSymbolAddress((void**)&qp,  g_q);
    cudaGetSymbolAddress((void**)&kp,  g_k);
    cudaGetSymbolAddress((void**)&vp,  g_v);
    cudaGetSymbolAddress((void**)&op,  g_o);
    cudaGetSymbolAddress((void**)&iqp, g_iq);
    cudaGetSymbolAddress((void**)&ikp, g_ik);

    dim3 gemm_grid(8, 32);

    zero_gacc_k<<<16, 256>>>();

    gemm_k<false><<<gemm_grid, 256>>>(x, Wq, bq, qp);
    gemm_k<false><<<gemm_grid, 256>>>(x, Wk, bk, kp);
    gemm_k<false><<<gemm_grid, 256>>>(x, Wv, bv, vp);

    rms_k<<<8192, 256>>>(qp, qw);
    rms_k<<<8192, 256>>>(kp, kw);

    attn_k<<<dim3(8, 8, 16), 256>>>(qp, kp, vp, op);

    e2_k<<<16, 256>>>(emb, Wik);
    ikb_k<<<16384, 256>>>(mask, bik, ikp);

    gemm_k<false><<<gemm_grid, 256>>>(op, Wiq, biq, iqp);

    instgate_k<<<dim3(8, 8, 8), 256>>>(iqp, ikp);

    gemm_k<true><<<gemm_grid, 256>>>(op, Wo, bo, out);
}

// round 3
// speedup vs baseline: 1.4749x; 1.4749x over previous
#include <cuda_runtime.h>
#include <cstdint>
#include <cstddef>

// ---------------------------------------------------------------------------
// MIDIMultiInstanceAttention  (B=8, N=512, D=1024, H=16, HD=64, NI=4)
// tf32 tensor-core GEMMs (canonical m16n8k8 fragments, plain smem tiles)
// + fp32 flash attention
// ---------------------------------------------------------------------------

#define CB 8
#define CN 512
#define CD 1024
#define CH 16
#define CHD 64
#define CM 4096            // B*N
#define ATT_SCALE 0.125f   // HD^-0.5
#define INST_SCALE (0.125f / 16.0f)

#define APAD 36
#define BPAD 136

// scratch (device globals: allocation-free rule)
__device__ __align__(16) float g_q [CM * CD];
__device__ __align__(16) float g_k [CM * CD];
__device__ __align__(16) float g_v [CM * CD];
__device__ __align__(16) float g_o [CM * CD];   // attention output [B,N,D]
__device__ __align__(16) float g_iq[CM * CD];
__device__ __align__(16) float g_ik[CM * CD];
__device__ __align__(16) float g_e2[4 * CD];    // emb[:4] @ Wik
__device__ float g_gacc[CM];                    // sum_m sigmoid(...)

__global__ void zero_gacc_k() {
    int i = blockIdx.x * 256 + threadIdx.x;
    if (i < CM) g_gacc[i] = 0.0f;
}

// ---------------------------------------------------------------------------
// tf32 helpers
// ---------------------------------------------------------------------------
__device__ __forceinline__ uint32_t f2tf32(float x) {
    uint32_t r;
    asm("cvt.rna.tf32.f32 %0, %1;" : "=r"(r) : "f"(x));
    return r;
}

__device__ __forceinline__ void mma_tf32(float* d, const uint32_t* a, const uint32_t* b) {
    asm volatile(
        "mma.sync.aligned.m16n8k8.row.col.f32.tf32.tf32.f32 "
        "{%0,%1,%2,%3}, {%4,%5,%6,%7}, {%8,%9}, {%0,%1,%2,%3};\n"
        : "+f"(d[0]), "+f"(d[1]), "+f"(d[2]), "+f"(d[3])
        : "r"(a[0]), "r"(a[1]), "r"(a[2]), "r"(a[3]), "r"(b[0]), "r"(b[1]));
}

// ---------------------------------------------------------------------------
// tf32 GEMM: C[4096,1024] = A[4096,1024] @ W[1024,1024] + bias
// block 128x128x32, 8 warps (2x4), warp tile 64x32 (4x4 m16n8k8)
// As[row][k] pad 36 (frag reads bank (4g+t): conflict-free)
// Bs[k][n]  pad 136 (frag reads bank (8t+g): conflict-free)
// GATE: scale A rows by (1 + gacc[row]/512) on load.
// ---------------------------------------------------------------------------
template <bool GATE>
__global__ __launch_bounds__(256, 2) void gemm_t(
    const float* __restrict__ A, const float* __restrict__ W,
    const float* __restrict__ bias, float* __restrict__ C)
{
    __shared__ uint32_t As[128 * APAD];
    __shared__ uint32_t Bs[32 * BPAD];

    const int tid  = threadIdx.x;
    const int lane = tid & 31;
    const int warp = tid >> 5;
    const int wm   = warp >> 2;     // 0..1
    const int wn   = warp & 3;      // 0..3
    const int bm   = blockIdx.y * 128;
    const int bn   = blockIdx.x * 128;
    const int g    = lane >> 2;     // groupID 0..7
    const int t    = lane & 3;      // threadID_in_group

    float acc[4][4][4];
#pragma unroll
    for (int i = 0; i < 4; i++)
#pragma unroll
        for (int j = 0; j < 4; j++)
#pragma unroll
            for (int r = 0; r < 4; r++) acc[i][j][r] = 0.0f;

    float gv[4];
#pragma unroll
    for (int p = 0; p < 4; p++) {
        int row = (p * 256 + tid) >> 3;
        gv[p] = GATE ? (1.0f + g_gacc[bm + row] * (1.0f / 512.0f)) : 1.0f;
    }

    for (int kt = 0; kt < CD; kt += 32) {
        // A tile: 128x32
#pragma unroll
        for (int p = 0; p < 4; p++) {
            int idx = p * 256 + tid;
            int r   = idx >> 3;
            int c4  = (idx & 7) << 2;
            float4 v = *(const float4*)(A + (size_t)(bm + r) * CD + kt + c4);
            if (GATE) { v.x *= gv[p]; v.y *= gv[p]; v.z *= gv[p]; v.w *= gv[p]; }
            uint4 s = {f2tf32(v.x), f2tf32(v.y), f2tf32(v.z), f2tf32(v.w)};
            *(uint4*)&As[r * APAD + c4] = s;
        }
        // B tile: 32x128 from W rows (contiguous in n)
#pragma unroll
        for (int p = 0; p < 4; p++) {
            int idx = p * 256 + tid;
            int kk  = idx >> 5;
            int c4  = (idx & 31) << 2;
            float4 v = *(const float4*)(W + (size_t)(kt + kk) * CD + bn + c4);
            uint4 s = {f2tf32(v.x), f2tf32(v.y), f2tf32(v.z), f2tf32(v.w)};
            *(uint4*)&Bs[kk * BPAD + c4] = s;
        }
        __syncthreads();

#pragma unroll
        for (int ks = 0; ks < 4; ks++) {
            const int kc = ks * 8;
            uint32_t af[4][4], bf[4][2];
#pragma unroll
            for (int mt = 0; mt < 4; mt++) {
                int row = wm * 64 + mt * 16 + g;
                af[mt][0] = As[row * APAD + kc + t];
                af[mt][1] = As[(row + 8) * APAD + kc + t];
                af[mt][2] = As[row * APAD + kc + t + 4];
                af[mt][3] = As[(row + 8) * APAD + kc + t + 4];
            }
#pragma unroll
            for (int nt = 0; nt < 4; nt++) {
                int col = wn * 32 + nt * 8 + g;
                bf[nt][0] = Bs[(kc + t) * BPAD + col];
                bf[nt][1] = Bs[(kc + t + 4) * BPAD + col];
            }
#pragma unroll
            for (int mt = 0; mt < 4; mt++)
#pragma unroll
                for (int nt = 0; nt < 4; nt++)
                    mma_tf32(acc[mt][nt], af[mt], bf[nt]);
        }
        __syncthreads();
    }

    // epilogue: c0=(g,2t) c1=(g,2t+1) c2=(g+8,2t) c3=(g+8,2t+1)
#pragma unroll
    for (int nt = 0; nt < 4; nt++) {
        int col = bn + wn * 32 + nt * 8 + t * 2;
        float2 bb = *(const float2*)(bias + col);
#pragma unroll
        for (int mt = 0; mt < 4; mt++) {
            int row = bm + wm * 64 + mt * 16 + g;
            float2 r0 = {acc[mt][nt][0] + bb.x, acc[mt][nt][1] + bb.y};
            float2 r1 = {acc[mt][nt][2] + bb.x, acc[mt][nt][3] + bb.y};
            *(float2*)(C + (size_t)row * CD + col)       = r0;
            *(float2*)(C + (size_t)(row + 8) * CD + col) = r1;
        }
    }
}

// ---------------------------------------------------------------------------
// instance gate (tf32): per batch S = iq[b] @ ik[b]^T (512x512x1024)
// gacc[b,row] += sum_col sigmoid(S * INST_SCALE)
// ik rows are col-major k x n  ->  Bs stored natural [n][k] pad 36, read like A
// ---------------------------------------------------------------------------
__global__ __launch_bounds__(256, 2) void instgate_t(
    const float* __restrict__ iq, const float* __restrict__ ikp)
{
    __shared__ uint32_t As[128 * APAD];
    __shared__ uint32_t Bs[128 * APAD];

    const int tid  = threadIdx.x;
    const int lane = tid & 31;
    const int warp = tid >> 5;
    const int wm   = warp >> 2;
    const int wn   = warp & 3;
    const int b    = blockIdx.z;
    const int bm   = blockIdx.y * 128;
    const int bn   = blockIdx.x * 128;
    const int g    = lane >> 2;
    const int t    = lane & 3;
    const float* Ab = iq  + (size_t)b * 512 * CD;
    const float* Bb = ikp + (size_t)b * 512 * CD;

    float acc[4][4][4];
#pragma unroll
    for (int i = 0; i < 4; i++)
#pragma unroll
        for (int j = 0; j < 4; j++)
#pragma unroll
            for (int r = 0; r < 4; r++) acc[i][j][r] = 0.0f;

    for (int kt = 0; kt < CD; kt += 32) {
#pragma unroll
        for (int p = 0; p < 4; p++) {
            int idx = p * 256 + tid;
            int r   = idx >> 3;
            int c4  = (idx & 7) << 2;
            float4 va = *(const float4*)(Ab + (size_t)(bm + r) * CD + kt + c4);
            float4 vb = *(const float4*)(Bb + (size_t)(bn + r) * CD + kt + c4);
            uint4 sa = {f2tf32(va.x), f2tf32(va.y), f2tf32(va.z), f2tf32(va.w)};
            uint4 sb = {f2tf32(vb.x), f2tf32(vb.y), f2tf32(vb.z), f2tf32(vb.w)};
            *(uint4*)&As[r * APAD + c4] = sa;
            *(uint4*)&Bs[r * APAD + c4] = sb;
        }
        __syncthreads();

#pragma unroll
        for (int ks = 0; ks < 4; ks++) {
            const int kc = ks * 8;
            uint32_t af[4][4], bf[4][2];
#pragma unroll
            for (int mt = 0; mt < 4; mt++) {
                int row = wm * 64 + mt * 16 + g;
                af[mt][0] = As[row * APAD + kc + t];
                af[mt][1] = As[(row + 8) * APAD + kc + t];
                af[mt][2] = As[row * APAD + kc + t + 4];
                af[mt][3] = As[(row + 8) * APAD + kc + t + 4];
            }
#pragma unroll
            for (int nt = 0; nt < 4; nt++) {
                int col = wn * 32 + nt * 8 + g;   // n index
                bf[nt][0] = Bs[col * APAD + kc + t];
                bf[nt][1] = Bs[col * APAD + kc + t + 4];
            }
#pragma unroll
            for (int mt = 0; mt < 4; mt++)
#pragma unroll
                for (int nt = 0; nt < 4; nt++)
                    mma_tf32(acc[mt][nt], af[mt], bf[nt]);
        }
        __syncthreads();
    }

    // epilogue: sigmoid + row-sum + atomicAdd
#pragma unroll
    for (int mt = 0; mt < 4; mt++) {
        float s0 = 0.0f, s1 = 0.0f;
#pragma unroll
        for (int nt = 0; nt < 4; nt++) {
            s0 += 1.0f / (1.0f + __expf(-acc[mt][nt][0] * INST_SCALE));
            s0 += 1.0f / (1.0f + __expf(-acc[mt][nt][1] * INST_SCALE));
            s1 += 1.0f / (1.0f + __expf(-acc[mt][nt][2] * INST_SCALE));
            s1 += 1.0f / (1.0f + __expf(-acc[mt][nt][3] * INST_SCALE));
        }
        s0 += __shfl_xor_sync(0xffffffffu, s0, 1);
        s0 += __shfl_xor_sync(0xffffffffu, s0, 2);
        s1 += __shfl_xor_sync(0xffffffffu, s1, 1);
        s1 += __shfl_xor_sync(0xffffffffu, s1, 2);
        if (t == 0) {
            int row = bm + wm * 64 + mt * 16 + g;
            atomicAdd(&g_gacc[b * 512 + row], s0);
            atomicAdd(&g_gacc[b * 512 + row + 8], s1);
        }
    }
}

// ---------------------------------------------------------------------------
// per-head RMSNorm, one warp per (b,n,h)
// ---------------------------------------------------------------------------
__global__ void rms_k(float* __restrict__ t, const float* __restrict__ w) {
    int g    = (blockIdx.x * blockDim.x + threadIdx.x) >> 5;
    int lane = threadIdx.x & 31;
    float* p = t + (size_t)g * 64;
    float a = p[lane];
    float b = p[lane + 32];
    float ss = fmaf(a, a, b * b);
#pragma unroll
    for (int off = 16; off; off >>= 1)
        ss += __shfl_xor_sync(0xffffffffu, ss, off);
    float sc = rsqrtf(ss * (1.0f / 64.0f) + 1e-6f);
    p[lane]      = a * sc * w[lane];
    p[lane + 32] = b * sc * w[lane + 32];
}

// ---------------------------------------------------------------------------
// grouped flash attention (fp32 FFMA; tensor conversion next round)
// ---------------------------------------------------------------------------
__global__ __launch_bounds__(256) void attn_k(
    const float* __restrict__ q, const float* __restrict__ k,
    const float* __restrict__ v, float* __restrict__ o)
{
    __shared__ float QsT[64 * 64];
    __shared__ float KP [64 * 64];
    __shared__ float Vs [64 * 64];

    const int bq  = blockIdx.y;
    const int h   = blockIdx.z;
    const int n0  = blockIdx.x * 64;
    const int tid = threadIdx.x;
    const int r0  = (tid >> 4) << 2;
    const int c0  = (tid & 15) << 2;

    {
        const int nl = tid & 63;
        const int db = (tid >> 6) << 4;
        const float* qp = q + ((size_t)(bq * CN + n0 + nl)) * CD + h * CHD + db;
#pragma unroll
        for (int it = 0; it < 4; it++) {
            float4 t4 = *(const float4*)(qp + it * 4);
            QsT[(db + it * 4 + 0) * 64 + nl] = t4.x;
            QsT[(db + it * 4 + 1) * 64 + nl] = t4.y;
            QsT[(db + it * 4 + 2) * 64 + nl] = t4.z;
            QsT[(db + it * 4 + 3) * 64 + nl] = t4.w;
        }
    }
    float oacc[4][4] = {};
    float mi[4] = {-1e30f, -1e30f, -1e30f, -1e30f};
    float li[4] = {};
    __syncthreads();

    const int gb = (bq >> 2) << 2;

    for (int kc = 0; kc < 32; kc++) {
        const int m0 = kc * 64;
        const int kb = gb + (m0 >> 9);
        const int kn = m0 & 511;
        {
            const int kl = tid & 63;
            const int db = (tid >> 6) << 4;
            const float* kp = k + ((size_t)(kb * CN + kn + kl)) * CD + h * CHD + db;
#pragma unroll
            for (int it = 0; it < 4; it++) {
                float4 t4 = *(const float4*)(kp + it * 4);
                KP[(db + it * 4 + 0) * 64 + kl] = t4.x;
                KP[(db + it * 4 + 1) * 64 + kl] = t4.y;
                KP[(db + it * 4 + 2) * 64 + kl] = t4.z;
                KP[(db + it * 4 + 3) * 64 + kl] = t4.w;
            }
#pragma unroll
            for (int p = 0; p < 4; p++) {
                int lin = p * 256 + tid;
                int row = lin >> 4;
                int c4  = (lin & 15) << 2;
                *(float4*)&Vs[row * 64 + c4] =
                    *(const float4*)(v + ((size_t)(kb * CN + kn + row)) * CD + h * CHD + c4);
            }
        }
        __syncthreads();

        float s[4][4] = {};
#pragma unroll 8
        for (int kk = 0; kk < 64; kk++) {
            float4 a4 = *(float4*)&QsT[kk * 64 + r0];
            float4 b4 = *(float4*)&KP [kk * 64 + c0];
            float a[4] = {a4.x, a4.y, a4.z, a4.w};
            float b[4] = {b4.x, b4.y, b4.z, b4.w};
#pragma unroll
            for (int i = 0; i < 4; i++)
#pragma unroll
                for (int j = 0; j < 4; j++)
                    s[i][j] = fmaf(a[i], b[j], s[i][j]);
        }

#pragma unroll
        for (int i = 0; i < 4; i++) {
#pragma unroll
            for (int j = 0; j < 4; j++) s[i][j] *= ATT_SCALE;
            float mx = fmaxf(fmaxf(s[i][0], s[i][1]), fmaxf(s[i][2], s[i][3]));
#pragma unroll
            for (int off = 8; off; off >>= 1)
                mx = fmaxf(mx, __shfl_xor_sync(0xffffffffu, mx, off));
            float mn = fmaxf(mi[i], mx);
            float corr = __expf(mi[i] - mn);
            mi[i] = mn;
            float rs = 0.0f;
#pragma unroll
            for (int j = 0; j < 4; j++) {
                float pv = __expf(s[i][j] - mn);
                s[i][j] = pv;
                rs += pv;
            }
#pragma unroll
            for (int off = 8; off; off >>= 1)
                rs += __shfl_xor_sync(0xffffffffu, rs, off);
            li[i] = li[i] * corr + rs;
#pragma unroll
            for (int j = 0; j < 4; j++) oacc[i][j] *= corr;
        }

        __syncthreads();
#pragma unroll
        for (int i = 0; i < 4; i++)
#pragma unroll
            for (int j = 0; j < 4; j++)
                KP[(r0 + i) * 64 + c0 + j] = s[i][j];
        __syncthreads();

#pragma unroll 8
        for (int c = 0; c < 64; c++) {
            float4 v4 = *(float4*)&Vs[c * 64 + c0];
            float vv[4] = {v4.x, v4.y, v4.z, v4.w};
#pragma unroll
            for (int i = 0; i < 4; i++) {
                float pv = KP[(r0 + i) * 64 + c];
#pragma unroll
                for (int j = 0; j < 4; j++)
                    oacc[i][j] = fmaf(pv, vv[j], oacc[i][j]);
            }
        }
        __syncthreads();
    }

#pragma unroll
    for (int i = 0; i < 4; i++) {
        float inv = 1.0f / li[i];
        float4 r;
        r.x = oacc[i][0] * inv;
        r.y = oacc[i][1] * inv;
        r.z = oacc[i][2] * inv;
        r.w = oacc[i][3] * inv;
        *(float4*)(o + ((size_t)(bq * CN + n0 + r0 + i)) * CD + h * CHD + c0) = r;
    }
}

// ---------------------------------------------------------------------------
// E2 = emb[:4] @ Wik   (tiny)
// ---------------------------------------------------------------------------
__global__ void e2_k(const float* __restrict__ emb, const float* __restrict__ Wik) {
    int n = blockIdx.x * 256 + threadIdx.x;
    int i = n >> 10;
    int c = n & 1023;
    const float* ep = emb + i * 1024;
    float acc = 0.0f;
#pragma unroll 4
    for (int kk = 0; kk < 1024; kk++)
        acc = fmaf(ep[kk], Wik[(size_t)kk * 1024 + c], acc);
    g_e2[n] = acc;
}

__global__ void ikb_k(const float* __restrict__ mask, const float* __restrict__ bik,
                      float* __restrict__ ik) {
    int idx = blockIdx.x * 256 + threadIdx.x;
    int d  = idx & 1023;
    int bn = idx >> 10;
    const float* mp = mask + (size_t)bn * 4;
    float acc = bik[d];
    acc = fmaf(mp[0], g_e2[d],        acc);
    acc = fmaf(mp[1], g_e2[1024 + d], acc);
    acc = fmaf(mp[2], g_e2[2048 + d], acc);
    acc = fmaf(mp[3], g_e2[3072 + d], acc);
    ik[idx] = acc;
}

// ---------------------------------------------------------------------------
// launch
// ---------------------------------------------------------------------------
extern "C" void kernel_launch(void* const* d_in, const int* in_sizes, int n_in,
                              void* d_out, int out_size)
{
    (void)in_sizes; (void)n_in; (void)out_size;
    const float* x    = (const float*)d_in[0];
    const float* mask = (const float*)d_in[1];
    const float* Wq   = (const float*)d_in[2];
    const float* bq   = (const float*)d_in[3];
    const float* Wk   = (const float*)d_in[4];
    const float* bk   = (const float*)d_in[5];
    const float* Wv   = (const float*)d_in[6];
    const float* bv   = (const float*)d_in[7];
    const float* Wo   = (const float*)d_in[8];
    const float* bo   = (const float*)d_in[9];
    const float* Wiq  = (const float*)d_in[10];
    const float* biq  = (const float*)d_in[11];
    const float* Wik  = (const float*)d_in[12];
    const float* bik  = (const float*)d_in[13];
    const float* emb  = (const float*)d_in[14];
    const float* qw   = (const float*)d_in[15];
    const float* kw   = (const float*)d_in[16];
    float* out = (float*)d_out;

    float *qp, *kp, *vp, *op, *iqp, *ikp;
    cudaGetSymbolAddress((void**)&qp,  g_q);
    cudaGetSymbolAddress((void**)&kp,  g_k);
    cudaGetSymbolAddress((void**)&vp,  g_v);
    cudaGetSymbolAddress((void**)&op,  g_o);
    cudaGetSymbolAddress((void**)&iqp, g_iq);
    cudaGetSymbolAddress((void**)&ikp, g_ik);

    dim3 gemm_grid(8, 32);   // (N/128, M/128)

    zero_gacc_k<<<16, 256>>>();

    gemm_t<false><<<gemm_grid, 256>>>(x, Wq, bq, qp);
    gemm_t<false><<<gemm_grid, 256>>>(x, Wk, bk, kp);
    gemm_t<false><<<gemm_grid, 256>>>(x, Wv, bv, vp);

    rms_k<<<8192, 256>>>(qp, qw);
    rms_k<<<8192, 256>>>(kp, kw);

    attn_k<<<dim3(8, 8, 16), 256>>>(qp, kp, vp, op);

    e2_k<<<16, 256>>>(emb, Wik);
    ikb_k<<<16384, 256>>>(mask, bik, ikp);

    gemm_t<false><<<gemm_grid, 256>>>(op, Wiq, biq, iqp);

    instgate_t<<<dim3(4, 4, 8), 256>>>(iqp, ikp);

    gemm_t<true><<<gemm_grid, 256>>>(op, Wo, bo, out);
}

// round 4
// speedup vs baseline: 2.5203x; 1.7089x over previous
#include <cuda_runtime.h>
#include <cstdint>
#include <cstddef>

// ---------------------------------------------------------------------------
// MIDIMultiInstanceAttention  (B=8, N=512, D=1024, H=16, HD=64, NI=4)
// tf32 tensor-core GEMMs + tf32 tensor-core flash attention
// ---------------------------------------------------------------------------

#define CB 8
#define CN 512
#define CD 1024
#define CH 16
#define CHD 64
#define CM 4096            // B*N
#define ATT_SCALE 0.125f   // HD^-0.5
#define INST_SCALE (0.125f / 16.0f)

#define APAD 36
#define BPAD 136

// attention smem geometry
#define KPAD 68            // K/V row pad (words)
#define PPAD 72            // P row pad (words)
#define SMEM_ATTN ((2 * 64 * KPAD + 8 * 16 * PPAD) * 4)   // 71680 bytes

// scratch (device globals: allocation-free rule)
__device__ __align__(16) float g_q [CM * CD];
__device__ __align__(16) float g_k [CM * CD];
__device__ __align__(16) float g_v [CM * CD];
__device__ __align__(16) float g_o [CM * CD];   // attention output [B,N,D]
__device__ __align__(16) float g_iq[CM * CD];
__device__ __align__(16) float g_ik[CM * CD];
__device__ __align__(16) float g_e2[4 * CD];    // emb[:4] @ Wik
__device__ float g_gacc[CM];                    // sum_m sigmoid(...)

__global__ void zero_gacc_k() {
    int i = blockIdx.x * 256 + threadIdx.x;
    if (i < CM) g_gacc[i] = 0.0f;
}

// ---------------------------------------------------------------------------
// tf32 helpers
// ---------------------------------------------------------------------------
__device__ __forceinline__ uint32_t f2tf32(float x) {
    uint32_t r;
    asm("cvt.rna.tf32.f32 %0, %1;" : "=r"(r) : "f"(x));
    return r;
}

__device__ __forceinline__ void mma_tf32(float* d, const uint32_t* a, const uint32_t* b) {
    asm volatile(
        "mma.sync.aligned.m16n8k8.row.col.f32.tf32.tf32.f32 "
        "{%0,%1,%2,%3}, {%4,%5,%6,%7}, {%8,%9}, {%0,%1,%2,%3};\n"
        : "+f"(d[0]), "+f"(d[1]), "+f"(d[2]), "+f"(d[3])
        : "r"(a[0]), "r"(a[1]), "r"(a[2]), "r"(a[3]), "r"(b[0]), "r"(b[1]));
}

// ---------------------------------------------------------------------------
// tf32 GEMM: C[4096,1024] = A[4096,1024] @ W[1024,1024] + bias  (validated R3)
// ---------------------------------------------------------------------------
template <bool GATE>
__global__ __launch_bounds__(256, 2) void gemm_t(
    const float* __restrict__ A, const float* __restrict__ W,
    const float* __restrict__ bias, float* __restrict__ C)
{
    __shared__ uint32_t As[128 * APAD];
    __shared__ uint32_t Bs[32 * BPAD];

    const int tid  = threadIdx.x;
    const int lane = tid & 31;
    const int warp = tid >> 5;
    const int wm   = warp >> 2;
    const int wn   = warp & 3;
    const int bm   = blockIdx.y * 128;
    const int bn   = blockIdx.x * 128;
    const int g    = lane >> 2;
    const int t    = lane & 3;

    float acc[4][4][4];
#pragma unroll
    for (int i = 0; i < 4; i++)
#pragma unroll
        for (int j = 0; j < 4; j++)
#pragma unroll
            for (int r = 0; r < 4; r++) acc[i][j][r] = 0.0f;

    float gv[4];
#pragma unroll
    for (int p = 0; p < 4; p++) {
        int row = (p * 256 + tid) >> 3;
        gv[p] = GATE ? (1.0f + g_gacc[bm + row] * (1.0f / 512.0f)) : 1.0f;
    }

    for (int kt = 0; kt < CD; kt += 32) {
#pragma unroll
        for (int p = 0; p < 4; p++) {
            int idx = p * 256 + tid;
            int r   = idx >> 3;
            int c4  = (idx & 7) << 2;
            float4 v = *(const float4*)(A + (size_t)(bm + r) * CD + kt + c4);
            if (GATE) { v.x *= gv[p]; v.y *= gv[p]; v.z *= gv[p]; v.w *= gv[p]; }
            uint4 s = {f2tf32(v.x), f2tf32(v.y), f2tf32(v.z), f2tf32(v.w)};
            *(uint4*)&As[r * APAD + c4] = s;
        }
#pragma unroll
        for (int p = 0; p < 4; p++) {
            int idx = p * 256 + tid;
            int kk  = idx >> 5;
            int c4  = (idx & 31) << 2;
            float4 v = *(const float4*)(W + (size_t)(kt + kk) * CD + bn + c4);
            uint4 s = {f2tf32(v.x), f2tf32(v.y), f2tf32(v.z), f2tf32(v.w)};
            *(uint4*)&Bs[kk * BPAD + c4] = s;
        }
        __syncthreads();

#pragma unroll
        for (int ks = 0; ks < 4; ks++) {
            const int kc = ks * 8;
            uint32_t af[4][4], bf[4][2];
#pragma unroll
            for (int mt = 0; mt < 4; mt++) {
                int row = wm * 64 + mt * 16 + g;
                af[mt][0] = As[row * APAD + kc + t];
                af[mt][1] = As[(row + 8) * APAD + kc + t];
                af[mt][2] = As[row * APAD + kc + t + 4];
                af[mt][3] = As[(row + 8) * APAD + kc + t + 4];
            }
#pragma unroll
            for (int nt = 0; nt < 4; nt++) {
                int col = wn * 32 + nt * 8 + g;
                bf[nt][0] = Bs[(kc + t) * BPAD + col];
                bf[nt][1] = Bs[(kc + t + 4) * BPAD + col];
            }
#pragma unroll
            for (int mt = 0; mt < 4; mt++)
#pragma unroll
                for (int nt = 0; nt < 4; nt++)
                    mma_tf32(acc[mt][nt], af[mt], bf[nt]);
        }
        __syncthreads();
    }

#pragma unroll
    for (int nt = 0; nt < 4; nt++) {
        int col = bn + wn * 32 + nt * 8 + t * 2;
        float2 bb = *(const float2*)(bias + col);
#pragma unroll
        for (int mt = 0; mt < 4; mt++) {
            int row = bm + wm * 64 + mt * 16 + g;
            float2 r0 = {acc[mt][nt][0] + bb.x, acc[mt][nt][1] + bb.y};
            float2 r1 = {acc[mt][nt][2] + bb.x, acc[mt][nt][3] + bb.y};
            *(float2*)(C + (size_t)row * CD + col)       = r0;
            *(float2*)(C + (size_t)(row + 8) * CD + col) = r1;
        }
    }
}

// ---------------------------------------------------------------------------
// instance gate (tf32): per batch S = iq[b] @ ik[b]^T (512x512x1024)  (validated R3)
// ---------------------------------------------------------------------------
__global__ __launch_bounds__(256, 2) void instgate_t(
    const float* __restrict__ iq, const float* __restrict__ ikp)
{
    __shared__ uint32_t As[128 * APAD];
    __shared__ uint32_t Bs[128 * APAD];

    const int tid  = threadIdx.x;
    const int lane = tid & 31;
    const int warp = tid >> 5;
    const int wm   = warp >> 2;
    const int wn   = warp & 3;
    const int b    = blockIdx.z;
    const int bm   = blockIdx.y * 128;
    const int bn   = blockIdx.x * 128;
    const int g    = lane >> 2;
    const int t    = lane & 3;
    const float* Ab = iq  + (size_t)b * 512 * CD;
    const float* Bb = ikp + (size_t)b * 512 * CD;

    float acc[4][4][4];
#pragma unroll
    for (int i = 0; i < 4; i++)
#pragma unroll
        for (int j = 0; j < 4; j++)
#pragma unroll
            for (int r = 0; r < 4; r++) acc[i][j][r] = 0.0f;

    for (int kt = 0; kt < CD; kt += 32) {
#pragma unroll
        for (int p = 0; p < 4; p++) {
            int idx = p * 256 + tid;
            int r   = idx >> 3;
            int c4  = (idx & 7) << 2;
            float4 va = *(const float4*)(Ab + (size_t)(bm + r) * CD + kt + c4);
            float4 vb = *(const float4*)(Bb + (size_t)(bn + r) * CD + kt + c4);
            uint4 sa = {f2tf32(va.x), f2tf32(va.y), f2tf32(va.z), f2tf32(va.w)};
            uint4 sb = {f2tf32(vb.x), f2tf32(vb.y), f2tf32(vb.z), f2tf32(vb.w)};
            *(uint4*)&As[r * APAD + c4] = sa;
            *(uint4*)&Bs[r * APAD + c4] = sb;
        }
        __syncthreads();

#pragma unroll
        for (int ks = 0; ks < 4; ks++) {
            const int kc = ks * 8;
            uint32_t af[4][4], bf[4][2];
#pragma unroll
            for (int mt = 0; mt < 4; mt++) {
                int row = wm * 64 + mt * 16 + g;
                af[mt][0] = As[row * APAD + kc + t];
                af[mt][1] = As[(row + 8) * APAD + kc + t];
                af[mt][2] = As[row * APAD + kc + t + 4];
                af[mt][3] = As[(row + 8) * APAD + kc + t + 4];
            }
#pragma unroll
            for (int nt = 0; nt < 4; nt++) {
                int col = wn * 32 + nt * 8 + g;
                bf[nt][0] = Bs[col * APAD + kc + t];
                bf[nt][1] = Bs[col * APAD + kc + t + 4];
            }
#pragma unroll
            for (int mt = 0; mt < 4; mt++)
#pragma unroll
                for (int nt = 0; nt < 4; nt++)
                    mma_tf32(acc[mt][nt], af[mt], bf[nt]);
        }
        __syncthreads();
    }

#pragma unroll
    for (int mt = 0; mt < 4; mt++) {
        float s0 = 0.0f, s1 = 0.0f;
#pragma unroll
        for (int nt = 0; nt < 4; nt++) {
            s0 += 1.0f / (1.0f + __expf(-acc[mt][nt][0] * INST_SCALE));
            s0 += 1.0f / (1.0f + __expf(-acc[mt][nt][1] * INST_SCALE));
            s1 += 1.0f / (1.0f + __expf(-acc[mt][nt][2] * INST_SCALE));
            s1 += 1.0f / (1.0f + __expf(-acc[mt][nt][3] * INST_SCALE));
        }
        s0 += __shfl_xor_sync(0xffffffffu, s0, 1);
        s0 += __shfl_xor_sync(0xffffffffu, s0, 2);
        s1 += __shfl_xor_sync(0xffffffffu, s1, 1);
        s1 += __shfl_xor_sync(0xffffffffu, s1, 2);
        if (t == 0) {
            int row = bm + wm * 64 + mt * 16 + g;
            atomicAdd(&g_gacc[b * 512 + row], s0);
            atomicAdd(&g_gacc[b * 512 + row + 8], s1);
        }
    }
}

// ---------------------------------------------------------------------------
// per-head RMSNorm, one warp per (b,n,h)
// ---------------------------------------------------------------------------
__global__ void rms_k(float* __restrict__ t, const float* __restrict__ w) {
    int g    = (blockIdx.x * blockDim.x + threadIdx.x) >> 5;
    int lane = threadIdx.x & 31;
    float* p = t + (size_t)g * 64;
    float a = p[lane];
    float b = p[lane + 32];
    float ss = fmaf(a, a, b * b);
#pragma unroll
    for (int off = 16; off; off >>= 1)
        ss += __shfl_xor_sync(0xffffffffu, ss, off);
    float sc = rsqrtf(ss * (1.0f / 64.0f) + 1e-6f);
    p[lane]      = a * sc * w[lane];
    p[lane + 32] = b * sc * w[lane + 32];
}

// ---------------------------------------------------------------------------
// tf32 tensor-core grouped flash attention.
// grid (qtile 4, b 8, h 16), 256 threads (8 warps), q-tile 128, kv-chunk 64.
// Each warp owns one m16 tile (16 q rows): P fragments stay warp-local,
// staged through a per-warp smem scratch with XOR-4 swizzle on (row&4).
// ATT_SCALE folded into Q (exact, power of 2).
// ---------------------------------------------------------------------------
__global__ __launch_bounds__(256, 2) void attn_t(
    const float* __restrict__ q, const float* __restrict__ k,
    const float* __restrict__ v, float* __restrict__ o)
{
    extern __shared__ uint32_t sm[];
    uint32_t* Ks = sm;                     // [64][KPAD]  K chunk, [kv][d]
    uint32_t* Vs = sm + 64 * KPAD;         // [64][KPAD]  V chunk, [kv][d]
    uint32_t* Ps = sm + 2 * 64 * KPAD;     // per-warp [16][PPAD]

    const int tid  = threadIdx.x;
    const int lane = tid & 31;
    const int warp = tid >> 5;
    const int g    = lane >> 2;
    const int t    = lane & 3;
    const int bq   = blockIdx.y;
    const int h    = blockIdx.z;
    const int n0   = blockIdx.x * 128;
    const int gb   = bq & ~3;              // first batch of the kv group
    const int qrow = n0 + warp * 16;       // warp's first q row

    // Q fragments, register-resident (scaled, tf32)
    uint32_t qf[8][4];
    {
        const float* qb = q + ((size_t)(bq * CN + qrow)) * CD + h * CHD;
#pragma unroll
        for (int ks = 0; ks < 8; ks++) {
            int c = ks * 8 + t;
            qf[ks][0] = f2tf32(qb[(size_t)g * CD + c]           * ATT_SCALE);
            qf[ks][1] = f2tf32(qb[(size_t)(g + 8) * CD + c]     * ATT_SCALE);
            qf[ks][2] = f2tf32(qb[(size_t)g * CD + c + 4]       * ATT_SCALE);
            qf[ks][3] = f2tf32(qb[(size_t)(g + 8) * CD + c + 4] * ATT_SCALE);
        }
    }

    float oa[8][4];
#pragma unroll
    for (int nt = 0; nt < 8; nt++)
#pragma unroll
        for (int r = 0; r < 4; r++) oa[nt][r] = 0.0f;
    float mi0 = -1e30f, mi1 = -1e30f, li0 = 0.0f, li1 = 0.0f;

    uint32_t* Pw = Ps + warp * 16 * PPAD;
    const int sw0 = (g & 4) ? 4 : 0;       // swizzle for rows g / g+8 (same row&4)

    for (int kc = 0; kc < 32; kc++) {
        const int m0 = kc * 64;
        const int kb = gb + (m0 >> 9);
        const int kn = m0 & 511;

        // ---- load K,V chunk (tf32) ----
#pragma unroll
        for (int p = 0; p < 4; p++) {
            int idx = p * 256 + tid;
            int r   = idx >> 4;
            int c4  = (idx & 15) << 2;
            size_t base = ((size_t)(kb * CN + kn + r)) * CD + h * CHD + c4;
            float4 k4 = *(const float4*)(k + base);
            float4 v4 = *(const float4*)(v + base);
            Ks[r * KPAD + c4 + 0] = f2tf32(k4.x);
            Ks[r * KPAD + c4 + 1] = f2tf32(k4.y);
            Ks[r * KPAD + c4 + 2] = f2tf32(k4.z);
            Ks[r * KPAD + c4 + 3] = f2tf32(k4.w);
            Vs[r * KPAD + c4 + 0] = f2tf32(v4.x);
            Vs[r * KPAD + c4 + 1] = f2tf32(v4.y);
            Vs[r * KPAD + c4 + 2] = f2tf32(v4.z);
            Vs[r * KPAD + c4 + 3] = f2tf32(v4.w);
        }
        __syncthreads();

        // ---- S = Q @ K^T  (16 x 64 per warp) ----
        float sacc[8][4];
#pragma unroll
        for (int nt = 0; nt < 8; nt++)
#pragma unroll
            for (int r = 0; r < 4; r++) sacc[nt][r] = 0.0f;
#pragma unroll
        for (int ks = 0; ks < 8; ks++) {
            const int kcd = ks * 8;
#pragma unroll
            for (int nt = 0; nt < 8; nt++) {
                uint32_t bf[2];
                bf[0] = Ks[(nt * 8 + g) * KPAD + kcd + t];
                bf[1] = Ks[(nt * 8 + g) * KPAD + kcd + t + 4];
                mma_tf32(sacc[nt], qf[ks], bf);
            }
        }

        // ---- online softmax (rows g and g+8, stats within quad) ----
        float rm0 = -1e30f, rm1 = -1e30f;
#pragma unroll
        for (int nt = 0; nt < 8; nt++) {
            rm0 = fmaxf(rm0, fmaxf(sacc[nt][0], sacc[nt][1]));
            rm1 = fmaxf(rm1, fmaxf(sacc[nt][2], sacc[nt][3]));
        }
        rm0 = fmaxf(rm0, __shfl_xor_sync(0xffffffffu, rm0, 1));
        rm0 = fmaxf(rm0, __shfl_xor_sync(0xffffffffu, rm0, 2));
        rm1 = fmaxf(rm1, __shfl_xor_sync(0xffffffffu, rm1, 1));
        rm1 = fmaxf(rm1, __shfl_xor_sync(0xffffffffu, rm1, 2));
        float mn0 = fmaxf(mi0, rm0), mn1 = fmaxf(mi1, rm1);
        float co0 = __expf(mi0 - mn0), co1 = __expf(mi1 - mn1);
        mi0 = mn0; mi1 = mn1;

        float rs0 = 0.0f, rs1 = 0.0f;
#pragma unroll
        for (int nt = 0; nt < 8; nt++) {
            float p0 = __expf(sacc[nt][0] - mn0);
            float p1 = __expf(sacc[nt][1] - mn0);
            float p2 = __expf(sacc[nt][2] - mn1);
            float p3 = __expf(sacc[nt][3] - mn1);
            rs0 += p0 + p1;
            rs1 += p2 + p3;
            int col = (nt * 8 + 2 * t) ^ sw0;
            uint32_t* p_lo = &Pw[g * PPAD + col];
            uint32_t* p_hi = &Pw[(g + 8) * PPAD + col];
            p_lo[0] = f2tf32(p0); p_lo[1] = f2tf32(p1);
            p_hi[0] = f2tf32(p2); p_hi[1] = f2tf32(p3);
        }
        rs0 += __shfl_xor_sync(0xffffffffu, rs0, 1);
        rs0 += __shfl_xor_sync(0xffffffffu, rs0, 2);
        rs1 += __shfl_xor_sync(0xffffffffu, rs1, 1);
        rs1 += __shfl_xor_sync(0xffffffffu, rs1, 2);
        li0 = li0 * co0 + rs0;
        li1 = li1 * co1 + rs1;
#pragma unroll
        for (int nt = 0; nt < 8; nt++) {
            oa[nt][0] *= co0; oa[nt][1] *= co0;
            oa[nt][2] *= co1; oa[nt][3] *= co1;
        }
        __syncwarp();

        // ---- O += P @ V  (16 x 64 per warp) ----
#pragma unroll
        for (int ks = 0; ks < 8; ks++) {
            const int kcd = ks * 8;
            uint32_t af[4];
            af[0] = Pw[g * PPAD + ((kcd + t) ^ sw0)];
            af[1] = Pw[(g + 8) * PPAD + ((kcd + t) ^ sw0)];
            af[2] = Pw[g * PPAD + ((kcd + t + 4) ^ sw0)];
            af[3] = Pw[(g + 8) * PPAD + ((kcd + t + 4) ^ sw0)];
#pragma unroll
            for (int nt = 0; nt < 8; nt++) {
                uint32_t bf[2];
                bf[0] = Vs[(kcd + t) * KPAD + nt * 8 + g];
                bf[1] = Vs[(kcd + t + 4) * KPAD + nt * 8 + g];
                mma_tf32(oa[nt], af, bf);
            }
        }
        __syncthreads();
    }

    // ---- epilogue: normalize + store ----
    float inv0 = 1.0f / li0, inv1 = 1.0f / li1;
    float* ob = o + ((size_t)(bq * CN + qrow)) * CD + h * CHD;
#pragma unroll
    for (int nt = 0; nt < 8; nt++) {
        int col = nt * 8 + 2 * t;
        float2 r0 = {oa[nt][0] * inv0, oa[nt][1] * inv0};
        float2 r1 = {oa[nt][2] * inv1, oa[nt][3] * inv1};
        *(float2*)(ob + (size_t)g * CD + col)       = r0;
        *(float2*)(ob + (size_t)(g + 8) * CD + col) = r1;
    }
}

// ---------------------------------------------------------------------------
// E2 = emb[:4] @ Wik   (tiny)
// ---------------------------------------------------------------------------
__global__ void e2_k(const float* __restrict__ emb, const float* __restrict__ Wik) {
    int n = blockIdx.x * 256 + threadIdx.x;
    int i = n >> 10;
    int c = n & 1023;
    const float* ep = emb + i * 1024;
    float acc = 0.0f;
#pragma unroll 4
    for (int kk = 0; kk < 1024; kk++)
        acc = fmaf(ep[kk], Wik[(size_t)kk * 1024 + c], acc);
    g_e2[n] = acc;
}

__global__ void ikb_k(const float* __restrict__ mask, const float* __restrict__ bik,
                      float* __restrict__ ik) {
    int idx = blockIdx.x * 256 + threadIdx.x;
    int d  = idx & 1023;
    int bn = idx >> 10;
    const float* mp = mask + (size_t)bn * 4;
    float acc = bik[d];
    acc = fmaf(mp[0], g_e2[d],        acc);
    acc = fmaf(mp[1], g_e2[1024 + d], acc);
    acc = fmaf(mp[2], g_e2[2048 + d], acc);
    acc = fmaf(mp[3], g_e2[3072 + d], acc);
    ik[idx] = acc;
}

// ---------------------------------------------------------------------------
// launch
// ---------------------------------------------------------------------------
extern "C" void kernel_launch(void* const* d_in, const int* in_sizes, int n_in,
                              void* d_out, int out_size)
{
    (void)in_sizes; (void)n_in; (void)out_size;
    const float* x    = (const float*)d_in[0];
    const float* mask = (const float*)d_in[1];
    const float* Wq   = (const float*)d_in[2];
    const float* bq   = (const float*)d_in[3];
    const float* Wk   = (const float*)d_in[4];
    const float* bk   = (const float*)d_in[5];
    const float* Wv   = (const float*)d_in[6];
    const float* bv   = (const float*)d_in[7];
    const float* Wo   = (const float*)d_in[8];
    const float* bo   = (const float*)d_in[9];
    const float* Wiq  = (const float*)d_in[10];
    const float* biq  = (const float*)d_in[11];
    const float* Wik  = (const float*)d_in[12];
    const float* bik  = (const float*)d_in[13];
    const float* emb  = (const float*)d_in[14];
    const float* qw   = (const float*)d_in[15];
    const float* kw   = (const float*)d_in[16];
    float* out = (float*)d_out;

    float *qp, *kp, *vp, *op, *iqp, *ikp;
    cudaGetSymbolAddress((void**)&qp,  g_q);
    cudaGetSymbolAddress((void**)&kp,  g_k);
    cudaGetSymbolAddress((void**)&vp,  g_v);
    cudaGetSymbolAddress((void**)&op,  g_o);
    cudaGetSymbolAddress((void**)&iqp, g_iq);
    cudaGetSymbolAddress((void**)&ikp, g_ik);

    static bool attr_done = false;
    if (!attr_done) {
        cudaFuncSetAttribute(attn_t, cudaFuncAttributeMaxDynamicSharedMemorySize,
                             SMEM_ATTN);
        attr_done = true;
    }

    dim3 gemm_grid(8, 32);   // (N/128, M/128)

    zero_gacc_k<<<16, 256>>>();

    gemm_t<false><<<gemm_grid, 256>>>(x, Wq, bq, qp);
    gemm_t<false><<<gemm_grid, 256>>>(x, Wk, bk, kp);
    gemm_t<false><<<gemm_grid, 256>>>(x, Wv, bv, vp);

    rms_k<<<8192, 256>>>(qp, qw);
    rms_k<<<8192, 256>>>(kp, kw);

    attn_t<<<dim3(4, 8, 16), 256, SMEM_ATTN>>>(qp, kp, vp, op);

    e2_k<<<16, 256>>>(emb, Wik);
    ikb_k<<<16384, 256>>>(mask, bik, ikp);

    gemm_t<false><<<gemm_grid, 256>>>(op, Wiq, biq, iqp);

    instgate_t<<<dim3(4, 4, 8), 256>>>(iqp, ikp);

    gemm_t<true><<<gemm_grid, 256>>>(op, Wo, bo, out);
}

// round 5
// speedup vs baseline: 2.6633x; 1.0567x over previous
#include <cuda_runtime.h>
#include <cstdint>
#include <cstddef>

// ---------------------------------------------------------------------------
// MIDIMultiInstanceAttention  (B=8, N=512, D=1024, H=16, HD=64, NI=4)
// pre-converted tf32 operands + cp.async double-buffered tensor-core kernels
// ---------------------------------------------------------------------------

#define CB 8
#define CN 512
#define CD 1024
#define CH 16
#define CHD 64
#define CM 4096
#define ATT_SCALE 0.125f
#define INST_SCALE (0.125f / 16.0f)

#define APAD 36
#define BPAD 136
#define KPAD 68
#define PPAD 72

#define GA_AW (128 * APAD)          // 4608 words
#define GA_BW (32 * BPAD)           // 4352 words
#define GA_STAGE (GA_AW + GA_BW)    // 8960 words
#define SMEM_GEMM (2 * GA_STAGE * 4)        // 71680 B

#define AT_KV (64 * KPAD)           // 4352 words per tensor
#define AT_STAGE (2 * AT_KV)        // 8704 words (K+V)
#define SMEM_ATTN ((2 * AT_STAGE + 8 * 16 * PPAD) * 4)   // 106496 B

// scratch (device globals: allocation-free rule)
__device__ __align__(16) uint32_t g_xt[CM * CD];   // tf32(x)
__device__ __align__(16) uint32_t g_wq[CD * CD];
__device__ __align__(16) uint32_t g_wk[CD * CD];
__device__ __align__(16) uint32_t g_wv[CD * CD];
__device__ __align__(16) uint32_t g_wiq[CD * CD];
__device__ __align__(16) uint32_t g_wo[CD * CD];
__device__ __align__(16) float g_q [CM * CD];      // tf32 bits
__device__ __align__(16) float g_k [CM * CD];      // tf32 bits
__device__ __align__(16) float g_v [CM * CD];      // tf32 bits
__device__ __align__(16) float g_o [CM * CD];      // tf32 bits
__device__ __align__(16) float g_iq[CM * CD];      // tf32 bits
__device__ __align__(16) float g_ik[CM * CD];      // f32 (cvt'd in instgate)
__device__ __align__(16) float g_e2[4 * CD];
__device__ float g_gacc[CM];

__global__ void zero_gacc_k() {
    int i = blockIdx.x * 256 + threadIdx.x;
    if (i < CM) g_gacc[i] = 0.0f;
}

// ---------------------------------------------------------------------------
// helpers
// ---------------------------------------------------------------------------
__device__ __forceinline__ uint32_t f2tf32(float x) {
    uint32_t r;
    asm("cvt.rna.tf32.f32 %0, %1;" : "=r"(r) : "f"(x));
    return r;
}

__device__ __forceinline__ void mma_tf32(float* d, const uint32_t* a, const uint32_t* b) {
    asm volatile(
        "mma.sync.aligned.m16n8k8.row.col.f32.tf32.tf32.f32 "
        "{%0,%1,%2,%3}, {%4,%5,%6,%7}, {%8,%9}, {%0,%1,%2,%3};\n"
        : "+f"(d[0]), "+f"(d[1]), "+f"(d[2]), "+f"(d[3])
        : "r"(a[0]), "r"(a[1]), "r"(a[2]), "r"(a[3]), "r"(b[0]), "r"(b[1]));
}

__device__ __forceinline__ void cp16(uint32_t dst, const void* src) {
    asm volatile("cp.async.cg.shared.global [%0], [%1], 16;\n" :: "r"(dst), "l"(src));
}
#define CP_COMMIT() asm volatile("cp.async.commit_group;\n")
#define CP_WAIT0()  asm volatile("cp.async.wait_group 0;\n")

// f32 -> tf32 bits (rna), vectorized
__global__ void cvt_k(const float* __restrict__ in, uint32_t* __restrict__ out, int n4) {
    int i = blockIdx.x * 256 + threadIdx.x;
    if (i < n4) {
        float4 v = ((const float4*)in)[i];
        uint4 o = {f2tf32(v.x), f2tf32(v.y), f2tf32(v.z), f2tf32(v.w)};
        ((uint4*)out)[i] = o;
    }
}

// ---------------------------------------------------------------------------
// async tf32 GEMM: C[4096,1024] = A @ W (+bias, + mode epilogue)
// A, W pre-converted tf32 bits. 128x128x32 tile, 2-stage cp.async pipeline.
// MODE 0: store tf32 bits
// MODE 1: QK-RMSNorm fused (per 64-col head), store tf32 bits
// MODE 2: gate rows by 1+gacc/512 (post-GEMM, exact), store f32
// ---------------------------------------------------------------------------
template <int MODE>
__global__ __launch_bounds__(256, 2) void gemm_a(
    const uint32_t* __restrict__ A, const uint32_t* __restrict__ W,
    const float* __restrict__ bias, const float* __restrict__ normw,
    float* __restrict__ C)
{
    extern __shared__ uint32_t sm[];
    const int tid  = threadIdx.x;
    const int lane = tid & 31;
    const int warp = tid >> 5;
    const int wm   = warp >> 2;
    const int wn   = warp & 3;
    const int bm   = blockIdx.y * 128;
    const int bn   = blockIdx.x * 128;
    const int g    = lane >> 2;
    const int t    = lane & 3;
    const uint32_t sb = (uint32_t)__cvta_generic_to_shared(sm);

    float acc[4][4][4];
#pragma unroll
    for (int i = 0; i < 4; i++)
#pragma unroll
        for (int j = 0; j < 4; j++)
#pragma unroll
            for (int r = 0; r < 4; r++) acc[i][j][r] = 0.0f;

    auto load_stage = [&](int kt, int st) {
        uint32_t as = sb + (uint32_t)(st * GA_STAGE) * 4u;
        uint32_t bs = as + GA_AW * 4u;
#pragma unroll
        for (int p = 0; p < 4; p++) {
            int idx = p * 256 + tid;
            int r = idx >> 3, c4 = (idx & 7) << 2;
            cp16(as + (uint32_t)(r * APAD + c4) * 4u,
                 A + (size_t)(bm + r) * CD + kt + c4);
        }
#pragma unroll
        for (int p = 0; p < 4; p++) {
            int idx = p * 256 + tid;
            int kk = idx >> 5, c4 = (idx & 31) << 2;
            cp16(bs + (uint32_t)(kk * BPAD + c4) * 4u,
                 W + (size_t)(kt + kk) * CD + bn + c4);
        }
        CP_COMMIT();
    };

    load_stage(0, 0);
    int st = 0;

    for (int it = 0; it < 32; it++) {
        CP_WAIT0();
        __syncthreads();
        if (it < 31) load_stage((it + 1) * 32, st ^ 1);

        const uint32_t* As = sm + st * GA_STAGE;
        const uint32_t* Bs = As + GA_AW;
#pragma unroll
        for (int ks = 0; ks < 4; ks++) {
            const int kc = ks * 8;
            uint32_t af[4][4], bf[4][2];
#pragma unroll
            for (int mt = 0; mt < 4; mt++) {
                int row = wm * 64 + mt * 16 + g;
                af[mt][0] = As[row * APAD + kc + t];
                af[mt][1] = As[(row + 8) * APAD + kc + t];
                af[mt][2] = As[row * APAD + kc + t + 4];
                af[mt][3] = As[(row + 8) * APAD + kc + t + 4];
            }
#pragma unroll
            for (int nt = 0; nt < 4; nt++) {
                int col = wn * 32 + nt * 8 + g;
                bf[nt][0] = Bs[(kc + t) * BPAD + col];
                bf[nt][1] = Bs[(kc + t + 4) * BPAD + col];
            }
#pragma unroll
            for (int mt = 0; mt < 4; mt++)
#pragma unroll
                for (int nt = 0; nt < 4; nt++)
                    mma_tf32(acc[mt][nt], af[mt], bf[nt]);
        }
        st ^= 1;
    }
    __syncthreads();   // smem reuse in NORM epilogue

    // bias per nt (float2)
    float2 bb[4];
#pragma unroll
    for (int nt = 0; nt < 4; nt++)
        bb[nt] = *(const float2*)(bias + bn + wn * 32 + nt * 8 + t * 2);

    if (MODE == 1) {
        // ---- fused RMSNorm over each 64-col head ----
        float ssA[4], ssB[4];
#pragma unroll
        for (int mt = 0; mt < 4; mt++) {
            float s0 = 0.0f, s1 = 0.0f;
#pragma unroll
            for (int nt = 0; nt < 4; nt++) {
                float v0 = acc[mt][nt][0] + bb[nt].x;
                float v1 = acc[mt][nt][1] + bb[nt].y;
                float v2 = acc[mt][nt][2] + bb[nt].x;
                float v3 = acc[mt][nt][3] + bb[nt].y;
                s0 = fmaf(v0, v0, s0); s0 = fmaf(v1, v1, s0);
                s1 = fmaf(v2, v2, s1); s1 = fmaf(v3, v3, s1);
            }
            s0 += __shfl_xor_sync(0xffffffffu, s0, 1);
            s0 += __shfl_xor_sync(0xffffffffu, s0, 2);
            s1 += __shfl_xor_sync(0xffffffffu, s1, 1);
            s1 += __shfl_xor_sync(0xffffffffu, s1, 2);
            ssA[mt] = s0; ssB[mt] = s1;
        }
        float* S = (float*)sm;    // [128 rows][4 wn]
        if (t == 0) {
#pragma unroll
            for (int mt = 0; mt < 4; mt++) {
                int r0 = wm * 64 + mt * 16 + g;
                S[r0 * 4 + wn]       = ssA[mt];
                S[(r0 + 8) * 4 + wn] = ssB[mt];
            }
        }
        __syncthreads();
        const int pi = wn & ~1;
        uint32_t* Cu = (uint32_t*)C;
#pragma unroll
        for (int mt = 0; mt < 4; mt++) {
            int r0 = wm * 64 + mt * 16 + g;
            float sc0 = rsqrtf((S[r0 * 4 + pi] + S[r0 * 4 + pi + 1]) * (1.0f / 64.0f) + 1e-6f);
            float sc1 = rsqrtf((S[(r0 + 8) * 4 + pi] + S[(r0 + 8) * 4 + pi + 1]) * (1.0f / 64.0f) + 1e-6f);
#pragma unroll
            for (int nt = 0; nt < 4; nt++) {
                int cl = wn * 32 + nt * 8 + t * 2;
                float2 ww = *(const float2*)(normw + (cl & 63));
                float v0 = acc[mt][nt][0] + bb[nt].x;
                float v1 = acc[mt][nt][1] + bb[nt].y;
                float v2 = acc[mt][nt][2] + bb[nt].x;
                float v3 = acc[mt][nt][3] + bb[nt].y;
                uint2 o0 = {f2tf32(v0 * sc0 * ww.x), f2tf32(v1 * sc0 * ww.y)};
                uint2 o1 = {f2tf32(v2 * sc1 * ww.x), f2tf32(v3 * sc1 * ww.y)};
                *(uint2*)(Cu + (size_t)(bm + r0) * CD + bn + cl)     = o0;
                *(uint2*)(Cu + (size_t)(bm + r0 + 8) * CD + bn + cl) = o1;
            }
        }
    } else if (MODE == 2) {
        // ---- gate epilogue, f32 out ----
#pragma unroll
        for (int mt = 0; mt < 4; mt++) {
            int r0 = bm + wm * 64 + mt * 16 + g;
            float ga0 = 1.0f + g_gacc[r0]     * (1.0f / 512.0f);
            float ga1 = 1.0f + g_gacc[r0 + 8] * (1.0f / 512.0f);
#pragma unroll
            for (int nt = 0; nt < 4; nt++) {
                int col = bn + wn * 32 + nt * 8 + t * 2;
                float2 w0 = {acc[mt][nt][0] * ga0 + bb[nt].x, acc[mt][nt][1] * ga0 + bb[nt].y};
                float2 w1 = {acc[mt][nt][2] * ga1 + bb[nt].x, acc[mt][nt][3] * ga1 + bb[nt].y};
                *(float2*)(C + (size_t)r0 * CD + col)       = w0;
                *(float2*)(C + (size_t)(r0 + 8) * CD + col) = w1;
            }
        }
    } else {
        // ---- plain, store tf32 bits ----
        uint32_t* Cu = (uint32_t*)C;
#pragma unroll
        for (int mt = 0; mt < 4; mt++) {
            int r0 = bm + wm * 64 + mt * 16 + g;
#pragma unroll
            for (int nt = 0; nt < 4; nt++) {
                int col = bn + wn * 32 + nt * 8 + t * 2;
                uint2 o0 = {f2tf32(acc[mt][nt][0] + bb[nt].x), f2tf32(acc[mt][nt][1] + bb[nt].y)};
                uint2 o1 = {f2tf32(acc[mt][nt][2] + bb[nt].x), f2tf32(acc[mt][nt][3] + bb[nt].y)};
                *(uint2*)(Cu + (size_t)r0 * CD + col)       = o0;
                *(uint2*)(Cu + (size_t)(r0 + 8) * CD + col) = o1;
            }
        }
    }
}

// ---------------------------------------------------------------------------
// instance gate (tf32, validated R3): per batch S = iq[b] @ ik[b]^T
// inputs already tf32 bits (cvt is idempotent)
// ---------------------------------------------------------------------------
__global__ __launch_bounds__(256, 2) void instgate_t(
    const float* __restrict__ iq, const float* __restrict__ ikp)
{
    __shared__ uint32_t As[128 * APAD];
    __shared__ uint32_t Bs[128 * APAD];

    const int tid  = threadIdx.x;
    const int lane = tid & 31;
    const int warp = tid >> 5;
    const int wm   = warp >> 2;
    const int wn   = warp & 3;
    const int b    = blockIdx.z;
    const int bm   = blockIdx.y * 128;
    const int bn   = blockIdx.x * 128;
    const int g    = lane >> 2;
    const int t    = lane & 3;
    const float* Ab = iq  + (size_t)b * 512 * CD;
    const float* Bb = ikp + (size_t)b * 512 * CD;

    float acc[4][4][4];
#pragma unroll
    for (int i = 0; i < 4; i++)
#pragma unroll
        for (int j = 0; j < 4; j++)
#pragma unroll
            for (int r = 0; r < 4; r++) acc[i][j][r] = 0.0f;

    for (int kt = 0; kt < CD; kt += 32) {
#pragma unroll
        for (int p = 0; p < 4; p++) {
            int idx = p * 256 + tid;
            int r   = idx >> 3;
            int c4  = (idx & 7) << 2;
            float4 va = *(const float4*)(Ab + (size_t)(bm + r) * CD + kt + c4);
            float4 vb = *(const float4*)(Bb + (size_t)(bn + r) * CD + kt + c4);
            uint4 sa = {f2tf32(va.x), f2tf32(va.y), f2tf32(va.z), f2tf32(va.w)};
            uint4 sb = {f2tf32(vb.x), f2tf32(vb.y), f2tf32(vb.z), f2tf32(vb.w)};
            *(uint4*)&As[r * APAD + c4] = sa;
            *(uint4*)&Bs[r * APAD + c4] = sb;
        }
        __syncthreads();

#pragma unroll
        for (int ks = 0; ks < 4; ks++) {
            const int kc = ks * 8;
            uint32_t af[4][4], bf[4][2];
#pragma unroll
            for (int mt = 0; mt < 4; mt++) {
                int row = wm * 64 + mt * 16 + g;
                af[mt][0] = As[row * APAD + kc + t];
                af[mt][1] = As[(row + 8) * APAD + kc + t];
                af[mt][2] = As[row * APAD + kc + t + 4];
                af[mt][3] = As[(row + 8) * APAD + kc + t + 4];
            }
#pragma unroll
            for (int nt = 0; nt < 4; nt++) {
                int col = wn * 32 + nt * 8 + g;
                bf[nt][0] = Bs[col * APAD + kc + t];
                bf[nt][1] = Bs[col * APAD + kc + t + 4];
            }
#pragma unroll
            for (int mt = 0; mt < 4; mt++)
#pragma unroll
                for (int nt = 0; nt < 4; nt++)
                    mma_tf32(acc[mt][nt], af[mt], bf[nt]);
        }
        __syncthreads();
    }

#pragma unroll
    for (int mt = 0; mt < 4; mt++) {
        float s0 = 0.0f, s1 = 0.0f;
#pragma unroll
        for (int nt = 0; nt < 4; nt++) {
            s0 += 1.0f / (1.0f + __expf(-acc[mt][nt][0] * INST_SCALE));
            s0 += 1.0f / (1.0f + __expf(-acc[mt][nt][1] * INST_SCALE));
            s1 += 1.0f / (1.0f + __expf(-acc[mt][nt][2] * INST_SCALE));
            s1 += 1.0f / (1.0f + __expf(-acc[mt][nt][3] * INST_SCALE));
        }
        s0 += __shfl_xor_sync(0xffffffffu, s0, 1);
        s0 += __shfl_xor_sync(0xffffffffu, s0, 2);
        s1 += __shfl_xor_sync(0xffffffffu, s1, 1);
        s1 += __shfl_xor_sync(0xffffffffu, s1, 2);
        if (t == 0) {
            int row = bm + wm * 64 + mt * 16 + g;
            atomicAdd(&g_gacc[b * 512 + row], s0);
            atomicAdd(&g_gacc[b * 512 + row + 8], s1);
        }
    }
}

// ---------------------------------------------------------------------------
// tf32 tensor-core grouped flash attention, cp.async double-buffered K/V.
// q/k/v already tf32 bits. grid (qtile 4, b 8, h 16), 256 threads.
// ---------------------------------------------------------------------------
__global__ __launch_bounds__(256, 2) void attn_t(
    const float* __restrict__ q, const float* __restrict__ k,
    const float* __restrict__ v, float* __restrict__ o)
{
    extern __shared__ uint32_t sm[];
    uint32_t* Ps = sm + 2 * AT_STAGE;      // per-warp [16][PPAD]

    const int tid  = threadIdx.x;
    const int lane = tid & 31;
    const int warp = tid >> 5;
    const int g    = lane >> 2;
    const int t    = lane & 3;
    const int bq   = blockIdx.y;
    const int h    = blockIdx.z;
    const int n0   = blockIdx.x * 128;
    const int gb   = bq & ~3;
    const int qrow = n0 + warp * 16;
    const uint32_t sb = (uint32_t)__cvta_generic_to_shared(sm);

    // Q fragments, register-resident (scale by 2^-3: exact, stays tf32)
    uint32_t qf[8][4];
    {
        const float* qb = q + ((size_t)(bq * CN + qrow)) * CD + h * CHD;
#pragma unroll
        for (int ks = 0; ks < 8; ks++) {
            int c = ks * 8 + t;
            qf[ks][0] = __float_as_uint(qb[(size_t)g * CD + c]           * ATT_SCALE);
            qf[ks][1] = __float_as_uint(qb[(size_t)(g + 8) * CD + c]     * ATT_SCALE);
            qf[ks][2] = __float_as_uint(qb[(size_t)g * CD + c + 4]       * ATT_SCALE);
            qf[ks][3] = __float_as_uint(qb[(size_t)(g + 8) * CD + c + 4] * ATT_SCALE);
        }
    }

    float oa[8][4];
#pragma unroll
    for (int nt = 0; nt < 8; nt++)
#pragma unroll
        for (int r = 0; r < 4; r++) oa[nt][r] = 0.0f;
    float mi0 = -1e30f, mi1 = -1e30f, li0 = 0.0f, li1 = 0.0f;

    uint32_t* Pw = Ps + warp * 16 * PPAD;
    const int sw0 = (g & 4) ? 4 : 0;

    auto load_kv = [&](int kc, int stg) {
        const int m0 = kc * 64;
        const int kb = gb + (m0 >> 9);
        const int kn = m0 & 511;
        uint32_t ksm = sb + (uint32_t)(stg * AT_STAGE) * 4u;
        uint32_t vsm = ksm + AT_KV * 4u;
#pragma unroll
        for (int p = 0; p < 4; p++) {
            int idx = p * 256 + tid;
            int r   = idx >> 4;
            int c4  = (idx & 15) << 2;
            size_t base = ((size_t)(kb * CN + kn + r)) * CD + h * CHD + c4;
            uint32_t off = (uint32_t)(r * KPAD + c4) * 4u;
            cp16(ksm + off, k + base);
            cp16(vsm + off, v + base);
        }
        CP_COMMIT();
    };

    load_kv(0, 0);
    int st = 0;

    for (int kc = 0; kc < 32; kc++) {
        CP_WAIT0();
        __syncthreads();
        if (kc < 31) load_kv(kc + 1, st ^ 1);

        const uint32_t* Ks = sm + st * AT_STAGE;
        const uint32_t* Vs = Ks + AT_KV;

        // ---- S = Q @ K^T ----
        float sacc[8][4];
#pragma unroll
        for (int nt = 0; nt < 8; nt++)
#pragma unroll
            for (int r = 0; r < 4; r++) sacc[nt][r] = 0.0f;
#pragma unroll
        for (int ks = 0; ks < 8; ks++) {
            const int kcd = ks * 8;
#pragma unroll
            for (int nt = 0; nt < 8; nt++) {
                uint32_t bf[2];
                bf[0] = Ks[(nt * 8 + g) * KPAD + kcd + t];
                bf[1] = Ks[(nt * 8 + g) * KPAD + kcd + t + 4];
                mma_tf32(sacc[nt], qf[ks], bf);
            }
        }

        // ---- online softmax ----
        float rm0 = -1e30f, rm1 = -1e30f;
#pragma unroll
        for (int nt = 0; nt < 8; nt++) {
            rm0 = fmaxf(rm0, fmaxf(sacc[nt][0], sacc[nt][1]));
            rm1 = fmaxf(rm1, fmaxf(sacc[nt][2], sacc[nt][3]));
        }
        rm0 = fmaxf(rm0, __shfl_xor_sync(0xffffffffu, rm0, 1));
        rm0 = fmaxf(rm0, __shfl_xor_sync(0xffffffffu, rm0, 2));
        rm1 = fmaxf(rm1, __shfl_xor_sync(0xffffffffu, rm1, 1));
        rm1 = fmaxf(rm1, __shfl_xor_sync(0xffffffffu, rm1, 2));
        float mn0 = fmaxf(mi0, rm0), mn1 = fmaxf(mi1, rm1);
        float co0 = __expf(mi0 - mn0), co1 = __expf(mi1 - mn1);
        mi0 = mn0; mi1 = mn1;

        float rs0 = 0.0f, rs1 = 0.0f;
#pragma unroll
        for (int nt = 0; nt < 8; nt++) {
            float p0 = __expf(sacc[nt][0] - mn0);
            float p1 = __expf(sacc[nt][1] - mn0);
            float p2 = __expf(sacc[nt][2] - mn1);
            float p3 = __expf(sacc[nt][3] - mn1);
            rs0 += p0 + p1;
            rs1 += p2 + p3;
            int col = (nt * 8 + 2 * t) ^ sw0;
            uint32_t* p_lo = &Pw[g * PPAD + col];
            uint32_t* p_hi = &Pw[(g + 8) * PPAD + col];
            p_lo[0] = f2tf32(p0); p_lo[1] = f2tf32(p1);
            p_hi[0] = f2tf32(p2); p_hi[1] = f2tf32(p3);
        }
        rs0 += __shfl_xor_sync(0xffffffffu, rs0, 1);
        rs0 += __shfl_xor_sync(0xffffffffu, rs0, 2);
        rs1 += __shfl_xor_sync(0xffffffffu, rs1, 1);
        rs1 += __shfl_xor_sync(0xffffffffu, rs1, 2);
        li0 = li0 * co0 + rs0;
        li1 = li1 * co1 + rs1;
#pragma unroll
        for (int nt = 0; nt < 8; nt++) {
            oa[nt][0] *= co0; oa[nt][1] *= co0;
            oa[nt][2] *= co1; oa[nt][3] *= co1;
        }
        __syncwarp();

        // ---- O += P @ V ----
#pragma unroll
        for (int ks = 0; ks < 8; ks++) {
            const int kcd = ks * 8;
            uint32_t af[4];
            af[0] = Pw[g * PPAD + ((kcd + t) ^ sw0)];
            af[1] = Pw[(g + 8) * PPAD + ((kcd + t) ^ sw0)];
            af[2] = Pw[g * PPAD + ((kcd + t + 4) ^ sw0)];
            af[3] = Pw[(g + 8) * PPAD + ((kcd + t + 4) ^ sw0)];
#pragma unroll
            for (int nt = 0; nt < 8; nt++) {
                uint32_t bf[2];
                bf[0] = Vs[(kcd + t) * KPAD + nt * 8 + g];
                bf[1] = Vs[(kcd + t + 4) * KPAD + nt * 8 + g];
                mma_tf32(oa[nt], af, bf);
            }
        }
        __syncwarp();   // P reads done before next chunk's P writes
        st ^= 1;
    }

    // ---- epilogue: normalize + store tf32 bits ----
    float inv0 = 1.0f / li0, inv1 = 1.0f / li1;
    uint32_t* ob = (uint32_t*)(o + ((size_t)(bq * CN + qrow)) * CD + h * CHD);
#pragma unroll
    for (int nt = 0; nt < 8; nt++) {
        int col = nt * 8 + 2 * t;
        uint2 r0 = {f2tf32(oa[nt][0] * inv0), f2tf32(oa[nt][1] * inv0)};
        uint2 r1 = {f2tf32(oa[nt][2] * inv1), f2tf32(oa[nt][3] * inv1)};
        *(uint2*)(ob + (size_t)g * CD + col)       = r0;
        *(uint2*)(ob + (size_t)(g + 8) * CD + col) = r1;
    }
}

// ---------------------------------------------------------------------------
// E2 = emb[:4] @ Wik   (tiny, fp32)
// ---------------------------------------------------------------------------
__global__ void e2_k(const float* __restrict__ emb, const float* __restrict__ Wik) {
    int n = blockIdx.x * 256 + threadIdx.x;
    int i = n >> 10;
    int c = n & 1023;
    const float* ep = emb + i * 1024;
    float acc = 0.0f;
#pragma unroll 4
    for (int kk = 0; kk < 1024; kk++)
        acc = fmaf(ep[kk], Wik[(size_t)kk * 1024 + c], acc);
    g_e2[n] = acc;
}

__global__ void ikb_k(const float* __restrict__ mask, const float* __restrict__ bik,
                      float* __restrict__ ik) {
    int idx = blockIdx.x * 256 + threadIdx.x;
    int d  = idx & 1023;
    int bn = idx >> 10;
    const float* mp = mask + (size_t)bn * 4;
    float acc = bik[d];
    acc = fmaf(mp[0], g_e2[d],        acc);
    acc = fmaf(mp[1], g_e2[1024 + d], acc);
    acc = fmaf(mp[2], g_e2[2048 + d], acc);
    acc = fmaf(mp[3], g_e2[3072 + d], acc);
    ik[idx] = acc;
}

// ---------------------------------------------------------------------------
// launch
// ---------------------------------------------------------------------------
extern "C" void kernel_launch(void* const* d_in, const int* in_sizes, int n_in,
                              void* d_out, int out_size)
{
    (void)in_sizes; (void)n_in; (void)out_size;
    const float* x    = (const float*)d_in[0];
    const float* mask = (const float*)d_in[1];
    const float* Wq   = (const float*)d_in[2];
    const float* bq   = (const float*)d_in[3];
    const float* Wk   = (const float*)d_in[4];
    const float* bk   = (const float*)d_in[5];
    const float* Wv   = (const float*)d_in[6];
    const float* bv   = (const float*)d_in[7];
    const float* Wo   = (const float*)d_in[8];
    const float* bo   = (const float*)d_in[9];
    const float* Wiq  = (const float*)d_in[10];
    const float* biq  = (const float*)d_in[11];
    const float* Wik  = (const float*)d_in[12];
    const float* bik  = (const float*)d_in[13];
    const float* emb  = (const float*)d_in[14];
    const float* qw   = (const float*)d_in[15];
    const float* kw   = (const float*)d_in[16];
    float* out = (float*)d_out;

    float *qp, *kp, *vp, *op, *iqp, *ikp;
    uint32_t *xt, *wq, *wk, *wv, *wiq, *wo;
    cudaGetSymbolAddress((void**)&qp,  g_q);
    cudaGetSymbolAddress((void**)&kp,  g_k);
    cudaGetSymbolAddress((void**)&vp,  g_v);
    cudaGetSymbolAddress((void**)&op,  g_o);
    cudaGetSymbolAddress((void**)&iqp, g_iq);
    cudaGetSymbolAddress((void**)&ikp, g_ik);
    cudaGetSymbolAddress((void**)&xt,  g_xt);
    cudaGetSymbolAddress((void**)&wq,  g_wq);
    cudaGetSymbolAddress((void**)&wk,  g_wk);
    cudaGetSymbolAddress((void**)&wv,  g_wv);
    cudaGetSymbolAddress((void**)&wiq, g_wiq);
    cudaGetSymbolAddress((void**)&wo,  g_wo);

    static bool attr_done = false;
    if (!attr_done) {
        cudaFuncSetAttribute(gemm_a<0>, cudaFuncAttributeMaxDynamicSharedMemorySize, SMEM_GEMM);
        cudaFuncSetAttribute(gemm_a<1>, cudaFuncAttributeMaxDynamicSharedMemorySize, SMEM_GEMM);
        cudaFuncSetAttribute(gemm_a<2>, cudaFuncAttributeMaxDynamicSharedMemorySize, SMEM_GEMM);
        cudaFuncSetAttribute(attn_t, cudaFuncAttributeMaxDynamicSharedMemorySize, SMEM_ATTN);
        attr_done = true;
    }

    dim3 gemm_grid(8, 32);

    zero_gacc_k<<<16, 256>>>();

    // pre-convert operands to tf32 bits
    cvt_k<<<4096, 256>>>(x,   xt,  CM * CD / 4);
    cvt_k<<<1024, 256>>>(Wq,  wq,  CD * CD / 4);
    cvt_k<<<1024, 256>>>(Wk,  wk,  CD * CD / 4);
    cvt_k<<<1024, 256>>>(Wv,  wv,  CD * CD / 4);
    cvt_k<<<1024, 256>>>(Wiq, wiq, CD * CD / 4);
    cvt_k<<<1024, 256>>>(Wo,  wo,  CD * CD / 4);

    gemm_a<1><<<gemm_grid, 256, SMEM_GEMM>>>(xt, wq, bq, qw, qp);
    gemm_a<1><<<gemm_grid, 256, SMEM_GEMM>>>(xt, wk, bk, kw, kp);
    gemm_a<0><<<gemm_grid, 256, SMEM_GEMM>>>(xt, wv, bv, nullptr, vp);

    attn_t<<<dim3(4, 8, 16), 256, SMEM_ATTN>>>(qp, kp, vp, op);

    e2_k<<<16, 256>>>(emb, Wik);
    ikb_k<<<16384, 256>>>(mask, bik, ikp);

    gemm_a<0><<<gemm_grid, 256, SMEM_GEMM>>>((const uint32_t*)op, wiq, biq, nullptr, iqp);

    instgate_t<<<dim3(4, 4, 8), 256>>>(iqp, ikp);

    gemm_a<2><<<gemm_grid, 256, SMEM_GEMM>>>((const uint32_t*)op, wo, bo, nullptr, out);
}

// round 7
// speedup vs baseline: 2.7388x; 1.0284x over previous
#include <cuda_runtime.h>
#include <cstdint>
#include <cstddef>

// ---------------------------------------------------------------------------
// MIDIMultiInstanceAttention  (B=8, N=512, D=1024, H=16, HD=64, NI=4)
// tf32 tensor-core everything; fixed-bound softmax (|s|<8 by RMSNorm+CS)
// ---------------------------------------------------------------------------

#define CB 8
#define CN 512
#define CD 1024
#define CH 16
#define CHD 64
#define CM 4096
#define ATT_SCALE 0.125f
#define SOFT_SHIFT 8.0f
#define INST_SCALE (0.125f / 16.0f)

#define APAD 36
#define BPAD 136
#define KPAD 68
#define PPAD 72

#define GA_AW (128 * APAD)
#define GA_BW (32 * BPAD)
#define GA_STAGE (GA_AW + GA_BW)
#define SMEM_GEMM (2 * GA_STAGE * 4)               // 71680 B

#define IG_STAGE (2 * 128 * APAD)                  // A+B, words
#define SMEM_IG (2 * IG_STAGE * 4)                 // 73728 B

#define AT_KV (64 * KPAD)
#define AT_STAGE (2 * AT_KV)
#define SMEM_ATTN ((2 * AT_STAGE + 8 * 16 * PPAD) * 4)   // 106496 B

// scratch (device globals: allocation-free rule)
__device__ __align__(16) uint32_t g_xt[CM * CD];
__device__ __align__(16) uint32_t g_wq[CD * CD];
__device__ __align__(16) uint32_t g_wk[CD * CD];
__device__ __align__(16) uint32_t g_wv[CD * CD];
__device__ __align__(16) uint32_t g_wiq[CD * CD];
__device__ __align__(16) uint32_t g_wo[CD * CD];
__device__ __align__(16) float g_q [CM * CD];      // tf32 bits (pre-scaled)
__device__ __align__(16) float g_k [CM * CD];      // tf32 bits
__device__ __align__(16) float g_v [CM * CD];      // tf32 bits
__device__ __align__(16) float g_o [CM * CD];      // tf32 bits
__device__ __align__(16) float g_iq[CM * CD];      // tf32 bits
__device__ __align__(16) uint32_t g_ik[CM * CD];   // tf32 bits
__device__ __align__(16) float g_e2[4 * CD];
__device__ float g_gacc[CM];

__global__ void zero_gacc_k() {
    int i = blockIdx.x * 256 + threadIdx.x;
    if (i < CM) g_gacc[i] = 0.0f;
}

// ---------------------------------------------------------------------------
// helpers
// ---------------------------------------------------------------------------
__device__ __forceinline__ uint32_t f2tf32(float x) {
    uint32_t r;
    asm("cvt.rna.tf32.f32 %0, %1;" : "=r"(r) : "f"(x));
    return r;
}

__device__ __forceinline__ void mma_tf32(float* d, const uint32_t* a, const uint32_t* b) {
    asm volatile(
        "mma.sync.aligned.m16n8k8.row.col.f32.tf32.tf32.f32 "
        "{%0,%1,%2,%3}, {%4,%5,%6,%7}, {%8,%9}, {%0,%1,%2,%3};\n"
        : "+f"(d[0]), "+f"(d[1]), "+f"(d[2]), "+f"(d[3])
        : "r"(a[0]), "r"(a[1]), "r"(a[2]), "r"(a[3]), "r"(b[0]), "r"(b[1]));
}

__device__ __forceinline__ void cp16(uint32_t dst, const void* src) {
    asm volatile("cp.async.cg.shared.global [%0], [%1], 16;\n" :: "r"(dst), "l"(src));
}
#define CP_COMMIT() asm volatile("cp.async.commit_group;\n")
#define CP_WAIT0()  asm volatile("cp.async.wait_group 0;\n")

// one launch converts x + 5 weight matrices to tf32 bits
__global__ void cvt_all_k(const float* __restrict__ x,
                          const float* __restrict__ w0, const float* __restrict__ w1,
                          const float* __restrict__ w2, const float* __restrict__ w3,
                          const float* __restrict__ w4,
                          uint32_t* __restrict__ xt,
                          uint32_t* __restrict__ o0, uint32_t* __restrict__ o1,
                          uint32_t* __restrict__ o2, uint32_t* __restrict__ o3,
                          uint32_t* __restrict__ o4)
{
    const int WQ4 = CD * CD / 4;        // 262144
    const int XQ4 = CM * CD / 4;        // 1048576
    int i = blockIdx.x * 256 + threadIdx.x;
    const float* src; uint32_t* dst; int off;
    if (i < XQ4)                { src = x;  dst = xt; off = i; }
    else if (i < XQ4 + WQ4)     { src = w0; dst = o0; off = i - XQ4; }
    else if (i < XQ4 + 2 * WQ4) { src = w1; dst = o1; off = i - XQ4 - WQ4; }
    else if (i < XQ4 + 3 * WQ4) { src = w2; dst = o2; off = i - XQ4 - 2 * WQ4; }
    else if (i < XQ4 + 4 * WQ4) { src = w3; dst = o3; off = i - XQ4 - 3 * WQ4; }
    else                        { src = w4; dst = o4; off = i - XQ4 - 4 * WQ4; }
    float4 v = ((const float4*)src)[off];
    uint4 o = {f2tf32(v.x), f2tf32(v.y), f2tf32(v.z), f2tf32(v.w)};
    ((uint4*)dst)[off] = o;
}

// ---------------------------------------------------------------------------
// fused QKV projection: z selects {Wq,Wk,Wv}. z<2 -> fused per-head RMSNorm
// (Q additionally pre-scaled by ATT_SCALE). stores tf32 bits.
// ---------------------------------------------------------------------------
__global__ __launch_bounds__(256, 2) void gemm_qkv(
    const uint32_t* __restrict__ A,
    const uint32_t* __restrict__ Wq_, const uint32_t* __restrict__ Wk_,
    const uint32_t* __restrict__ Wv_,
    const float* __restrict__ bq_, const float* __restrict__ bk_,
    const float* __restrict__ bv_,
    const float* __restrict__ qw_, const float* __restrict__ kw_,
    float* __restrict__ oq_, float* __restrict__ ok_, float* __restrict__ ov_)
{
    extern __shared__ uint32_t sm[];
    const int z = blockIdx.z;
    const uint32_t* W   = (z == 0) ? Wq_ : (z == 1) ? Wk_ : Wv_;
    const float* bias   = (z == 0) ? bq_ : (z == 1) ? bk_ : bv_;
    const float* normw  = (z == 0) ? qw_ : kw_;
    float* C            = (z == 0) ? oq_ : (z == 1) ? ok_ : ov_;
    const float qsc     = (z == 0) ? ATT_SCALE : 1.0f;

    const int tid  = threadIdx.x;
    const int lane = tid & 31;
    const int warp = tid >> 5;
    const int wm   = warp >> 2;
    const int wn   = warp & 3;
    const int bm   = blockIdx.y * 128;
    const int bn   = blockIdx.x * 128;
    const int g    = lane >> 2;
    const int t    = lane & 3;
    const uint32_t sb = (uint32_t)__cvta_generic_to_shared(sm);

    float acc[4][4][4];
#pragma unroll
    for (int i = 0; i < 4; i++)
#pragma unroll
        for (int j = 0; j < 4; j++)
#pragma unroll
            for (int r = 0; r < 4; r++) acc[i][j][r] = 0.0f;

    auto load_stage = [&](int kt, int st) {
        uint32_t as = sb + (uint32_t)(st * GA_STAGE) * 4u;
        uint32_t bs = as + GA_AW * 4u;
#pragma unroll
        for (int p = 0; p < 4; p++) {
            int idx = p * 256 + tid;
            int r = idx >> 3, c4 = (idx & 7) << 2;
            cp16(as + (uint32_t)(r * APAD + c4) * 4u,
                 A + (size_t)(bm + r) * CD + kt + c4);
        }
#pragma unroll
        for (int p = 0; p < 4; p++) {
            int idx = p * 256 + tid;
            int kk = idx >> 5, c4 = (idx & 31) << 2;
            cp16(bs + (uint32_t)(kk * BPAD + c4) * 4u,
                 W + (size_t)(kt + kk) * CD + bn + c4);
        }
        CP_COMMIT();
    };

    load_stage(0, 0);
    int st = 0;
    for (int it = 0; it < 32; it++) {
        CP_WAIT0();
        __syncthreads();
        if (it < 31) load_stage((it + 1) * 32, st ^ 1);
        const uint32_t* As = sm + st * GA_STAGE;
        const uint32_t* Bs = As + GA_AW;
#pragma unroll
        for (int ks = 0; ks < 4; ks++) {
            const int kc = ks * 8;
            uint32_t af[4][4], bf[4][2];
#pragma unroll
            for (int mt = 0; mt < 4; mt++) {
                int row = wm * 64 + mt * 16 + g;
                af[mt][0] = As[row * APAD + kc + t];
                af[mt][1] = As[(row + 8) * APAD + kc + t];
                af[mt][2] = As[row * APAD + kc + t + 4];
                af[mt][3] = As[(row + 8) * APAD + kc + t + 4];
            }
#pragma unroll
            for (int nt = 0; nt < 4; nt++) {
                int col = wn * 32 + nt * 8 + g;
                bf[nt][0] = Bs[(kc + t) * BPAD + col];
                bf[nt][1] = Bs[(kc + t + 4) * BPAD + col];
            }
#pragma unroll
            for (int mt = 0; mt < 4; mt++)
#pragma unroll
                for (int nt = 0; nt < 4; nt++)
                    mma_tf32(acc[mt][nt], af[mt], bf[nt]);
        }
        st ^= 1;
    }
    __syncthreads();

    float2 bb[4];
#pragma unroll
    for (int nt = 0; nt < 4; nt++)
        bb[nt] = *(const float2*)(bias + bn + wn * 32 + nt * 8 + t * 2);

    uint32_t* Cu = (uint32_t*)C;
    if (z < 2) {
        // fused per-head RMSNorm (+ATT_SCALE for Q)
        float ssA[4], ssB[4];
#pragma unroll
        for (int mt = 0; mt < 4; mt++) {
            float s0 = 0.0f, s1 = 0.0f;
#pragma unroll
            for (int nt = 0; nt < 4; nt++) {
                float v0 = acc[mt][nt][0] + bb[nt].x;
                float v1 = acc[mt][nt][1] + bb[nt].y;
                float v2 = acc[mt][nt][2] + bb[nt].x;
                float v3 = acc[mt][nt][3] + bb[nt].y;
                s0 = fmaf(v0, v0, s0); s0 = fmaf(v1, v1, s0);
                s1 = fmaf(v2, v2, s1); s1 = fmaf(v3, v3, s1);
            }
            s0 += __shfl_xor_sync(0xffffffffu, s0, 1);
            s0 += __shfl_xor_sync(0xffffffffu, s0, 2);
            s1 += __shfl_xor_sync(0xffffffffu, s1, 1);
            s1 += __shfl_xor_sync(0xffffffffu, s1, 2);
            ssA[mt] = s0; ssB[mt] = s1;
        }
        float* S = (float*)sm;
        if (t == 0) {
#pragma unroll
            for (int mt = 0; mt < 4; mt++) {
                int r0 = wm * 64 + mt * 16 + g;
                S[r0 * 4 + wn]       = ssA[mt];
                S[(r0 + 8) * 4 + wn] = ssB[mt];
            }
        }
        __syncthreads();
        const int pi = wn & ~1;
#pragma unroll
        for (int mt = 0; mt < 4; mt++) {
            int r0 = wm * 64 + mt * 16 + g;
            float sc0 = rsqrtf((S[r0 * 4 + pi] + S[r0 * 4 + pi + 1]) * (1.0f / 64.0f) + 1e-6f) * qsc;
            float sc1 = rsqrtf((S[(r0 + 8) * 4 + pi] + S[(r0 + 8) * 4 + pi + 1]) * (1.0f / 64.0f) + 1e-6f) * qsc;
#pragma unroll
            for (int nt = 0; nt < 4; nt++) {
                int cl = wn * 32 + nt * 8 + t * 2;
                float2 ww = *(const float2*)(normw + (cl & 63));
                float v0 = acc[mt][nt][0] + bb[nt].x;
                float v1 = acc[mt][nt][1] + bb[nt].y;
                float v2 = acc[mt][nt][2] + bb[nt].x;
                float v3 = acc[mt][nt][3] + bb[nt].y;
                uint2 o0 = {f2tf32(v0 * sc0 * ww.x), f2tf32(v1 * sc0 * ww.y)};
                uint2 o1 = {f2tf32(v2 * sc1 * ww.x), f2tf32(v3 * sc1 * ww.y)};
                *(uint2*)(Cu + (size_t)(bm + r0) * CD + bn + cl)     = o0;
                *(uint2*)(Cu + (size_t)(bm + r0 + 8) * CD + bn + cl) = o1;
            }
        }
    } else {
#pragma unroll
        for (int mt = 0; mt < 4; mt++) {
            int r0 = bm + wm * 64 + mt * 16 + g;
#pragma unroll
            for (int nt = 0; nt < 4; nt++) {
                int col = bn + wn * 32 + nt * 8 + t * 2;
                uint2 o0 = {f2tf32(acc[mt][nt][0] + bb[nt].x), f2tf32(acc[mt][nt][1] + bb[nt].y)};
                uint2 o1 = {f2tf32(acc[mt][nt][2] + bb[nt].x), f2tf32(acc[mt][nt][3] + bb[nt].y)};
                *(uint2*)(Cu + (size_t)r0 * CD + col)       = o0;
                *(uint2*)(Cu + (size_t)(r0 + 8) * CD + col) = o1;
            }
        }
    }
}

// ---------------------------------------------------------------------------
// async tf32 GEMM (modes 0/2), operands tf32 bits
// MODE 0: store tf32 bits; MODE 2: gate rows post-GEMM, store f32
// ---------------------------------------------------------------------------
template <int MODE>
__global__ __launch_bounds__(256, 2) void gemm_a(
    const uint32_t* __restrict__ A, const uint32_t* __restrict__ W,
    const float* __restrict__ bias, float* __restrict__ C)
{
    extern __shared__ uint32_t sm[];
    const int tid  = threadIdx.x;
    const int lane = tid & 31;
    const int warp = tid >> 5;
    const int wm   = warp >> 2;
    const int wn   = warp & 3;
    const int bm   = blockIdx.y * 128;
    const int bn   = blockIdx.x * 128;
    const int g    = lane >> 2;
    const int t    = lane & 3;
    const uint32_t sb = (uint32_t)__cvta_generic_to_shared(sm);

    float acc[4][4][4];
#pragma unroll
    for (int i = 0; i < 4; i++)
#pragma unroll
        for (int j = 0; j < 4; j++)
#pragma unroll
            for (int r = 0; r < 4; r++) acc[i][j][r] = 0.0f;

    auto load_stage = [&](int kt, int st) {
        uint32_t as = sb + (uint32_t)(st * GA_STAGE) * 4u;
        uint32_t bs = as + GA_AW * 4u;
#pragma unroll
        for (int p = 0; p < 4; p++) {
            int idx = p * 256 + tid;
            int r = idx >> 3, c4 = (idx & 7) << 2;
            cp16(as + (uint32_t)(r * APAD + c4) * 4u,
                 A + (size_t)(bm + r) * CD + kt + c4);
        }
#pragma unroll
        for (int p = 0; p < 4; p++) {
            int idx = p * 256 + tid;
            int kk = idx >> 5, c4 = (idx & 31) << 2;
            cp16(bs + (uint32_t)(kk * BPAD + c4) * 4u,
                 W + (size_t)(kt + kk) * CD + bn + c4);
        }
        CP_COMMIT();
    };

    load_stage(0, 0);
    int st = 0;
    for (int it = 0; it < 32; it++) {
        CP_WAIT0();
        __syncthreads();
        if (it < 31) load_stage((it + 1) * 32, st ^ 1);
        const uint32_t* As = sm + st * GA_STAGE;
        const uint32_t* Bs = As + GA_AW;
#pragma unroll
        for (int ks = 0; ks < 4; ks++) {
            const int kc = ks * 8;
            uint32_t af[4][4], bf[4][2];
#pragma unroll
            for (int mt = 0; mt < 4; mt++) {
                int row = wm * 64 + mt * 16 + g;
                af[mt][0] = As[row * APAD + kc + t];
                af[mt][1] = As[(row + 8) * APAD + kc + t];
                af[mt][2] = As[row * APAD + kc + t + 4];
                af[mt][3] = As[(row + 8) * APAD + kc + t + 4];
            }
#pragma unroll
            for (int nt = 0; nt < 4; nt++) {
                int col = wn * 32 + nt * 8 + g;
                bf[nt][0] = Bs[(kc + t) * BPAD + col];
                bf[nt][1] = Bs[(kc + t + 4) * BPAD + col];
            }
#pragma unroll
            for (int mt = 0; mt < 4; mt++)
#pragma unroll
                for (int nt = 0; nt < 4; nt++)
                    mma_tf32(acc[mt][nt], af[mt], bf[nt]);
        }
        st ^= 1;
    }

    float2 bb[4];
#pragma unroll
    for (int nt = 0; nt < 4; nt++)
        bb[nt] = *(const float2*)(bias + bn + wn * 32 + nt * 8 + t * 2);

    if (MODE == 2) {
#pragma unroll
        for (int mt = 0; mt < 4; mt++) {
            int r0 = bm + wm * 64 + mt * 16 + g;
            float ga0 = 1.0f + g_gacc[r0]     * (1.0f / 512.0f);
            float ga1 = 1.0f + g_gacc[r0 + 8] * (1.0f / 512.0f);
#pragma unroll
            for (int nt = 0; nt < 4; nt++) {
                int col = bn + wn * 32 + nt * 8 + t * 2;
                float2 w0 = {acc[mt][nt][0] * ga0 + bb[nt].x, acc[mt][nt][1] * ga0 + bb[nt].y};
                float2 w1 = {acc[mt][nt][2] * ga1 + bb[nt].x, acc[mt][nt][3] * ga1 + bb[nt].y};
                *(float2*)(C + (size_t)r0 * CD + col)       = w0;
                *(float2*)(C + (size_t)(r0 + 8) * CD + col) = w1;
            }
        }
    } else {
        uint32_t* Cu = (uint32_t*)C;
#pragma unroll
        for (int mt = 0; mt < 4; mt++) {
            int r0 = bm + wm * 64 + mt * 16 + g;
#pragma unroll
            for (int nt = 0; nt < 4; nt++) {
                int col = bn + wn * 32 + nt * 8 + t * 2;
                uint2 o0 = {f2tf32(acc[mt][nt][0] + bb[nt].x), f2tf32(acc[mt][nt][1] + bb[nt].y)};
                uint2 o1 = {f2tf32(acc[mt][nt][2] + bb[nt].x), f2tf32(acc[mt][nt][3] + bb[nt].y)};
                *(uint2*)(Cu + (size_t)r0 * CD + col)       = o0;
                *(uint2*)(Cu + (size_t)(r0 + 8) * CD + col) = o1;
            }
        }
    }
}

// ---------------------------------------------------------------------------
// instance gate: cp.async double-buffered, inputs tf32 bits
// ---------------------------------------------------------------------------
__global__ __launch_bounds__(256, 2) void instgate_t(
    const uint32_t* __restrict__ iq, const uint32_t* __restrict__ ikp)
{
    extern __shared__ uint32_t sm[];
    const int tid  = threadIdx.x;
    const int lane = tid & 31;
    const int warp = tid >> 5;
    const int wm   = warp >> 2;
    const int wn   = warp & 3;
    const int b    = blockIdx.z;
    const int bm   = blockIdx.y * 128;
    const int bn   = blockIdx.x * 128;
    const int g    = lane >> 2;
    const int t    = lane & 3;
    const uint32_t* Ab = iq  + (size_t)b * 512 * CD;
    const uint32_t* Bb = ikp + (size_t)b * 512 * CD;
    const uint32_t sb = (uint32_t)__cvta_generic_to_shared(sm);

    float acc[4][4][4];
#pragma unroll
    for (int i = 0; i < 4; i++)
#pragma unroll
        for (int j = 0; j < 4; j++)
#pragma unroll
            for (int r = 0; r < 4; r++) acc[i][j][r] = 0.0f;

    auto load_stage = [&](int kt, int st) {
        uint32_t as = sb + (uint32_t)(st * IG_STAGE) * 4u;
        uint32_t bs = as + (uint32_t)(128 * APAD) * 4u;
#pragma unroll
        for (int p = 0; p < 4; p++) {
            int idx = p * 256 + tid;
            int r = idx >> 3, c4 = (idx & 7) << 2;
            cp16(as + (uint32_t)(r * APAD + c4) * 4u, Ab + (size_t)(bm + r) * CD + kt + c4);
            cp16(bs + (uint32_t)(r * APAD + c4) * 4u, Bb + (size_t)(bn + r) * CD + kt + c4);
        }
        CP_COMMIT();
    };

    load_stage(0, 0);
    int st = 0;
    for (int it = 0; it < 32; it++) {
        CP_WAIT0();
        __syncthreads();
        if (it < 31) load_stage((it + 1) * 32, st ^ 1);
        const uint32_t* As = sm + st * IG_STAGE;
        const uint32_t* Bs = As + 128 * APAD;
#pragma unroll
        for (int ks = 0; ks < 4; ks++) {
            const int kc = ks * 8;
            uint32_t af[4][4], bf[4][2];
#pragma unroll
            for (int mt = 0; mt < 4; mt++) {
                int row = wm * 64 + mt * 16 + g;
                af[mt][0] = As[row * APAD + kc + t];
                af[mt][1] = As[(row + 8) * APAD + kc + t];
                af[mt][2] = As[row * APAD + kc + t + 4];
                af[mt][3] = As[(row + 8) * APAD + kc + t + 4];
            }
#pragma unroll
            for (int nt = 0; nt < 4; nt++) {
                int col = wn * 32 + nt * 8 + g;
                bf[nt][0] = Bs[col * APAD + kc + t];
                bf[nt][1] = Bs[col * APAD + kc + t + 4];
            }
#pragma unroll
            for (int mt = 0; mt < 4; mt++)
#pragma unroll
                for (int nt = 0; nt < 4; nt++)
                    mma_tf32(acc[mt][nt], af[mt], bf[nt]);
        }
        st ^= 1;
    }

#pragma unroll
    for (int mt = 0; mt < 4; mt++) {
        float s0 = 0.0f, s1 = 0.0f;
#pragma unroll
        for (int nt = 0; nt < 4; nt++) {
            s0 += 1.0f / (1.0f + __expf(-acc[mt][nt][0] * INST_SCALE));
            s0 += 1.0f / (1.0f + __expf(-acc[mt][nt][1] * INST_SCALE));
            s1 += 1.0f / (1.0f + __expf(-acc[mt][nt][2] * INST_SCALE));
            s1 += 1.0f / (1.0f + __expf(-acc[mt][nt][3] * INST_SCALE));
        }
        s0 += __shfl_xor_sync(0xffffffffu, s0, 1);
        s0 += __shfl_xor_sync(0xffffffffu, s0, 2);
        s1 += __shfl_xor_sync(0xffffffffu, s1, 1);
        s1 += __shfl_xor_sync(0xffffffffu, s1, 2);
        if (t == 0) {
            int row = bm + wm * 64 + mt * 16 + g;
            atomicAdd(&g_gacc[b * 512 + row], s0);
            atomicAdd(&g_gacc[b * 512 + row + 8], s1);
        }
    }
}

// ---------------------------------------------------------------------------
// tf32 flash attention, FIXED-BOUND softmax.
// |q_row|<8, |k_row|<8 (RMSNorm w=1), Q pre-scaled by 0.125 => |s|<8.
// p = exp(s - 8): no online max, no rescale. Quad li-reduction once at end.
// ---------------------------------------------------------------------------
__global__ __launch_bounds__(256, 2) void attn_t(
    const uint32_t* __restrict__ q, const uint32_t* __restrict__ k,
    const uint32_t* __restrict__ v, float* __restrict__ o)
{
    extern __shared__ uint32_t sm[];
    uint32_t* Ps = sm + 2 * AT_STAGE;

    const int tid  = threadIdx.x;
    const int lane = tid & 31;
    const int warp = tid >> 5;
    const int g    = lane >> 2;
    const int t    = lane & 3;
    const int bq   = blockIdx.y;
    const int h    = blockIdx.z;
    const int n0   = blockIdx.x * 128;
    const int gb   = bq & ~3;
    const int qrow = n0 + warp * 16;
    const uint32_t sb = (uint32_t)__cvta_generic_to_shared(sm);

    // Q fragments: raw bit loads (already tf32, already scaled)
    uint32_t qf[8][4];
    {
        const uint32_t* qb = q + ((size_t)(bq * CN + qrow)) * CD + h * CHD;
#pragma unroll
        for (int ks = 0; ks < 8; ks++) {
            int c = ks * 8 + t;
            qf[ks][0] = qb[(size_t)g * CD + c];
            qf[ks][1] = qb[(size_t)(g + 8) * CD + c];
            qf[ks][2] = qb[(size_t)g * CD + c + 4];
            qf[ks][3] = qb[(size_t)(g + 8) * CD + c + 4];
        }
    }

    float oa[8][4];
#pragma unroll
    for (int nt = 0; nt < 8; nt++)
#pragma unroll
        for (int r = 0; r < 4; r++) oa[nt][r] = 0.0f;
    float li0 = 0.0f, li1 = 0.0f;

    uint32_t* Pw = Ps + warp * 16 * PPAD;
    const int sw0 = (g & 4) ? 4 : 0;

    auto load_kv = [&](int kc, int stg) {
        const int m0 = kc * 64;
        const int kb = gb + (m0 >> 9);
        const int kn = m0 & 511;
        uint32_t ksm = sb + (uint32_t)(stg * AT_STAGE) * 4u;
        uint32_t vsm = ksm + AT_KV * 4u;
#pragma unroll
        for (int p = 0; p < 4; p++) {
            int idx = p * 256 + tid;
            int r   = idx >> 4;
            int c4  = (idx & 15) << 2;
            size_t base = ((size_t)(kb * CN + kn + r)) * CD + h * CHD + c4;
            uint32_t off = (uint32_t)(r * KPAD + c4) * 4u;
            cp16(ksm + off, k + base);
            cp16(vsm + off, v + base);
        }
        CP_COMMIT();
    };

    load_kv(0, 0);
    int st = 0;

    for (int kc = 0; kc < 32; kc++) {
        CP_WAIT0();
        __syncthreads();
        if (kc < 31) load_kv(kc + 1, st ^ 1);

        const uint32_t* Ks = sm + st * AT_STAGE;
        const uint32_t* Vs = Ks + AT_KV;

        // S = Q @ K^T
        float sacc[8][4];
#pragma unroll
        for (int nt = 0; nt < 8; nt++)
#pragma unroll
            for (int r = 0; r < 4; r++) sacc[nt][r] = 0.0f;
#pragma unroll
        for (int ks = 0; ks < 8; ks++) {
            const int kcd = ks * 8;
#pragma unroll
            for (int nt = 0; nt < 8; nt++) {
                uint32_t bf[2];
                bf[0] = Ks[(nt * 8 + g) * KPAD + kcd + t];
                bf[1] = Ks[(nt * 8 + g) * KPAD + kcd + t + 4];
                mma_tf32(sacc[nt], qf[ks], bf);
            }
        }

        // fixed-shift softmax: p = exp(s - 8), accumulate li locally
#pragma unroll
        for (int nt = 0; nt < 8; nt++) {
            float p0 = __expf(sacc[nt][0] - SOFT_SHIFT);
            float p1 = __expf(sacc[nt][1] - SOFT_SHIFT);
            float p2 = __expf(sacc[nt][2] - SOFT_SHIFT);
            float p3 = __expf(sacc[nt][3] - SOFT_SHIFT);
            li0 += p0 + p1;
            li1 += p2 + p3;
            int col = (nt * 8 + 2 * t) ^ sw0;
            uint32_t* p_lo = &Pw[g * PPAD + col];
            uint32_t* p_hi = &Pw[(g + 8) * PPAD + col];
            p_lo[0] = f2tf32(p0); p_lo[1] = f2tf32(p1);
            p_hi[0] = f2tf32(p2); p_hi[1] = f2tf32(p3);
        }
        __syncwarp();

        // O += P @ V  (no rescale needed)
#pragma unroll
        for (int ks = 0; ks < 8; ks++) {
            const int kcd = ks * 8;
            uint32_t af[4];
            af[0] = Pw[g * PPAD + ((kcd + t) ^ sw0)];
            af[1] = Pw[(g + 8) * PPAD + ((kcd + t) ^ sw0)];
            af[2] = Pw[g * PPAD + ((kcd + t + 4) ^ sw0)];
            af[3] = Pw[(g + 8) * PPAD + ((kcd + t + 4) ^ sw0)];
#pragma unroll
            for (int nt = 0; nt < 8; nt++) {
                uint32_t bf[2];
                bf[0] = Vs[(kcd + t) * KPAD + nt * 8 + g];
                bf[1] = Vs[(kcd + t + 4) * KPAD + nt * 8 + g];
                mma_tf32(oa[nt], af, bf);
            }
        }
        __syncwarp();
        st ^= 1;
    }

    // final quad reduction of li, normalize, store tf32 bits
    li0 += __shfl_xor_sync(0xffffffffu, li0, 1);
    li0 += __shfl_xor_sync(0xffffffffu, li0, 2);
    li1 += __shfl_xor_sync(0xffffffffu, li1, 1);
    li1 += __shfl_xor_sync(0xffffffffu, li1, 2);
    float inv0 = 1.0f / li0, inv1 = 1.0f / li1;
    uint32_t* ob = (uint32_t*)(o + ((size_t)(bq * CN + qrow)) * CD + h * CHD);
#pragma unroll
    for (int nt = 0; nt < 8; nt++) {
        int col = nt * 8 + 2 * t;
        uint2 r0 = {f2tf32(oa[nt][0] * inv0), f2tf32(oa[nt][1] * inv0)};
        uint2 r1 = {f2tf32(oa[nt][2] * inv1), f2tf32(oa[nt][3] * inv1)};
        *(uint2*)(ob + (size_t)g * CD + col)       = r0;
        *(uint2*)(ob + (size_t)(g + 8) * CD + col) = r1;
    }
}

// ---------------------------------------------------------------------------
// E2 = emb[:4] @ Wik (tiny); ik = mask @ E2 + bik (tf32 bits out)
// ---------------------------------------------------------------------------
__global__ void e2_k(const float* __restrict__ emb, const float* __restrict__ Wik) {
    int n = blockIdx.x * 256 + threadIdx.x;
    int i = n >> 10;
    int c = n & 1023;
    const float* ep = emb + i * 1024;
    float acc = 0.0f;
#pragma unroll 4
    for (int kk = 0; kk < 1024; kk++)
        acc = fmaf(ep[kk], Wik[(size_t)kk * 1024 + c], acc);
    g_e2[n] = acc;
}

__global__ void ikb_k(const float* __restrict__ mask, const float* __restrict__ bik,
                      uint32_t* __restrict__ ik) {
    int idx = blockIdx.x * 256 + threadIdx.x;
    int d  = idx & 1023;
    int bn = idx >> 10;
    const float* mp = mask + (size_t)bn * 4;
    float acc = bik[d];
    acc = fmaf(mp[0], g_e2[d],        acc);
    acc = fmaf(mp[1], g_e2[1024 + d], acc);
    acc = fmaf(mp[2], g_e2[2048 + d], acc);
    acc = fmaf(mp[3], g_e2[3072 + d], acc);
    ik[idx] = f2tf32(acc);
}

// ---------------------------------------------------------------------------
// launch
// ---------------------------------------------------------------------------
extern "C" void kernel_launch(void* const* d_in, const int* in_sizes, int n_in,
                              void* d_out, int out_size)
{
    (void)in_sizes; (void)n_in; (void)out_size;
    const float* x    = (const float*)d_in[0];
    const float* mask = (const float*)d_in[1];
    const float* Wq   = (const float*)d_in[2];
    const float* bq   = (const float*)d_in[3];
    const float* Wk   = (const float*)d_in[4];
    const float* bk   = (const float*)d_in[5];
    const float* Wv   = (const float*)d_in[6];
    const float* bv   = (const float*)d_in[7];
    const float* Wo   = (const float*)d_in[8];
    const float* bo   = (const float*)d_in[9];
    const float* Wiq  = (const float*)d_in[10];
    const float* biq  = (const float*)d_in[11];
    const float* Wik  = (const float*)d_in[12];
    const float* bik  = (const float*)d_in[13];
    const float* emb  = (const float*)d_in[14];
    const float* qw   = (const float*)d_in[15];
    const float* kw   = (const float*)d_in[16];
    float* out = (float*)d_out;

    float *qp, *kp, *vp, *op, *iqp;
    uint32_t *xt, *wq, *wk, *wv, *wiq, *wo, *ikp;
    cudaGetSymbolAddress((void**)&qp,  g_q);
    cudaGetSymbolAddress((void**)&kp,  g_k);
    cudaGetSymbolAddress((void**)&vp,  g_v);
    cudaGetSymbolAddress((void**)&op,  g_o);
    cudaGetSymbolAddress((void**)&iqp, g_iq);
    cudaGetSymbolAddress((void**)&ikp, g_ik);
    cudaGetSymbolAddress((void**)&xt,  g_xt);
    cudaGetSymbolAddress((void**)&wq,  g_wq);
    cudaGetSymbolAddress((void**)&wk,  g_wk);
    cudaGetSymbolAddress((void**)&wv,  g_wv);
    cudaGetSymbolAddress((void**)&wiq, g_wiq);
    cudaGetSymbolAddress((void**)&wo,  g_wo);

    static bool attr_done = false;
    if (!attr_done) {
        cudaFuncSetAttribute(gemm_qkv, cudaFuncAttributeMaxDynamicSharedMemorySize, SMEM_GEMM);
        cudaFuncSetAttribute(gemm_a<0>, cudaFuncAttributeMaxDynamicSharedMemorySize, SMEM_GEMM);
        cudaFuncSetAttribute(gemm_a<2>, cudaFuncAttributeMaxDynamicSharedMemorySize, SMEM_GEMM);
        cudaFuncSetAttribute(instgate_t, cudaFuncAttributeMaxDynamicSharedMemorySize, SMEM_IG);
        cudaFuncSetAttribute(attn_t, cudaFuncAttributeMaxDynamicSharedMemorySize, SMEM_ATTN);
        attr_done = true;
    }

    dim3 gemm_grid(8, 32);

    zero_gacc_k<<<16, 256>>>();

    // x:1048576 + 5 weights * 262144 = 2359296 float4s -> 9216 blocks
    cvt_all_k<<<9216, 256>>>(x, Wq, Wk, Wv, Wiq, Wo, xt, wq, wk, wv, wiq, wo);

    gemm_qkv<<<dim3(8, 32, 3), 256, SMEM_GEMM>>>(xt, wq, wk, wv, bq, bk, bv,
                                                 qw, kw, qp, kp, vp);

    attn_t<<<dim3(4, 8, 16), 256, SMEM_ATTN>>>((const uint32_t*)qp, (const uint32_t*)kp,
                                               (const uint32_t*)vp, op);

    e2_k<<<16, 256>>>(emb, Wik);
    ikb_k<<<16384, 256>>>(mask, bik, ikp);

    gemm_a<0><<<gemm_grid, 256, SMEM_GEMM>>>((const uint32_t*)op, wiq, biq, iqp);

    instgate_t<<<dim3(4, 4, 8), 256, SMEM_IG>>>((const uint32_t*)iqp, ikp);

    gemm_a<2><<<gemm_grid, 256, SMEM_GEMM>>>((const uint32_t*)op, wo, bo, out);
}

// round 8
// speedup vs baseline: 3.0347x; 1.1081x over previous
#include <cuda_runtime.h>
#include <cstdint>
#include <cstddef>

// ---------------------------------------------------------------------------
// MIDIMultiInstanceAttention  (B=8, N=512, D=1024, H=16, HD=64, NI=4)
// tf32 tensor-core everything; fixed-bound softmax; ldmatrix attention
// ---------------------------------------------------------------------------

#define CB 8
#define CN 512
#define CD 1024
#define CH 16
#define CHD 64
#define CM 4096
#define ATT_SCALE 0.125f
#define SOFT_SHIFT 8.0f
#define INST_SCALE (0.125f / 16.0f)

#define APAD 36
#define BPAD 136
#define KPAD 68
#define PPAD 68

#define GA_AW (128 * APAD)
#define GA_BW (32 * BPAD)
#define GA_STAGE (GA_AW + GA_BW)
#define SMEM_GEMM (2 * GA_STAGE * 4)               // 71680 B

#define IG_STAGE (2 * 128 * APAD)                  // A+B, words
#define SMEM_IG (2 * IG_STAGE * 4)                 // 73728 B

#define AT_KV (64 * KPAD)                          // 4352 words
#define AT_STAGE (2 * AT_KV)                       // 8704 words (K+Vt)
#define SMEM_ATTN ((2 * AT_STAGE + 8 * 16 * PPAD) * 4)   // 104448 B

// scratch (device globals: allocation-free rule)
__device__ __align__(16) uint32_t g_xt[CM * CD];
__device__ __align__(16) uint32_t g_wq[CD * CD];
__device__ __align__(16) uint32_t g_wk[CD * CD];
__device__ __align__(16) uint32_t g_wv[CD * CD];
__device__ __align__(16) uint32_t g_wiq[CD * CD];
__device__ __align__(16) uint32_t g_wo[CD * CD];
__device__ __align__(16) float g_q [CM * CD];      // tf32 bits (pre-scaled)
__device__ __align__(16) float g_k [CM * CD];      // tf32 bits
__device__ __align__(16) float g_vt[CM * CD];      // tf32 bits, TRANSPOSED [b,h][d][n]
__device__ __align__(16) float g_o [CM * CD];      // tf32 bits
__device__ __align__(16) float g_iq[CM * CD];      // tf32 bits
__device__ __align__(16) uint32_t g_ik[CM * CD];   // tf32 bits
__device__ __align__(16) float g_e2[4 * CD];
__device__ float g_gacc[CM];

__global__ void zero_gacc_k() {
    int i = blockIdx.x * 256 + threadIdx.x;
    if (i < CM) g_gacc[i] = 0.0f;
}

// ---------------------------------------------------------------------------
// helpers
// ---------------------------------------------------------------------------
__device__ __forceinline__ uint32_t f2tf32(float x) {
    uint32_t r;
    asm("cvt.rna.tf32.f32 %0, %1;" : "=r"(r) : "f"(x));
    return r;
}

__device__ __forceinline__ void mma_tf32(float* d, const uint32_t* a, const uint32_t* b) {
    asm volatile(
        "mma.sync.aligned.m16n8k8.row.col.f32.tf32.tf32.f32 "
        "{%0,%1,%2,%3}, {%4,%5,%6,%7}, {%8,%9}, {%0,%1,%2,%3};\n"
        : "+f"(d[0]), "+f"(d[1]), "+f"(d[2]), "+f"(d[3])
        : "r"(a[0]), "r"(a[1]), "r"(a[2]), "r"(a[3]), "r"(b[0]), "r"(b[1]));
}

__device__ __forceinline__ void ldsm_x4(uint32_t* r, uint32_t saddr) {
    asm volatile("ldmatrix.sync.aligned.m8n8.x4.shared.b16 {%0,%1,%2,%3}, [%4];\n"
        : "=r"(r[0]), "=r"(r[1]), "=r"(r[2]), "=r"(r[3]) : "r"(saddr));
}

__device__ __forceinline__ void cp16(uint32_t dst, const void* src) {
    asm volatile("cp.async.cg.shared.global [%0], [%1], 16;\n" :: "r"(dst), "l"(src));
}
#define CP_COMMIT() asm volatile("cp.async.commit_group;\n")
#define CP_WAIT0()  asm volatile("cp.async.wait_group 0;\n")

// one launch converts x + 5 weight matrices to tf32 bits
__global__ void cvt_all_k(const float* __restrict__ x,
                          const float* __restrict__ w0, const float* __restrict__ w1,
                          const float* __restrict__ w2, const float* __restrict__ w3,
                          const float* __restrict__ w4,
                          uint32_t* __restrict__ xt,
                          uint32_t* __restrict__ o0, uint32_t* __restrict__ o1,
                          uint32_t* __restrict__ o2, uint32_t* __restrict__ o3,
                          uint32_t* __restrict__ o4)
{
    const int WQ4 = CD * CD / 4;        // 262144
    const int XQ4 = CM * CD / 4;        // 1048576
    int i = blockIdx.x * 256 + threadIdx.x;
    const float* src; uint32_t* dst; int off;
    if (i < XQ4)                { src = x;  dst = xt; off = i; }
    else if (i < XQ4 + WQ4)     { src = w0; dst = o0; off = i - XQ4; }
    else if (i < XQ4 + 2 * WQ4) { src = w1; dst = o1; off = i - XQ4 - WQ4; }
    else if (i < XQ4 + 3 * WQ4) { src = w2; dst = o2; off = i - XQ4 - 2 * WQ4; }
    else if (i < XQ4 + 4 * WQ4) { src = w3; dst = o3; off = i - XQ4 - 3 * WQ4; }
    else                        { src = w4; dst = o4; off = i - XQ4 - 4 * WQ4; }
    float4 v = ((const float4*)src)[off];
    uint4 o = {f2tf32(v.x), f2tf32(v.y), f2tf32(v.z), f2tf32(v.w)};
    ((uint4*)dst)[off] = o;
}

// ---------------------------------------------------------------------------
// fused QKV projection: z selects {Wq,Wk,Wv}. z<2 -> fused per-head RMSNorm
// (Q additionally pre-scaled by ATT_SCALE). z==2 -> store V TRANSPOSED.
// ---------------------------------------------------------------------------
__global__ __launch_bounds__(256, 2) void gemm_qkv(
    const uint32_t* __restrict__ A,
    const uint32_t* __restrict__ Wq_, const uint32_t* __restrict__ Wk_,
    const uint32_t* __restrict__ Wv_,
    const float* __restrict__ bq_, const float* __restrict__ bk_,
    const float* __restrict__ bv_,
    const float* __restrict__ qw_, const float* __restrict__ kw_,
    float* __restrict__ oq_, float* __restrict__ ok_, float* __restrict__ ov_)
{
    extern __shared__ uint32_t sm[];
    const int z = blockIdx.z;
    const uint32_t* W   = (z == 0) ? Wq_ : (z == 1) ? Wk_ : Wv_;
    const float* bias   = (z == 0) ? bq_ : (z == 1) ? bk_ : bv_;
    const float* normw  = (z == 0) ? qw_ : kw_;
    float* C            = (z == 0) ? oq_ : (z == 1) ? ok_ : ov_;
    const float qsc     = (z == 0) ? ATT_SCALE : 1.0f;

    const int tid  = threadIdx.x;
    const int lane = tid & 31;
    const int warp = tid >> 5;
    const int wm   = warp >> 2;
    const int wn   = warp & 3;
    const int bm   = blockIdx.y * 128;
    const int bn   = blockIdx.x * 128;
    const int g    = lane >> 2;
    const int t    = lane & 3;
    const uint32_t sb = (uint32_t)__cvta_generic_to_shared(sm);

    float acc[4][4][4];
#pragma unroll
    for (int i = 0; i < 4; i++)
#pragma unroll
        for (int j = 0; j < 4; j++)
#pragma unroll
            for (int r = 0; r < 4; r++) acc[i][j][r] = 0.0f;

    auto load_stage = [&](int kt, int st) {
        uint32_t as = sb + (uint32_t)(st * GA_STAGE) * 4u;
        uint32_t bs = as + GA_AW * 4u;
#pragma unroll
        for (int p = 0; p < 4; p++) {
            int idx = p * 256 + tid;
            int r = idx >> 3, c4 = (idx & 7) << 2;
            cp16(as + (uint32_t)(r * APAD + c4) * 4u,
                 A + (size_t)(bm + r) * CD + kt + c4);
        }
#pragma unroll
        for (int p = 0; p < 4; p++) {
            int idx = p * 256 + tid;
            int kk = idx >> 5, c4 = (idx & 31) << 2;
            cp16(bs + (uint32_t)(kk * BPAD + c4) * 4u,
                 W + (size_t)(kt + kk) * CD + bn + c4);
        }
        CP_COMMIT();
    };

    load_stage(0, 0);
    int st = 0;
    for (int it = 0; it < 32; it++) {
        CP_WAIT0();
        __syncthreads();
        if (it < 31) load_stage((it + 1) * 32, st ^ 1);
        const uint32_t* As = sm + st * GA_STAGE;
        const uint32_t* Bs = As + GA_AW;
#pragma unroll
        for (int ks = 0; ks < 4; ks++) {
            const int kc = ks * 8;
            uint32_t af[4][4], bf[4][2];
#pragma unroll
            for (int mt = 0; mt < 4; mt++) {
                int row = wm * 64 + mt * 16 + g;
                af[mt][0] = As[row * APAD + kc + t];
                af[mt][1] = As[(row + 8) * APAD + kc + t];
                af[mt][2] = As[row * APAD + kc + t + 4];
                af[mt][3] = As[(row + 8) * APAD + kc + t + 4];
            }
#pragma unroll
            for (int nt = 0; nt < 4; nt++) {
                int col = wn * 32 + nt * 8 + g;
                bf[nt][0] = Bs[(kc + t) * BPAD + col];
                bf[nt][1] = Bs[(kc + t + 4) * BPAD + col];
            }
#pragma unroll
            for (int mt = 0; mt < 4; mt++)
#pragma unroll
                for (int nt = 0; nt < 4; nt++)
                    mma_tf32(acc[mt][nt], af[mt], bf[nt]);
        }
        st ^= 1;
    }
    __syncthreads();

    float2 bb[4];
#pragma unroll
    for (int nt = 0; nt < 4; nt++)
        bb[nt] = *(const float2*)(bias + bn + wn * 32 + nt * 8 + t * 2);

    uint32_t* Cu = (uint32_t*)C;
    if (z < 2) {
        // fused per-head RMSNorm (+ATT_SCALE for Q)
        float ssA[4], ssB[4];
#pragma unroll
        for (int mt = 0; mt < 4; mt++) {
            float s0 = 0.0f, s1 = 0.0f;
#pragma unroll
            for (int nt = 0; nt < 4; nt++) {
                float v0 = acc[mt][nt][0] + bb[nt].x;
                float v1 = acc[mt][nt][1] + bb[nt].y;
                float v2 = acc[mt][nt][2] + bb[nt].x;
                float v3 = acc[mt][nt][3] + bb[nt].y;
                s0 = fmaf(v0, v0, s0); s0 = fmaf(v1, v1, s0);
                s1 = fmaf(v2, v2, s1); s1 = fmaf(v3, v3, s1);
            }
            s0 += __shfl_xor_sync(0xffffffffu, s0, 1);
            s0 += __shfl_xor_sync(0xffffffffu, s0, 2);
            s1 += __shfl_xor_sync(0xffffffffu, s1, 1);
            s1 += __shfl_xor_sync(0xffffffffu, s1, 2);
            ssA[mt] = s0; ssB[mt] = s1;
        }
        float* S = (float*)sm;
        if (t == 0) {
#pragma unroll
            for (int mt = 0; mt < 4; mt++) {
                int r0 = wm * 64 + mt * 16 + g;
                S[r0 * 4 + wn]       = ssA[mt];
                S[(r0 + 8) * 4 + wn] = ssB[mt];
            }
        }
        __syncthreads();
        const int pi = wn & ~1;
#pragma unroll
        for (int mt = 0; mt < 4; mt++) {
            int r0 = wm * 64 + mt * 16 + g;
            float sc0 = rsqrtf((S[r0 * 4 + pi] + S[r0 * 4 + pi + 1]) * (1.0f / 64.0f) + 1e-6f) * qsc;
            float sc1 = rsqrtf((S[(r0 + 8) * 4 + pi] + S[(r0 + 8) * 4 + pi + 1]) * (1.0f / 64.0f) + 1e-6f) * qsc;
#pragma unroll
            for (int nt = 0; nt < 4; nt++) {
                int cl = wn * 32 + nt * 8 + t * 2;
                float2 ww = *(const float2*)(normw + (cl & 63));
                float v0 = acc[mt][nt][0] + bb[nt].x;
                float v1 = acc[mt][nt][1] + bb[nt].y;
                float v2 = acc[mt][nt][2] + bb[nt].x;
                float v3 = acc[mt][nt][3] + bb[nt].y;
                uint2 o0 = {f2tf32(v0 * sc0 * ww.x), f2tf32(v1 * sc0 * ww.y)};
                uint2 o1 = {f2tf32(v2 * sc1 * ww.x), f2tf32(v3 * sc1 * ww.y)};
                *(uint2*)(Cu + (size_t)(bm + r0) * CD + bn + cl)     = o0;
                *(uint2*)(Cu + (size_t)(bm + r0 + 8) * CD + bn + cl) = o1;
            }
        }
    } else {
        // V: store TRANSPOSED tf32 bits: vt[((b*16+h)*64+hd)*512 + n]
#pragma unroll
        for (int mt = 0; mt < 4; mt++) {
            int m0 = bm + wm * 64 + mt * 16 + g;    // token (and +8 in same batch)
#pragma unroll
            for (int nt = 0; nt < 4; nt++) {
                int d0 = bn + wn * 32 + nt * 8 + t * 2;   // even; d0,d0+1 same head
                float v00 = acc[mt][nt][0] + bb[nt].x;
                float v01 = acc[mt][nt][1] + bb[nt].y;
                float v10 = acc[mt][nt][2] + bb[nt].x;
                float v11 = acc[mt][nt][3] + bb[nt].y;
                size_t ib = ((size_t)((m0 >> 9) * CH + (d0 >> 6)) * CHD + (d0 & 63)) * CN
                          + (m0 & 511);
                Cu[ib]            = f2tf32(v00);
                Cu[ib + CN]       = f2tf32(v01);
                Cu[ib + 8]        = f2tf32(v10);
                Cu[ib + CN + 8]   = f2tf32(v11);
            }
        }
    }
}

// ---------------------------------------------------------------------------
// async tf32 GEMM (modes 0/2), operands tf32 bits
// MODE 0: store tf32 bits; MODE 2: gate rows post-GEMM, store f32
// ---------------------------------------------------------------------------
template <int MODE>
__global__ __launch_bounds__(256, 2) void gemm_a(
    const uint32_t* __restrict__ A, const uint32_t* __restrict__ W,
    const float* __restrict__ bias, float* __restrict__ C)
{
    extern __shared__ uint32_t sm[];
    const int tid  = threadIdx.x;
    const int lane = tid & 31;
    const int warp = tid >> 5;
    const int wm   = warp >> 2;
    const int wn   = warp & 3;
    const int bm   = blockIdx.y * 128;
    const int bn   = blockIdx.x * 128;
    const int g    = lane >> 2;
    const int t    = lane & 3;
    const uint32_t sb = (uint32_t)__cvta_generic_to_shared(sm);

    float acc[4][4][4];
#pragma unroll
    for (int i = 0; i < 4; i++)
#pragma unroll
        for (int j = 0; j < 4; j++)
#pragma unroll
            for (int r = 0; r < 4; r++) acc[i][j][r] = 0.0f;

    auto load_stage = [&](int kt, int st) {
        uint32_t as = sb + (uint32_t)(st * GA_STAGE) * 4u;
        uint32_t bs = as + GA_AW * 4u;
#pragma unroll
        for (int p = 0; p < 4; p++) {
            int idx = p * 256 + tid;
            int r = idx >> 3, c4 = (idx & 7) << 2;
            cp16(as + (uint32_t)(r * APAD + c4) * 4u,
                 A + (size_t)(bm + r) * CD + kt + c4);
        }
#pragma unroll
        for (int p = 0; p < 4; p++) {
            int idx = p * 256 + tid;
            int kk = idx >> 5, c4 = (idx & 31) << 2;
            cp16(bs + (uint32_t)(kk * BPAD + c4) * 4u,
                 W + (size_t)(kt + kk) * CD + bn + c4);
        }
        CP_COMMIT();
    };

    load_stage(0, 0);
    int st = 0;
    for (int it = 0; it < 32; it++) {
        CP_WAIT0();
        __syncthreads();
        if (it < 31) load_stage((it + 1) * 32, st ^ 1);
        const uint32_t* As = sm + st * GA_STAGE;
        const uint32_t* Bs = As + GA_AW;
#pragma unroll
        for (int ks = 0; ks < 4; ks++) {
            const int kc = ks * 8;
            uint32_t af[4][4], bf[4][2];
#pragma unroll
            for (int mt = 0; mt < 4; mt++) {
                int row = wm * 64 + mt * 16 + g;
                af[mt][0] = As[row * APAD + kc + t];
                af[mt][1] = As[(row + 8) * APAD + kc + t];
                af[mt][2] = As[row * APAD + kc + t + 4];
                af[mt][3] = As[(row + 8) * APAD + kc + t + 4];
            }
#pragma unroll
            for (int nt = 0; nt < 4; nt++) {
                int col = wn * 32 + nt * 8 + g;
                bf[nt][0] = Bs[(kc + t) * BPAD + col];
                bf[nt][1] = Bs[(kc + t + 4) * BPAD + col];
            }
#pragma unroll
            for (int mt = 0; mt < 4; mt++)
#pragma unroll
                for (int nt = 0; nt < 4; nt++)
                    mma_tf32(acc[mt][nt], af[mt], bf[nt]);
        }
        st ^= 1;
    }

    float2 bb[4];
#pragma unroll
    for (int nt = 0; nt < 4; nt++)
        bb[nt] = *(const float2*)(bias + bn + wn * 32 + nt * 8 + t * 2);

    if (MODE == 2) {
#pragma unroll
        for (int mt = 0; mt < 4; mt++) {
            int r0 = bm + wm * 64 + mt * 16 + g;
            float ga0 = 1.0f + g_gacc[r0]     * (1.0f / 512.0f);
            float ga1 = 1.0f + g_gacc[r0 + 8] * (1.0f / 512.0f);
#pragma unroll
            for (int nt = 0; nt < 4; nt++) {
                int col = bn + wn * 32 + nt * 8 + t * 2;
                float2 w0 = {acc[mt][nt][0] * ga0 + bb[nt].x, acc[mt][nt][1] * ga0 + bb[nt].y};
                float2 w1 = {acc[mt][nt][2] * ga1 + bb[nt].x, acc[mt][nt][3] * ga1 + bb[nt].y};
                *(float2*)(C + (size_t)r0 * CD + col)       = w0;
                *(float2*)(C + (size_t)(r0 + 8) * CD + col) = w1;
            }
        }
    } else {
        uint32_t* Cu = (uint32_t*)C;
#pragma unroll
        for (int mt = 0; mt < 4; mt++) {
            int r0 = bm + wm * 64 + mt * 16 + g;
#pragma unroll
            for (int nt = 0; nt < 4; nt++) {
                int col = bn + wn * 32 + nt * 8 + t * 2;
                uint2 o0 = {f2tf32(acc[mt][nt][0] + bb[nt].x), f2tf32(acc[mt][nt][1] + bb[nt].y)};
                uint2 o1 = {f2tf32(acc[mt][nt][2] + bb[nt].x), f2tf32(acc[mt][nt][3] + bb[nt].y)};
                *(uint2*)(Cu + (size_t)r0 * CD + col)       = o0;
                *(uint2*)(Cu + (size_t)(r0 + 8) * CD + col) = o1;
            }
        }
    }
}

// ---------------------------------------------------------------------------
// instance gate: cp.async double-buffered, inputs tf32 bits
// ---------------------------------------------------------------------------
__global__ __launch_bounds__(256, 2) void instgate_t(
    const uint32_t* __restrict__ iq, const uint32_t* __restrict__ ikp)
{
    extern __shared__ uint32_t sm[];
    const int tid  = threadIdx.x;
    const int lane = tid & 31;
    const int warp = tid >> 5;
    const int wm   = warp >> 2;
    const int wn   = warp & 3;
    const int b    = blockIdx.z;
    const int bm   = blockIdx.y * 128;
    const int bn   = blockIdx.x * 128;
    const int g    = lane >> 2;
    const int t    = lane & 3;
    const uint32_t* Ab = iq  + (size_t)b * 512 * CD;
    const uint32_t* Bb = ikp + (size_t)b * 512 * CD;
    const uint32_t sb = (uint32_t)__cvta_generic_to_shared(sm);

    float acc[4][4][4];
#pragma unroll
    for (int i = 0; i < 4; i++)
#pragma unroll
        for (int j = 0; j < 4; j++)
#pragma unroll
            for (int r = 0; r < 4; r++) acc[i][j][r] = 0.0f;

    auto load_stage = [&](int kt, int st) {
        uint32_t as = sb + (uint32_t)(st * IG_STAGE) * 4u;
        uint32_t bs = as + (uint32_t)(128 * APAD) * 4u;
#pragma unroll
        for (int p = 0; p < 4; p++) {
            int idx = p * 256 + tid;
            int r = idx >> 3, c4 = (idx & 7) << 2;
            cp16(as + (uint32_t)(r * APAD + c4) * 4u, Ab + (size_t)(bm + r) * CD + kt + c4);
            cp16(bs + (uint32_t)(r * APAD + c4) * 4u, Bb + (size_t)(bn + r) * CD + kt + c4);
        }
        CP_COMMIT();
    };

    load_stage(0, 0);
    int st = 0;
    for (int it = 0; it < 32; it++) {
        CP_WAIT0();
        __syncthreads();
        if (it < 31) load_stage((it + 1) * 32, st ^ 1);
        const uint32_t* As = sm + st * IG_STAGE;
        const uint32_t* Bs = As + 128 * APAD;
#pragma unroll
        for (int ks = 0; ks < 4; ks++) {
            const int kc = ks * 8;
            uint32_t af[4][4], bf[4][2];
#pragma unroll
            for (int mt = 0; mt < 4; mt++) {
                int row = wm * 64 + mt * 16 + g;
                af[mt][0] = As[row * APAD + kc + t];
                af[mt][1] = As[(row + 8) * APAD + kc + t];
                af[mt][2] = As[row * APAD + kc + t + 4];
                af[mt][3] = As[(row + 8) * APAD + kc + t + 4];
            }
#pragma unroll
            for (int nt = 0; nt < 4; nt++) {
                int col = wn * 32 + nt * 8 + g;
                bf[nt][0] = Bs[col * APAD + kc + t];
                bf[nt][1] = Bs[col * APAD + kc + t + 4];
            }
#pragma unroll
            for (int mt = 0; mt < 4; mt++)
#pragma unroll
                for (int nt = 0; nt < 4; nt++)
                    mma_tf32(acc[mt][nt], af[mt], bf[nt]);
        }
        st ^= 1;
    }

#pragma unroll
    for (int mt = 0; mt < 4; mt++) {
        float s0 = 0.0f, s1 = 0.0f;
#pragma unroll
        for (int nt = 0; nt < 4; nt++) {
            s0 += 1.0f / (1.0f + __expf(-acc[mt][nt][0] * INST_SCALE));
            s0 += 1.0f / (1.0f + __expf(-acc[mt][nt][1] * INST_SCALE));
            s1 += 1.0f / (1.0f + __expf(-acc[mt][nt][2] * INST_SCALE));
            s1 += 1.0f / (1.0f + __expf(-acc[mt][nt][3] * INST_SCALE));
        }
        s0 += __shfl_xor_sync(0xffffffffu, s0, 1);
        s0 += __shfl_xor_sync(0xffffffffu, s0, 2);
        s1 += __shfl_xor_sync(0xffffffffu, s1, 1);
        s1 += __shfl_xor_sync(0xffffffffu, s1, 2);
        if (t == 0) {
            int row = bm + wm * 64 + mt * 16 + g;
            atomicAdd(&g_gacc[b * 512 + row], s0);
            atomicAdd(&g_gacc[b * 512 + row + 8], s1);
        }
    }
}

// ---------------------------------------------------------------------------
// tf32 flash attention: fixed-bound softmax + ldmatrix fragments.
// K smem [kv][d] (B-frag native), Vt smem [d][kv] (B-frag native via g_vt),
// P smem [q][kv] (A-frag native). All fragment loads are ldmatrix.x4.
// ---------------------------------------------------------------------------
__global__ __launch_bounds__(256, 2) void attn_t(
    const uint32_t* __restrict__ q, const uint32_t* __restrict__ k,
    const uint32_t* __restrict__ vt, float* __restrict__ o)
{
    extern __shared__ uint32_t sm[];

    const int tid  = threadIdx.x;
    const int lane = tid & 31;
    const int warp = tid >> 5;
    const int g    = lane >> 2;
    const int t    = lane & 3;
    const int bq   = blockIdx.y;
    const int h    = blockIdx.z;
    const int n0   = blockIdx.x * 128;
    const int gb   = bq & ~3;
    const int qrow = n0 + warp * 16;
    const uint32_t sb = (uint32_t)__cvta_generic_to_shared(sm);

    // Q fragments: raw bit loads (already tf32, already scaled)
    uint32_t qf[8][4];
    {
        const uint32_t* qb = q + ((size_t)(bq * CN + qrow)) * CD + h * CHD;
#pragma unroll
        for (int ks = 0; ks < 8; ks++) {
            int c = ks * 8 + t;
            qf[ks][0] = qb[(size_t)g * CD + c];
            qf[ks][1] = qb[(size_t)(g + 8) * CD + c];
            qf[ks][2] = qb[(size_t)g * CD + c + 4];
            qf[ks][3] = qb[(size_t)(g + 8) * CD + c + 4];
        }
    }

    float oa[8][4];
#pragma unroll
    for (int nt = 0; nt < 8; nt++)
#pragma unroll
        for (int r = 0; r < 4; r++) oa[nt][r] = 0.0f;
    float li0 = 0.0f, li1 = 0.0f;

    // per-warp P tile
    uint32_t* Pw = sm + 2 * AT_STAGE + warp * 16 * PPAD;
    const uint32_t pw_sb = sb + (uint32_t)(2 * AT_STAGE + warp * 16 * PPAD) * 4u;
    // ldmatrix row addresses (thread-dependent parts)
    const int lrow = lane & 7;          // row within 8-row block
    const int lmat = lane >> 3;         // matrix index 0..3
    // K/V: matrices = (ks half0, ks half1, ks+1 half0, ks+1 half1)
    const uint32_t kv_off = (uint32_t)(lrow * KPAD + lmat * 4) * 4u;
    // P: matrices = (a0: rows0-7 c0, a1: rows8-15 c0, a2: rows0-7 c4, a3: rows8-15 c4)
    const uint32_t p_off = (uint32_t)(((lmat & 1) * 8 + lrow) * PPAD + (lmat >> 1) * 4) * 4u;

    auto load_kv = [&](int kc, int stg) {
        const int m0 = kc * 64;
        const int kb = gb + (m0 >> 9);
        const int kn = m0 & 511;
        uint32_t ksm = sb + (uint32_t)(stg * AT_STAGE) * 4u;
        uint32_t vsm = ksm + AT_KV * 4u;
#pragma unroll
        for (int p = 0; p < 4; p++) {
            int idx = p * 256 + tid;
            int r   = idx >> 4;
            int c4  = (idx & 15) << 2;
            uint32_t off = (uint32_t)(r * KPAD + c4) * 4u;
            cp16(ksm + off, k + ((size_t)(kb * CN + kn + r)) * CD + h * CHD + c4);
            cp16(vsm + off, vt + ((size_t)((kb * CH + h) * CHD + r)) * CN + kn + c4);
        }
        CP_COMMIT();
    };

    load_kv(0, 0);
    int st = 0;

    for (int kc = 0; kc < 32; kc++) {
        CP_WAIT0();
        __syncthreads();
        if (kc < 31) load_kv(kc + 1, st ^ 1);

        const uint32_t ks_sb = sb + (uint32_t)(st * AT_STAGE) * 4u;
        const uint32_t vs_sb = ks_sb + AT_KV * 4u;

        // ---- S = Q @ K^T  (ldmatrix K fragments) ----
        float sacc[8][4];
#pragma unroll
        for (int nt = 0; nt < 8; nt++)
#pragma unroll
            for (int r = 0; r < 4; r++) sacc[nt][r] = 0.0f;
#pragma unroll
        for (int nt = 0; nt < 8; nt++) {
            uint32_t rowa = ks_sb + (uint32_t)(nt * 8 * KPAD) * 4u + kv_off;
#pragma unroll
            for (int kp = 0; kp < 4; kp++) {
                uint32_t kb4[4];
                ldsm_x4(kb4, rowa + (uint32_t)(kp * 16) * 4u);
                mma_tf32(sacc[nt], qf[2 * kp],     kb4);
                mma_tf32(sacc[nt], qf[2 * kp + 1], kb4 + 2);
            }
        }

        // ---- fixed-shift softmax: p = exp(s - 8) ----
#pragma unroll
        for (int nt = 0; nt < 8; nt++) {
            float p0 = __expf(sacc[nt][0] - SOFT_SHIFT);
            float p1 = __expf(sacc[nt][1] - SOFT_SHIFT);
            float p2 = __expf(sacc[nt][2] - SOFT_SHIFT);
            float p3 = __expf(sacc[nt][3] - SOFT_SHIFT);
            li0 += p0 + p1;
            li1 += p2 + p3;
            int col = nt * 8 + 2 * t;
            uint2 w0 = {f2tf32(p0), f2tf32(p1)};
            uint2 w1 = {f2tf32(p2), f2tf32(p3)};
            *(uint2*)&Pw[g * PPAD + col]       = w0;
            *(uint2*)&Pw[(g + 8) * PPAD + col] = w1;
        }
        __syncwarp();

        // ---- load all P fragments (8 ldmatrix.x4) ----
        uint32_t pf[8][4];
#pragma unroll
        for (int ks = 0; ks < 8; ks++)
            ldsm_x4(pf[ks], pw_sb + p_off + (uint32_t)(ks * 8) * 4u);

        // ---- O += P @ V  (ldmatrix V fragments from transposed tile) ----
#pragma unroll
        for (int nt = 0; nt < 8; nt++) {
            uint32_t rowv = vs_sb + (uint32_t)(nt * 8 * KPAD) * 4u + kv_off;
#pragma unroll
            for (int kp = 0; kp < 4; kp++) {
                uint32_t vb4[4];
                ldsm_x4(vb4, rowv + (uint32_t)(kp * 16) * 4u);
                mma_tf32(oa[nt], pf[2 * kp],     vb4);
                mma_tf32(oa[nt], pf[2 * kp + 1], vb4 + 2);
            }
        }
        __syncwarp();
        st ^= 1;
    }

    // final quad reduction of li, normalize, store tf32 bits
    li0 += __shfl_xor_sync(0xffffffffu, li0, 1);
    li0 += __shfl_xor_sync(0xffffffffu, li0, 2);
    li1 += __shfl_xor_sync(0xffffffffu, li1, 1);
    li1 += __shfl_xor_sync(0xffffffffu, li1, 2);
    float inv0 = 1.0f / li0, inv1 = 1.0f / li1;
    uint32_t* ob = (uint32_t*)(o + ((size_t)(bq * CN + qrow)) * CD + h * CHD);
#pragma unroll
    for (int nt = 0; nt < 8; nt++) {
        int col = nt * 8 + 2 * t;
        uint2 r0 = {f2tf32(oa[nt][0] * inv0), f2tf32(oa[nt][1] * inv0)};
        uint2 r1 = {f2tf32(oa[nt][2] * inv1), f2tf32(oa[nt][3] * inv1)};
        *(uint2*)(ob + (size_t)g * CD + col)       = r0;
        *(uint2*)(ob + (size_t)(g + 8) * CD + col) = r1;
    }
}

// ---------------------------------------------------------------------------
// E2 = emb[:4] @ Wik (tiny); ik = mask @ E2 + bik (tf32 bits out)
// ---------------------------------------------------------------------------
__global__ void e2_k(const float* __restrict__ emb, const float* __restrict__ Wik) {
    int n = blockIdx.x * 256 + threadIdx.x;
    int i = n >> 10;
    int c = n & 1023;
    const float* ep = emb + i * 1024;
    float acc = 0.0f;
#pragma unroll 4
    for (int kk = 0; kk < 1024; kk++)
        acc = fmaf(ep[kk], Wik[(size_t)kk * 1024 + c], acc);
    g_e2[n] = acc;
}

__global__ void ikb_k(const float* __restrict__ mask, const float* __restrict__ bik,
                      uint32_t* __restrict__ ik) {
    int idx = blockIdx.x * 256 + threadIdx.x;
    int d  = idx & 1023;
    int bn = idx >> 10;
    const float* mp = mask + (size_t)bn * 4;
    float acc = bik[d];
    acc = fmaf(mp[0], g_e2[d],        acc);
    acc = fmaf(mp[1], g_e2[1024 + d], acc);
    acc = fmaf(mp[2], g_e2[2048 + d], acc);
    acc = fmaf(mp[3], g_e2[3072 + d], acc);
    ik[idx] = f2tf32(acc);
}

// ---------------------------------------------------------------------------
// launch
// ---------------------------------------------------------------------------
extern "C" void kernel_launch(void* const* d_in, const int* in_sizes, int n_in,
                              void* d_out, int out_size)
{
    (void)in_sizes; (void)n_in; (void)out_size;
    const float* x    = (const float*)d_in[0];
    const float* mask = (const float*)d_in[1];
    const float* Wq   = (const float*)d_in[2];
    const float* bq   = (const float*)d_in[3];
    const float* Wk   = (const float*)d_in[4];
    const float* bk   = (const float*)d_in[5];
    const float* Wv   = (const float*)d_in[6];
    const float* bv   = (const float*)d_in[7];
    const float* Wo   = (const float*)d_in[8];
    const float* bo   = (const float*)d_in[9];
    const float* Wiq  = (const float*)d_in[10];
    const float* biq  = (const float*)d_in[11];
    const float* Wik  = (const float*)d_in[12];
    const float* bik  = (const float*)d_in[13];
    const float* emb  = (const float*)d_in[14];
    const float* qw   = (const float*)d_in[15];
    const float* kw   = (const float*)d_in[16];
    float* out = (float*)d_out;

    float *qp, *kp, *vtp, *op, *iqp;
    uint32_t *xt, *wq, *wk, *wv, *wiq, *wo, *ikp;
    cudaGetSymbolAddress((void**)&qp,  g_q);
    cudaGetSymbolAddress((void**)&kp,  g_k);
    cudaGetSymbolAddress((void**)&vtp, g_vt);
    cudaGetSymbolAddress((void**)&op,  g_o);
    cudaGetSymbolAddress((void**)&iqp, g_iq);
    cudaGetSymbolAddress((void**)&ikp, g_ik);
    cudaGetSymbolAddress((void**)&xt,  g_xt);
    cudaGetSymbolAddress((void**)&wq,  g_wq);
    cudaGetSymbolAddress((void**)&wk,  g_wk);
    cudaGetSymbolAddress((void**)&wv,  g_wv);
    cudaGetSymbolAddress((void**)&wiq, g_wiq);
    cudaGetSymbolAddress((void**)&wo,  g_wo);

    static bool attr_done = false;
    if (!attr_done) {
        cudaFuncSetAttribute(gemm_qkv, cudaFuncAttributeMaxDynamicSharedMemorySize, SMEM_GEMM);
        cudaFuncSetAttribute(gemm_a<0>, cudaFuncAttributeMaxDynamicSharedMemorySize, SMEM_GEMM);
        cudaFuncSetAttribute(gemm_a<2>, cudaFuncAttributeMaxDynamicSharedMemorySize, SMEM_GEMM);
        cudaFuncSetAttribute(instgate_t, cudaFuncAttributeMaxDynamicSharedMemorySize, SMEM_IG);
        cudaFuncSetAttribute(attn_t, cudaFuncAttributeMaxDynamicSharedMemorySize, SMEM_ATTN);
        attr_done = true;
    }

    dim3 gemm_grid(8, 32);

    zero_gacc_k<<<16, 256>>>();

    cvt_all_k<<<9216, 256>>>(x, Wq, Wk, Wv, Wiq, Wo, xt, wq, wk, wv, wiq, wo);

    gemm_qkv<<<dim3(8, 32, 3), 256, SMEM_GEMM>>>(xt, wq, wk, wv, bq, bk, bv,
                                                 qw, kw, qp, kp, vtp);

    attn_t<<<dim3(4, 8, 16), 256, SMEM_ATTN>>>((const uint32_t*)qp, (const uint32_t*)kp,
                                               (const uint32_t*)vtp, op);

    e2_k<<<16, 256>>>(emb, Wik);
    ikb_k<<<16384, 256>>>(mask, bik, ikp);

    gemm_a<0><<<gemm_grid, 256, SMEM_GEMM>>>((const uint32_t*)op, wiq, biq, iqp);

    instgate_t<<<dim3(4, 4, 8), 256, SMEM_IG>>>((const uint32_t*)iqp, ikp);

    gemm_a<2><<<gemm_grid, 256, SMEM_GEMM>>>((const uint32_t*)op, wo, bo, out);
}

// round 11
// speedup vs baseline: 3.1080x; 1.0241x over previous
#include <cuda_runtime.h>
#include <cstdint>
#include <cstddef>

// ---------------------------------------------------------------------------
// MIDIMultiInstanceAttention  (B=8, N=512, D=1024, H=16, HD=64, NI=4)
// tf32 tensor cores everywhere; ldmatrix fragment loads in ALL mma kernels;
// fixed-bound softmax; transposed weights for ldmatrix-native B fragments
// ---------------------------------------------------------------------------

#define CB 8
#define CN 512
#define CD 1024
#define CH 16
#define CHD 64
#define CM 4096
#define ATT_SCALE 0.125f
#define SOFT_SHIFT 8.0f
#define INST_SCALE (0.125f / 16.0f)

#define APAD 36
#define KPAD 68
#define PPAD 68

#define GA_AW (128 * APAD)                 // 4608 words
#define GA_STAGE (2 * GA_AW)               // A + B(t), 9216 words
#define SMEM_GEMM (2 * GA_STAGE * 4)       // 73728 B

#define AT_KV (64 * KPAD)                  // 4352 words
#define AT_STAGE (2 * AT_KV)               // K + Vt
#define SMEM_ATTN ((2 * AT_STAGE + 8 * 16 * PPAD) * 4)   // 104448 B

// scratch (device globals: allocation-free rule)
__device__ __align__(16) uint32_t g_xt[CM * CD];
__device__ __align__(16) uint32_t g_wq[CD * CD];    // transposed tf32 [n][k]
__device__ __align__(16) uint32_t g_wk[CD * CD];
__device__ __align__(16) uint32_t g_wv[CD * CD];
__device__ __align__(16) uint32_t g_wiq[CD * CD];
__device__ __align__(16) uint32_t g_wo[CD * CD];
__device__ __align__(16) float g_q [CM * CD];       // tf32 bits (pre-scaled)
__device__ __align__(16) float g_k [CM * CD];       // tf32 bits
__device__ __align__(16) float g_vt[CM * CD];       // tf32 bits, [b,h][d][n]
__device__ __align__(16) float g_o [CM * CD];       // tf32 bits
__device__ __align__(16) float g_iq[CM * CD];       // tf32 bits
__device__ __align__(16) uint32_t g_ik[CM * CD];    // tf32 bits
__device__ __align__(16) float g_e2[4 * CD];
__device__ float g_gacc[CM];

__global__ void zero_gacc_k() {
    int i = blockIdx.x * 256 + threadIdx.x;
    if (i < CM) g_gacc[i] = 0.0f;
}

// ---------------------------------------------------------------------------
// helpers
// ---------------------------------------------------------------------------
__device__ __forceinline__ uint32_t f2tf32(float x) {
    uint32_t r;
    asm("cvt.rna.tf32.f32 %0, %1;" : "=r"(r) : "f"(x));
    return r;
}

__device__ __forceinline__ void mma_tf32(float* d, const uint32_t* a, const uint32_t* b) {
    asm volatile(
        "mma.sync.aligned.m16n8k8.row.col.f32.tf32.tf32.f32 "
        "{%0,%1,%2,%3}, {%4,%5,%6,%7}, {%8,%9}, {%0,%1,%2,%3};\n"
        : "+f"(d[0]), "+f"(d[1]), "+f"(d[2]), "+f"(d[3])
        : "r"(a[0]), "r"(a[1]), "r"(a[2]), "r"(a[3]), "r"(b[0]), "r"(b[1]));
}

__device__ __forceinline__ void ldsm_x4(uint32_t* r, uint32_t saddr) {
    asm volatile("ldmatrix.sync.aligned.m8n8.x4.shared.b16 {%0,%1,%2,%3}, [%4];\n"
        : "=r"(r[0]), "=r"(r[1]), "=r"(r[2]), "=r"(r[3]) : "r"(saddr));
}

__device__ __forceinline__ void cp16(uint32_t dst, const void* src) {
    asm volatile("cp.async.cg.shared.global [%0], [%1], 16;\n" :: "r"(dst), "l"(src));
}
#define CP_COMMIT() asm volatile("cp.async.commit_group;\n")
#define CP_WAIT0()  asm volatile("cp.async.wait_group 0;\n")

// x -> tf32 bits (no transpose)
__global__ void cvt_x_k(const float* __restrict__ x, uint32_t* __restrict__ xt) {
    int i = blockIdx.x * 256 + threadIdx.x;
    float4 v = ((const float4*)x)[i];
    uint4 o = {f2tf32(v.x), f2tf32(v.y), f2tf32(v.z), f2tf32(v.w)};
    ((uint4*)xt)[i] = o;
}

// weights: cvt to tf32 bits AND transpose -> Wt[n][k]
__global__ void wtr_k(const float* __restrict__ w0, const float* __restrict__ w1,
                      const float* __restrict__ w2, const float* __restrict__ w3,
                      const float* __restrict__ w4,
                      uint32_t* __restrict__ o0, uint32_t* __restrict__ o1,
                      uint32_t* __restrict__ o2, uint32_t* __restrict__ o3,
                      uint32_t* __restrict__ o4)
{
    __shared__ uint32_t ts[32][33];
    const int z = blockIdx.z;
    const float* src = (z == 0) ? w0 : (z == 1) ? w1 : (z == 2) ? w2 : (z == 3) ? w3 : w4;
    uint32_t*    dst = (z == 0) ? o0 : (z == 1) ? o1 : (z == 2) ? o2 : (z == 3) ? o3 : o4;
    const int n0 = blockIdx.x * 32;
    const int k0 = blockIdx.y * 32;
    const int c  = threadIdx.x & 31;
    const int r8 = threadIdx.x >> 5;
#pragma unroll
    for (int i = 0; i < 4; i++) {
        int r = r8 + i * 8;
        ts[r][c] = f2tf32(src[(size_t)(k0 + r) * CD + n0 + c]);
    }
    __syncthreads();
#pragma unroll
    for (int i = 0; i < 4; i++) {
        int r = r8 + i * 8;
        dst[(size_t)(n0 + r) * CD + k0 + c] = ts[c][r];
    }
}

// ---------------------------------------------------------------------------
// fused QKV projection: z selects {Wq,Wk,Wv} (transposed). z<2 -> fused
// per-head RMSNorm (Q pre-scaled by ATT_SCALE). z==2 -> V stored transposed.
// ---------------------------------------------------------------------------
__global__ __launch_bounds__(256, 2) void gemm_qkv(
    const uint32_t* __restrict__ A,
    const uint32_t* __restrict__ Wq_, const uint32_t* __restrict__ Wk_,
    const uint32_t* __restrict__ Wv_,
    const float* __restrict__ bq_, const float* __restrict__ bk_,
    const float* __restrict__ bv_,
    const float* __restrict__ qw_, const float* __restrict__ kw_,
    float* __restrict__ oq_, float* __restrict__ ok_, float* __restrict__ ov_)
{
    extern __shared__ uint32_t sm[];
    const int z = blockIdx.z;
    const uint32_t* W   = (z == 0) ? Wq_ : (z == 1) ? Wk_ : Wv_;
    const float* bias   = (z == 0) ? bq_ : (z == 1) ? bk_ : bv_;
    const float* normw  = (z == 0) ? qw_ : kw_;
    float* C            = (z == 0) ? oq_ : (z == 1) ? ok_ : ov_;
    const float qsc     = (z == 0) ? ATT_SCALE : 1.0f;

    const int tid  = threadIdx.x;
    const int lane = tid & 31;
    const int warp = tid >> 5;
    const int wm   = warp >> 2;
    const int wn   = warp & 3;
    const int bm   = blockIdx.y * 128;
    const int bn   = blockIdx.x * 128;
    const int g    = lane >> 2;
    const int t    = lane & 3;
    const int lrow = lane & 7;
    const int lmat = lane >> 3;
    const uint32_t sb = (uint32_t)__cvta_generic_to_shared(sm);
    // ldmatrix lane-offsets (words)
    const int a_loff = ((lmat & 1) * 8 + lrow) * APAD + (lmat >> 1) * 4;
    const int b_loff = ((lmat >> 1) * 8 + lrow) * APAD + (lmat & 1) * 4;

    float acc[4][4][4];
#pragma unroll
    for (int i = 0; i < 4; i++)
#pragma unroll
        for (int j = 0; j < 4; j++)
#pragma unroll
            for (int r = 0; r < 4; r++) acc[i][j][r] = 0.0f;

    auto load_stage = [&](int kt, int st) {
        uint32_t as = sb + (uint32_t)(st * GA_STAGE) * 4u;
        uint32_t bs = as + GA_AW * 4u;
#pragma unroll
        for (int p = 0; p < 4; p++) {
            int idx = p * 256 + tid;
            int r = idx >> 3, c4 = (idx & 7) << 2;
            cp16(as + (uint32_t)(r * APAD + c4) * 4u,
                 A + (size_t)(bm + r) * CD + kt + c4);
            cp16(bs + (uint32_t)(r * APAD + c4) * 4u,
                 W + (size_t)(bn + r) * CD + kt + c4);
        }
        CP_COMMIT();
    };

    load_stage(0, 0);
    int st = 0;
    for (int it = 0; it < 32; it++) {
        CP_WAIT0();
        __syncthreads();
        if (it < 31) load_stage((it + 1) * 32, st ^ 1);
        const uint32_t as_b = sb + (uint32_t)(st * GA_STAGE) * 4u;
        const uint32_t bs_b = as_b + GA_AW * 4u;
#pragma unroll
        for (int ks = 0; ks < 4; ks++) {
            const int kc = ks * 8;
            uint32_t af[4][4], bq4[2][4];
#pragma unroll
            for (int mt = 0; mt < 4; mt++)
                ldsm_x4(af[mt], as_b + (uint32_t)((wm * 64 + mt * 16) * APAD + kc + a_loff) * 4u);
#pragma unroll
            for (int h2 = 0; h2 < 2; h2++)
                ldsm_x4(bq4[h2], bs_b + (uint32_t)((wn * 32 + h2 * 16) * APAD + kc + b_loff) * 4u);
#pragma unroll
            for (int mt = 0; mt < 4; mt++)
#pragma unroll
                for (int nt = 0; nt < 4; nt++)
                    mma_tf32(acc[mt][nt], af[mt], &bq4[nt >> 1][(nt & 1) * 2]);
        }
        st ^= 1;
    }
    __syncthreads();

    float2 bb[4];
#pragma unroll
    for (int nt = 0; nt < 4; nt++)
        bb[nt] = *(const float2*)(bias + bn + wn * 32 + nt * 8 + t * 2);

    uint32_t* Cu = (uint32_t*)C;
    if (z < 2) {
        float ssA[4], ssB[4];
#pragma unroll
        for (int mt = 0; mt < 4; mt++) {
            float s0 = 0.0f, s1 = 0.0f;
#pragma unroll
            for (int nt = 0; nt < 4; nt++) {
                float v0 = acc[mt][nt][0] + bb[nt].x;
                float v1 = acc[mt][nt][1] + bb[nt].y;
                float v2 = acc[mt][nt][2] + bb[nt].x;
                float v3 = acc[mt][nt][3] + bb[nt].y;
                s0 = fmaf(v0, v0, s0); s0 = fmaf(v1, v1, s0);
                s1 = fmaf(v2, v2, s1); s1 = fmaf(v3, v3, s1);
            }
            s0 += __shfl_xor_sync(0xffffffffu, s0, 1);
            s0 += __shfl_xor_sync(0xffffffffu, s0, 2);
            s1 += __shfl_xor_sync(0xffffffffu, s1, 1);
            s1 += __shfl_xor_sync(0xffffffffu, s1, 2);
            ssA[mt] = s0; ssB[mt] = s1;
        }
        float* S = (float*)sm;
        if (t == 0) {
#pragma unroll
            for (int mt = 0; mt < 4; mt++) {
                int r0 = wm * 64 + mt * 16 + g;
                S[r0 * 4 + wn]       = ssA[mt];
                S[(r0 + 8) * 4 + wn] = ssB[mt];
            }
        }
        __syncthreads();
        const int pi = wn & ~1;
#pragma unroll
        for (int mt = 0; mt < 4; mt++) {
            int r0 = wm * 64 + mt * 16 + g;
            float sc0 = rsqrtf((S[r0 * 4 + pi] + S[r0 * 4 + pi + 1]) * (1.0f / 64.0f) + 1e-6f) * qsc;
            float sc1 = rsqrtf((S[(r0 + 8) * 4 + pi] + S[(r0 + 8) * 4 + pi + 1]) * (1.0f / 64.0f) + 1e-6f) * qsc;
#pragma unroll
            for (int nt = 0; nt < 4; nt++) {
                int cl = wn * 32 + nt * 8 + t * 2;
                float2 ww = *(const float2*)(normw + (cl & 63));
                float v0 = acc[mt][nt][0] + bb[nt].x;
                float v1 = acc[mt][nt][1] + bb[nt].y;
                float v2 = acc[mt][nt][2] + bb[nt].x;
                float v3 = acc[mt][nt][3] + bb[nt].y;
                uint2 o0 = {f2tf32(v0 * sc0 * ww.x), f2tf32(v1 * sc0 * ww.y)};
                uint2 o1 = {f2tf32(v2 * sc1 * ww.x), f2tf32(v3 * sc1 * ww.y)};
                *(uint2*)(Cu + (size_t)(bm + r0) * CD + bn + cl)     = o0;
                *(uint2*)(Cu + (size_t)(bm + r0 + 8) * CD + bn + cl) = o1;
            }
        }
    } else {
        // V: store TRANSPOSED tf32 bits: vt[((b*16+h)*64+hd)*512 + n]
#pragma unroll
        for (int mt = 0; mt < 4; mt++) {
            int m0 = bm + wm * 64 + mt * 16 + g;
#pragma unroll
            for (int nt = 0; nt < 4; nt++) {
                int d0 = bn + wn * 32 + nt * 8 + t * 2;
                float v00 = acc[mt][nt][0] + bb[nt].x;
                float v01 = acc[mt][nt][1] + bb[nt].y;
                float v10 = acc[mt][nt][2] + bb[nt].x;
                float v11 = acc[mt][nt][3] + bb[nt].y;
                size_t ib = ((size_t)((m0 >> 9) * CH + (d0 >> 6)) * CHD + (d0 & 63)) * CN
                          + (m0 & 511);
                Cu[ib]            = f2tf32(v00);
                Cu[ib + CN]       = f2tf32(v01);
                Cu[ib + 8]        = f2tf32(v10);
                Cu[ib + CN + 8]   = f2tf32(v11);
            }
        }
    }
}

// ---------------------------------------------------------------------------
// async tf32 GEMM (W transposed [n][k]); MODE 0: tf32 bits; MODE 2: gated f32
// ---------------------------------------------------------------------------
template <int MODE>
__global__ __launch_bounds__(256, 2) void gemm_a(
    const uint32_t* __restrict__ A, const uint32_t* __restrict__ W,
    const float* __restrict__ bias, float* __restrict__ C)
{
    extern __shared__ uint32_t sm[];
    const int tid  = threadIdx.x;
    const int lane = tid & 31;
    const int warp = tid >> 5;
    const int wm   = warp >> 2;
    const int wn   = warp & 3;
    const int bm   = blockIdx.y * 128;
    const int bn   = blockIdx.x * 128;
    const int g    = lane >> 2;
    const int t    = lane & 3;
    const int lrow = lane & 7;
    const int lmat = lane >> 3;
    const uint32_t sb = (uint32_t)__cvta_generic_to_shared(sm);
    const int a_loff = ((lmat & 1) * 8 + lrow) * APAD + (lmat >> 1) * 4;
    const int b_loff = ((lmat >> 1) * 8 + lrow) * APAD + (lmat & 1) * 4;

    float acc[4][4][4];
#pragma unroll
    for (int i = 0; i < 4; i++)
#pragma unroll
        for (int j = 0; j < 4; j++)
#pragma unroll
            for (int r = 0; r < 4; r++) acc[i][j][r] = 0.0f;

    auto load_stage = [&](int kt, int st) {
        uint32_t as = sb + (uint32_t)(st * GA_STAGE) * 4u;
        uint32_t bs = as + GA_AW * 4u;
#pragma unroll
        for (int p = 0; p < 4; p++) {
            int idx = p * 256 + tid;
            int r = idx >> 3, c4 = (idx & 7) << 2;
            cp16(as + (uint32_t)(r * APAD + c4) * 4u,
                 A + (size_t)(bm + r) * CD + kt + c4);
            cp16(bs + (uint32_t)(r * APAD + c4) * 4u,
                 W + (size_t)(bn + r) * CD + kt + c4);
        }
        CP_COMMIT();
    };

    load_stage(0, 0);
    int st = 0;
    for (int it = 0; it < 32; it++) {
        CP_WAIT0();
        __syncthreads();
        if (it < 31) load_stage((it + 1) * 32, st ^ 1);
        const uint32_t as_b = sb + (uint32_t)(st * GA_STAGE) * 4u;
        const uint32_t bs_b = as_b + GA_AW * 4u;
#pragma unroll
        for (int ks = 0; ks < 4; ks++) {
            const int kc = ks * 8;
            uint32_t af[4][4], bq4[2][4];
#pragma unroll
            for (int mt = 0; mt < 4; mt++)
                ldsm_x4(af[mt], as_b + (uint32_t)((wm * 64 + mt * 16) * APAD + kc + a_loff) * 4u);
#pragma unroll
            for (int h2 = 0; h2 < 2; h2++)
                ldsm_x4(bq4[h2], bs_b + (uint32_t)((wn * 32 + h2 * 16) * APAD + kc + b_loff) * 4u);
#pragma unroll
            for (int mt = 0; mt < 4; mt++)
#pragma unroll
                for (int nt = 0; nt < 4; nt++)
                    mma_tf32(acc[mt][nt], af[mt], &bq4[nt >> 1][(nt & 1) * 2]);
        }
        st ^= 1;
    }

    float2 bb[4];
#pragma unroll
    for (int nt = 0; nt < 4; nt++)
        bb[nt] = *(const float2*)(bias + bn + wn * 32 + nt * 8 + t * 2);

    if (MODE == 2) {
#pragma unroll
        for (int mt = 0; mt < 4; mt++) {
            int r0 = bm + wm * 64 + mt * 16 + g;
            float ga0 = 1.0f + g_gacc[r0]     * (1.0f / 512.0f);
            float ga1 = 1.0f + g_gacc[r0 + 8] * (1.0f / 512.0f);
#pragma unroll
            for (int nt = 0; nt < 4; nt++) {
                int col = bn + wn * 32 + nt * 8 + t * 2;
                float2 w0 = {acc[mt][nt][0] * ga0 + bb[nt].x, acc[mt][nt][1] * ga0 + bb[nt].y};
                float2 w1 = {acc[mt][nt][2] * ga1 + bb[nt].x, acc[mt][nt][3] * ga1 + bb[nt].y};
                *(float2*)(C + (size_t)r0 * CD + col)       = w0;
                *(float2*)(C + (size_t)(r0 + 8) * CD + col) = w1;
            }
        }
    } else {
        uint32_t* Cu = (uint32_t*)C;
#pragma unroll
        for (int mt = 0; mt < 4; mt++) {
            int r0 = bm + wm * 64 + mt * 16 + g;
#pragma unroll
            for (int nt = 0; nt < 4; nt++) {
                int col = bn + wn * 32 + nt * 8 + t * 2;
                uint2 o0 = {f2tf32(acc[mt][nt][0] + bb[nt].x), f2tf32(acc[mt][nt][1] + bb[nt].y)};
                uint2 o1 = {f2tf32(acc[mt][nt][2] + bb[nt].x), f2tf32(acc[mt][nt][3] + bb[nt].y)};
                *(uint2*)(Cu + (size_t)r0 * CD + col)       = o0;
                *(uint2*)(Cu + (size_t)(r0 + 8) * CD + col) = o1;
            }
        }
    }
}

// ---------------------------------------------------------------------------
// instance gate: both operands n-major [row][k] -> ldmatrix for A and B
// ---------------------------------------------------------------------------
__global__ __launch_bounds__(256, 2) void instgate_t(
    const uint32_t* __restrict__ iq, const uint32_t* __restrict__ ikp)
{
    extern __shared__ uint32_t sm[];
    const int tid  = threadIdx.x;
    const int lane = tid & 31;
    const int warp = tid >> 5;
    const int wm   = warp >> 2;
    const int wn   = warp & 3;
    const int b    = blockIdx.z;
    const int bm   = blockIdx.y * 128;
    const int bn   = blockIdx.x * 128;
    const int g    = lane >> 2;
    const int t    = lane & 3;
    const int lrow = lane & 7;
    const int lmat = lane >> 3;
    const uint32_t* Ab = iq  + (size_t)b * 512 * CD;
    const uint32_t* Bb = ikp + (size_t)b * 512 * CD;
    const uint32_t sb = (uint32_t)__cvta_generic_to_shared(sm);
    const int a_loff = ((lmat & 1) * 8 + lrow) * APAD + (lmat >> 1) * 4;
    const int b_loff = ((lmat >> 1) * 8 + lrow) * APAD + (lmat & 1) * 4;

    float acc[4][4][4];
#pragma unroll
    for (int i = 0; i < 4; i++)
#pragma unroll
        for (int j = 0; j < 4; j++)
#pragma unroll
            for (int r = 0; r < 4; r++) acc[i][j][r] = 0.0f;

    auto load_stage = [&](int kt, int st) {
        uint32_t as = sb + (uint32_t)(st * GA_STAGE) * 4u;
        uint32_t bs = as + GA_AW * 4u;
#pragma unroll
        for (int p = 0; p < 4; p++) {
            int idx = p * 256 + tid;
            int r = idx >> 3, c4 = (idx & 7) << 2;
            cp16(as + (uint32_t)(r * APAD + c4) * 4u, Ab + (size_t)(bm + r) * CD + kt + c4);
            cp16(bs + (uint32_t)(r * APAD + c4) * 4u, Bb + (size_t)(bn + r) * CD + kt + c4);
        }
        CP_COMMIT();
    };

    load_stage(0, 0);
    int st = 0;
    for (int it = 0; it < 32; it++) {
        CP_WAIT0();
        __syncthreads();
        if (it < 31) load_stage((it + 1) * 32, st ^ 1);
        const uint32_t as_b = sb + (uint32_t)(st * GA_STAGE) * 4u;
        const uint32_t bs_b = as_b + GA_AW * 4u;
#pragma unroll
        for (int ks = 0; ks < 4; ks++) {
            const int kc = ks * 8;
            uint32_t af[4][4], bq4[2][4];
#pragma unroll
            for (int mt = 0; mt < 4; mt++)
                ldsm_x4(af[mt], as_b + (uint32_t)((wm * 64 + mt * 16) * APAD + kc + a_loff) * 4u);
#pragma unroll
            for (int h2 = 0; h2 < 2; h2++)
                ldsm_x4(bq4[h2], bs_b + (uint32_t)((wn * 32 + h2 * 16) * APAD + kc + b_loff) * 4u);
#pragma unroll
            for (int mt = 0; mt < 4; mt++)
#pragma unroll
                for (int nt = 0; nt < 4; nt++)
                    mma_tf32(acc[mt][nt], af[mt], &bq4[nt >> 1][(nt & 1) * 2]);
        }
        st ^= 1;
    }

#pragma unroll
    for (int mt = 0; mt < 4; mt++) {
        float s0 = 0.0f, s1 = 0.0f;
#pragma unroll
        for (int nt = 0; nt < 4; nt++) {
            s0 += 1.0f / (1.0f + __expf(-acc[mt][nt][0] * INST_SCALE));
            s0 += 1.0f / (1.0f + __expf(-acc[mt][nt][1] * INST_SCALE));
            s1 += 1.0f / (1.0f + __expf(-acc[mt][nt][2] * INST_SCALE));
            s1 += 1.0f / (1.0f + __expf(-acc[mt][nt][3] * INST_SCALE));
        }
        s0 += __shfl_xor_sync(0xffffffffu, s0, 1);
        s0 += __shfl_xor_sync(0xffffffffu, s0, 2);
        s1 += __shfl_xor_sync(0xffffffffu, s1, 1);
        s1 += __shfl_xor_sync(0xffffffffu, s1, 2);
        if (t == 0) {
            int row = bm + wm * 64 + mt * 16 + g;
            atomicAdd(&g_gacc[b * 512 + row], s0);
            atomicAdd(&g_gacc[b * 512 + row + 8], s1);
        }
    }
}

// ---------------------------------------------------------------------------
// tf32 flash attention: fixed-bound softmax + ldmatrix fragments (R8-validated)
// ---------------------------------------------------------------------------
__global__ __launch_bounds__(256, 2) void attn_t(
    const uint32_t* __restrict__ q, const uint32_t* __restrict__ k,
    const uint32_t* __restrict__ vt, float* __restrict__ o)
{
    extern __shared__ uint32_t sm[];

    const int tid  = threadIdx.x;
    const int lane = tid & 31;
    const int warp = tid >> 5;
    const int g    = lane >> 2;
    const int t    = lane & 3;
    const int bq   = blockIdx.y;
    const int h    = blockIdx.z;
    const int n0   = blockIdx.x * 128;
    const int gb   = bq & ~3;
    const int qrow = n0 + warp * 16;
    const uint32_t sb = (uint32_t)__cvta_generic_to_shared(sm);

    uint32_t qf[8][4];
    {
        const uint32_t* qb = q + ((size_t)(bq * CN + qrow)) * CD + h * CHD;
#pragma unroll
        for (int ks = 0; ks < 8; ks++) {
            int c = ks * 8 + t;
            qf[ks][0] = qb[(size_t)g * CD + c];
            qf[ks][1] = qb[(size_t)(g + 8) * CD + c];
            qf[ks][2] = qb[(size_t)g * CD + c + 4];
            qf[ks][3] = qb[(size_t)(g + 8) * CD + c + 4];
        }
    }

    float oa[8][4];
#pragma unroll
    for (int nt = 0; nt < 8; nt++)
#pragma unroll
        for (int r = 0; r < 4; r++) oa[nt][r] = 0.0f;
    float li0 = 0.0f, li1 = 0.0f;

    uint32_t* Pw = sm + 2 * AT_STAGE + warp * 16 * PPAD;
    const uint32_t pw_sb = sb + (uint32_t)(2 * AT_STAGE + warp * 16 * PPAD) * 4u;
    const int lrow = lane & 7;
    const int lmat = lane >> 3;
    const uint32_t kv_off = (uint32_t)(lrow * KPAD + lmat * 4) * 4u;
    const uint32_t p_off = (uint32_t)(((lmat & 1) * 8 + lrow) * PPAD + (lmat >> 1) * 4) * 4u;

    auto load_kv = [&](int kc, int stg) {
        const int m0 = kc * 64;
        const int kb = gb + (m0 >> 9);
        const int kn = m0 & 511;
        uint32_t ksm = sb + (uint32_t)(stg * AT_STAGE) * 4u;
        uint32_t vsm = ksm + AT_KV * 4u;
#pragma unroll
        for (int p = 0; p < 4; p++) {
            int idx = p * 256 + tid;
            int r   = idx >> 4;
            int c4  = (idx & 15) << 2;
            uint32_t off = (uint32_t)(r * KPAD + c4) * 4u;
            cp16(ksm + off, k + ((size_t)(kb * CN + kn + r)) * CD + h * CHD + c4);
            cp16(vsm + off, vt + ((size_t)((kb * CH + h) * CHD + r)) * CN + kn + c4);
        }
        CP_COMMIT();
    };

    load_kv(0, 0);
    int st = 0;

    for (int kc = 0; kc < 32; kc++) {
        CP_WAIT0();
        __syncthreads();
        if (kc < 31) load_kv(kc + 1, st ^ 1);

        const uint32_t ks_sb = sb + (uint32_t)(st * AT_STAGE) * 4u;
        const uint32_t vs_sb = ks_sb + AT_KV * 4u;

        float sacc[8][4];
#pragma unroll
        for (int nt = 0; nt < 8; nt++)
#pragma unroll
            for (int r = 0; r < 4; r++) sacc[nt][r] = 0.0f;
#pragma unroll
        for (int nt = 0; nt < 8; nt++) {
            uint32_t rowa = ks_sb + (uint32_t)(nt * 8 * KPAD) * 4u + kv_off;
#pragma unroll
            for (int kp = 0; kp < 4; kp++) {
                uint32_t kb4[4];
                ldsm_x4(kb4, rowa + (uint32_t)(kp * 16) * 4u);
                mma_tf32(sacc[nt], qf[2 * kp],     kb4);
                mma_tf32(sacc[nt], qf[2 * kp + 1], kb4 + 2);
            }
        }

#pragma unroll
        for (int nt = 0; nt < 8; nt++) {
            float p0 = __expf(sacc[nt][0] - SOFT_SHIFT);
            float p1 = __expf(sacc[nt][1] - SOFT_SHIFT);
            float p2 = __expf(sacc[nt][2] - SOFT_SHIFT);
            float p3 = __expf(sacc[nt][3] - SOFT_SHIFT);
            li0 += p0 + p1;
            li1 += p2 + p3;
            int col = nt * 8 + 2 * t;
            uint2 w0 = {f2tf32(p0), f2tf32(p1)};
            uint2 w1 = {f2tf32(p2), f2tf32(p3)};
            *(uint2*)&Pw[g * PPAD + col]       = w0;
            *(uint2*)&Pw[(g + 8) * PPAD + col] = w1;
        }
        __syncwarp();

        uint32_t pf[8][4];
#pragma unroll
        for (int ks = 0; ks < 8; ks++)
            ldsm_x4(pf[ks], pw_sb + p_off + (uint32_t)(ks * 8) * 4u);

#pragma unroll
        for (int nt = 0; nt < 8; nt++) {
            uint32_t rowv = vs_sb + (uint32_t)(nt * 8 * KPAD) * 4u + kv_off;
#pragma unroll
            for (int kp = 0; kp < 4; kp++) {
                uint32_t vb4[4];
                ldsm_x4(vb4, rowv + (uint32_t)(kp * 16) * 4u);
                mma_tf32(oa[nt], pf[2 * kp],     vb4);
                mma_tf32(oa[nt], pf[2 * kp + 1], vb4 + 2);
            }
        }
        __syncwarp();
        st ^= 1;
    }

    li0 += __shfl_xor_sync(0xffffffffu, li0, 1);
    li0 += __shfl_xor_sync(0xffffffffu, li0, 2);
    li1 += __shfl_xor_sync(0xffffffffu, li1, 1);
    li1 += __shfl_xor_sync(0xffffffffu, li1, 2);
    float inv0 = 1.0f / li0, inv1 = 1.0f / li1;
    uint32_t* ob = (uint32_t*)(o + ((size_t)(bq * CN + qrow)) * CD + h * CHD);
#pragma unroll
    for (int nt = 0; nt < 8; nt++) {
        int col = nt * 8 + 2 * t;
        uint2 r0 = {f2tf32(oa[nt][0] * inv0), f2tf32(oa[nt][1] * inv0)};
        uint2 r1 = {f2tf32(oa[nt][2] * inv1), f2tf32(oa[nt][3] * inv1)};
        *(uint2*)(ob + (size_t)g * CD + col)       = r0;
        *(uint2*)(ob + (size_t)(g + 8) * CD + col) = r1;
    }
}

// ---------------------------------------------------------------------------
// E2 = emb[:4] @ Wik (tiny); ik = mask @ E2 + bik (tf32 bits out)
// ---------------------------------------------------------------------------
__global__ void e2_k(const float* __restrict__ emb, const float* __restrict__ Wik) {
    int n = blockIdx.x * 256 + threadIdx.x;
    int i = n >> 10;
    int c = n & 1023;
    const float* ep = emb + i * 1024;
    float acc = 0.0f;
#pragma unroll 4
    for (int kk = 0; kk < 1024; kk++)
        acc = fmaf(ep[kk], Wik[(size_t)kk * 1024 + c], acc);
    g_e2[n] = acc;
}

__global__ void ikb_k(const float* __restrict__ mask, const float* __restrict__ bik,
                      uint32_t* __restrict__ ik) {
    int idx = blockIdx.x * 256 + threadIdx.x;
    int d  = idx & 1023;
    int bn = idx >> 10;
    const float* mp = mask + (size_t)bn * 4;
    float acc = bik[d];
    acc = fmaf(mp[0], g_e2[d],        acc);
    acc = fmaf(mp[1], g_e2[1024 + d], acc);
    acc = fmaf(mp[2], g_e2[2048 + d], acc);
    acc = fmaf(mp[3], g_e2[3072 + d], acc);
    ik[idx] = f2tf32(acc);
}

// ---------------------------------------------------------------------------
// launch
// ---------------------------------------------------------------------------
extern "C" void kernel_launch(void* const* d_in, const int* in_sizes, int n_in,
                              void* d_out, int out_size)
{
    (void)in_sizes; (void)n_in; (void)out_size;
    const float* x    = (const float*)d_in[0];
    const float* mask = (const float*)d_in[1];
    const float* Wq   = (const float*)d_in[2];
    const float* bq   = (const float*)d_in[3];
    const float* Wk   = (const float*)d_in[4];
    const float* bk   = (const float*)d_in[5];
    const float* Wv   = (const float*)d_in[6];
    const float* bv   = (const float*)d_in[7];
    const float* Wo   = (const float*)d_in[8];
    const float* bo   = (const float*)d_in[9];
    const float* Wiq  = (const float*)d_in[10];
    const float* biq  = (const float*)d_in[11];
    const float* Wik  = (const float*)d_in[12];
    const float* bik  = (const float*)d_in[13];
    const float* emb  = (const float*)d_in[14];
    const float* qw   = (const float*)d_in[15];
    const float* kw   = (const float*)d_in[16];
    float* out = (float*)d_out;

    float *qp, *kp, *vtp, *op, *iqp;
    uint32_t *xt, *wq, *wk, *wv, *wiq, *wo, *ikp;
    cudaGetSymbolAddress((void**)&qp,  g_q);
    cudaGetSymbolAddress((void**)&kp,  g_k);
    cudaGetSymbolAddress((void**)&vtp, g_vt);
    cudaGetSymbolAddress((void**)&op,  g_o);
    cudaGetSymbolAddress((void**)&iqp, g_iq);
    cudaGetSymbolAddress((void**)&ikp, g_ik);
    cudaGetSymbolAddress((void**)&xt,  g_xt);
    cudaGetSymbolAddress((void**)&wq,  g_wq);
    cudaGetSymbolAddress((void**)&wk,  g_wk);
    cudaGetSymbolAddress((void**)&wv,  g_wv);
    cudaGetSymbolAddress((void**)&wiq, g_wiq);
    cudaGetSymbolAddress((void**)&wo,  g_wo);

    static bool attr_done = false;
    if (!attr_done) {
        cudaFuncSetAttribute(gemm_qkv, cudaFuncAttributeMaxDynamicSharedMemorySize, SMEM_GEMM);
        cudaFuncSetAttribute(gemm_a<0>, cudaFuncAttributeMaxDynamicSharedMemorySize, SMEM_GEMM);
        cudaFuncSetAttribute(gemm_a<2>, cudaFuncAttributeMaxDynamicSharedMemorySize, SMEM_GEMM);
        cudaFuncSetAttribute(instgate_t, cudaFuncAttributeMaxDynamicSharedMemorySize, SMEM_GEMM);
        cudaFuncSetAttribute(attn_t, cudaFuncAttributeMaxDynamicSharedMemorySize, SMEM_ATTN);
        attr_done = true;
    }

    dim3 gemm_grid(8, 32);

    zero_gacc_k<<<16, 256>>>();

    cvt_x_k<<<4096, 256>>>(x, xt);
    wtr_k<<<dim3(32, 32, 5), 256>>>(Wq, Wk, Wv, Wiq, Wo, wq, wk, wv, wiq, wo);

    gemm_qkv<<<dim3(8, 32, 3), 256, SMEM_GEMM>>>(xt, wq, wk, wv, bq, bk, bv,
                                                 qw, kw, qp, kp, vtp);

    attn_t<<<dim3(4, 8, 16), 256, SMEM_ATTN>>>((const uint32_t*)qp, (const uint32_t*)kp,
                                               (const uint32_t*)vtp, op);

    e2_k<<<16, 256>>>(emb, Wik);
    ikb_k<<<16384, 256>>>(mask, bik, ikp);

    gemm_a<0><<<gemm_grid, 256, SMEM_GEMM>>>((const uint32_t*)op, wiq, biq, iqp);

    instgate_t<<<dim3(4, 4, 8), 256, SMEM_GEMM>>>((const uint32_t*)iqp, ikp);

    gemm_a<2><<<gemm_grid, 256, SMEM_GEMM>>>((const uint32_t*)op, wo, bo, out);
}

// round 12
// speedup vs baseline: 3.6893x; 1.1871x over previous
#include <cuda_runtime.h>
#include <cstdint>
#include <cstddef>

// ---------------------------------------------------------------------------
// MIDIMultiInstanceAttention  (B=8, N=512, D=1024, H=16, HD=64, NI=4)
// tf32 tensor cores everywhere; ldmatrix fragment loads in ALL mma kernels;
// fixed-bound softmax; transposed weights; parallel k-split e2
// ---------------------------------------------------------------------------

#define CB 8
#define CN 512
#define CD 1024
#define CH 16
#define CHD 64
#define CM 4096
#define ATT_SCALE 0.125f
#define SOFT_SHIFT 8.0f
#define INST_SCALE (0.125f / 16.0f)

#define APAD 36
#define KPAD 68
#define PPAD 68

#define GA_AW (128 * APAD)                 // 4608 words
#define GA_STAGE (2 * GA_AW)               // A + B(t), 9216 words
#define SMEM_GEMM (2 * GA_STAGE * 4)       // 73728 B

#define AT_KV (64 * KPAD)                  // 4352 words
#define AT_STAGE (2 * AT_KV)               // K + Vt
#define SMEM_ATTN ((2 * AT_STAGE + 8 * 16 * PPAD) * 4)   // 104448 B

// scratch (device globals: allocation-free rule)
__device__ __align__(16) uint32_t g_xt[CM * CD];
__device__ __align__(16) uint32_t g_wq[CD * CD];    // transposed tf32 [n][k]
__device__ __align__(16) uint32_t g_wk[CD * CD];
__device__ __align__(16) uint32_t g_wv[CD * CD];
__device__ __align__(16) uint32_t g_wiq[CD * CD];
__device__ __align__(16) uint32_t g_wo[CD * CD];
__device__ __align__(16) float g_q [CM * CD];       // tf32 bits (pre-scaled)
__device__ __align__(16) float g_k [CM * CD];       // tf32 bits
__device__ __align__(16) float g_vt[CM * CD];       // tf32 bits, [b,h][d][n]
__device__ __align__(16) float g_o [CM * CD];       // tf32 bits
__device__ __align__(16) float g_iq[CM * CD];       // tf32 bits
__device__ __align__(16) uint32_t g_ik[CM * CD];    // tf32 bits
__device__ __align__(16) float g_e2[4 * CD];
__device__ float g_gacc[CM];

// zero gacc AND e2 partial-sum buffer (both 4096 floats)
__global__ void zero_gacc_k() {
    int i = blockIdx.x * 256 + threadIdx.x;
    if (i < CM) g_gacc[i] = 0.0f;
    if (i < 4 * CD) g_e2[i] = 0.0f;
}

// ---------------------------------------------------------------------------
// helpers
// ---------------------------------------------------------------------------
__device__ __forceinline__ uint32_t f2tf32(float x) {
    uint32_t r;
    asm("cvt.rna.tf32.f32 %0, %1;" : "=r"(r) : "f"(x));
    return r;
}

__device__ __forceinline__ void mma_tf32(float* d, const uint32_t* a, const uint32_t* b) {
    asm volatile(
        "mma.sync.aligned.m16n8k8.row.col.f32.tf32.tf32.f32 "
        "{%0,%1,%2,%3}, {%4,%5,%6,%7}, {%8,%9}, {%0,%1,%2,%3};\n"
        : "+f"(d[0]), "+f"(d[1]), "+f"(d[2]), "+f"(d[3])
        : "r"(a[0]), "r"(a[1]), "r"(a[2]), "r"(a[3]), "r"(b[0]), "r"(b[1]));
}

__device__ __forceinline__ void ldsm_x4(uint32_t* r, uint32_t saddr) {
    asm volatile("ldmatrix.sync.aligned.m8n8.x4.shared.b16 {%0,%1,%2,%3}, [%4];\n"
        : "=r"(r[0]), "=r"(r[1]), "=r"(r[2]), "=r"(r[3]) : "r"(saddr));
}

__device__ __forceinline__ void cp16(uint32_t dst, const void* src) {
    asm volatile("cp.async.cg.shared.global [%0], [%1], 16;\n" :: "r"(dst), "l"(src));
}
#define CP_COMMIT() asm volatile("cp.async.commit_group;\n")
#define CP_WAIT0()  asm volatile("cp.async.wait_group 0;\n")

// x -> tf32 bits (no transpose)
__global__ void cvt_x_k(const float* __restrict__ x, uint32_t* __restrict__ xt) {
    int i = blockIdx.x * 256 + threadIdx.x;
    float4 v = ((const float4*)x)[i];
    uint4 o = {f2tf32(v.x), f2tf32(v.y), f2tf32(v.z), f2tf32(v.w)};
    ((uint4*)xt)[i] = o;
}

// weights: cvt to tf32 bits AND transpose -> Wt[n][k]
__global__ void wtr_k(const float* __restrict__ w0, const float* __restrict__ w1,
                      const float* __restrict__ w2, const float* __restrict__ w3,
                      const float* __restrict__ w4,
                      uint32_t* __restrict__ o0, uint32_t* __restrict__ o1,
                      uint32_t* __restrict__ o2, uint32_t* __restrict__ o3,
                      uint32_t* __restrict__ o4)
{
    __shared__ uint32_t ts[32][33];
    const int z = blockIdx.z;
    const float* src = (z == 0) ? w0 : (z == 1) ? w1 : (z == 2) ? w2 : (z == 3) ? w3 : w4;
    uint32_t*    dst = (z == 0) ? o0 : (z == 1) ? o1 : (z == 2) ? o2 : (z == 3) ? o3 : o4;
    const int n0 = blockIdx.x * 32;
    const int k0 = blockIdx.y * 32;
    const int c  = threadIdx.x & 31;
    const int r8 = threadIdx.x >> 5;
#pragma unroll
    for (int i = 0; i < 4; i++) {
        int r = r8 + i * 8;
        ts[r][c] = f2tf32(src[(size_t)(k0 + r) * CD + n0 + c]);
    }
    __syncthreads();
#pragma unroll
    for (int i = 0; i < 4; i++) {
        int r = r8 + i * 8;
        dst[(size_t)(n0 + r) * CD + k0 + c] = ts[c][r];
    }
}

// ---------------------------------------------------------------------------
// fused QKV projection: z selects {Wq,Wk,Wv} (transposed). z<2 -> fused
// per-head RMSNorm (Q pre-scaled by ATT_SCALE). z==2 -> V stored transposed.
// ---------------------------------------------------------------------------
__global__ __launch_bounds__(256, 2) void gemm_qkv(
    const uint32_t* __restrict__ A,
    const uint32_t* __restrict__ Wq_, const uint32_t* __restrict__ Wk_,
    const uint32_t* __restrict__ Wv_,
    const float* __restrict__ bq_, const float* __restrict__ bk_,
    const float* __restrict__ bv_,
    const float* __restrict__ qw_, const float* __restrict__ kw_,
    float* __restrict__ oq_, float* __restrict__ ok_, float* __restrict__ ov_)
{
    extern __shared__ uint32_t sm[];
    const int z = blockIdx.z;
    const uint32_t* W   = (z == 0) ? Wq_ : (z == 1) ? Wk_ : Wv_;
    const float* bias   = (z == 0) ? bq_ : (z == 1) ? bk_ : bv_;
    const float* normw  = (z == 0) ? qw_ : kw_;
    float* C            = (z == 0) ? oq_ : (z == 1) ? ok_ : ov_;
    const float qsc     = (z == 0) ? ATT_SCALE : 1.0f;

    const int tid  = threadIdx.x;
    const int lane = tid & 31;
    const int warp = tid >> 5;
    const int wm   = warp >> 2;
    const int wn   = warp & 3;
    const int bm   = blockIdx.y * 128;
    const int bn   = blockIdx.x * 128;
    const int g    = lane >> 2;
    const int t    = lane & 3;
    const int lrow = lane & 7;
    const int lmat = lane >> 3;
    const uint32_t sb = (uint32_t)__cvta_generic_to_shared(sm);
    // ldmatrix lane-offsets (words)
    const int a_loff = ((lmat & 1) * 8 + lrow) * APAD + (lmat >> 1) * 4;
    const int b_loff = ((lmat >> 1) * 8 + lrow) * APAD + (lmat & 1) * 4;

    float acc[4][4][4];
#pragma unroll
    for (int i = 0; i < 4; i++)
#pragma unroll
        for (int j = 0; j < 4; j++)
#pragma unroll
            for (int r = 0; r < 4; r++) acc[i][j][r] = 0.0f;

    auto load_stage = [&](int kt, int st) {
        uint32_t as = sb + (uint32_t)(st * GA_STAGE) * 4u;
        uint32_t bs = as + GA_AW * 4u;
#pragma unroll
        for (int p = 0; p < 4; p++) {
            int idx = p * 256 + tid;
            int r = idx >> 3, c4 = (idx & 7) << 2;
            cp16(as + (uint32_t)(r * APAD + c4) * 4u,
                 A + (size_t)(bm + r) * CD + kt + c4);
            cp16(bs + (uint32_t)(r * APAD + c4) * 4u,
                 W + (size_t)(bn + r) * CD + kt + c4);
        }
        CP_COMMIT();
    };

    load_stage(0, 0);
    int st = 0;
    for (int it = 0; it < 32; it++) {
        CP_WAIT0();
        __syncthreads();
        if (it < 31) load_stage((it + 1) * 32, st ^ 1);
        const uint32_t as_b = sb + (uint32_t)(st * GA_STAGE) * 4u;
        const uint32_t bs_b = as_b + GA_AW * 4u;
#pragma unroll
        for (int ks = 0; ks < 4; ks++) {
            const int kc = ks * 8;
            uint32_t af[4][4], bq4[2][4];
#pragma unroll
            for (int mt = 0; mt < 4; mt++)
                ldsm_x4(af[mt], as_b + (uint32_t)((wm * 64 + mt * 16) * APAD + kc + a_loff) * 4u);
#pragma unroll
            for (int h2 = 0; h2 < 2; h2++)
                ldsm_x4(bq4[h2], bs_b + (uint32_t)((wn * 32 + h2 * 16) * APAD + kc + b_loff) * 4u);
#pragma unroll
            for (int mt = 0; mt < 4; mt++)
#pragma unroll
                for (int nt = 0; nt < 4; nt++)
                    mma_tf32(acc[mt][nt], af[mt], &bq4[nt >> 1][(nt & 1) * 2]);
        }
        st ^= 1;
    }
    __syncthreads();

    float2 bb[4];
#pragma unroll
    for (int nt = 0; nt < 4; nt++)
        bb[nt] = *(const float2*)(bias + bn + wn * 32 + nt * 8 + t * 2);

    uint32_t* Cu = (uint32_t*)C;
    if (z < 2) {
        float ssA[4], ssB[4];
#pragma unroll
        for (int mt = 0; mt < 4; mt++) {
            float s0 = 0.0f, s1 = 0.0f;
#pragma unroll
            for (int nt = 0; nt < 4; nt++) {
                float v0 = acc[mt][nt][0] + bb[nt].x;
                float v1 = acc[mt][nt][1] + bb[nt].y;
                float v2 = acc[mt][nt][2] + bb[nt].x;
                float v3 = acc[mt][nt][3] + bb[nt].y;
                s0 = fmaf(v0, v0, s0); s0 = fmaf(v1, v1, s0);
                s1 = fmaf(v2, v2, s1); s1 = fmaf(v3, v3, s1);
            }
            s0 += __shfl_xor_sync(0xffffffffu, s0, 1);
            s0 += __shfl_xor_sync(0xffffffffu, s0, 2);
            s1 += __shfl_xor_sync(0xffffffffu, s1, 1);
            s1 += __shfl_xor_sync(0xffffffffu, s1, 2);
            ssA[mt] = s0; ssB[mt] = s1;
        }
        float* S = (float*)sm;
        if (t == 0) {
#pragma unroll
            for (int mt = 0; mt < 4; mt++) {
                int r0 = wm * 64 + mt * 16 + g;
                S[r0 * 4 + wn]       = ssA[mt];
                S[(r0 + 8) * 4 + wn] = ssB[mt];
            }
        }
        __syncthreads();
        const int pi = wn & ~1;
#pragma unroll
        for (int mt = 0; mt < 4; mt++) {
            int r0 = wm * 64 + mt * 16 + g;
            float sc0 = rsqrtf((S[r0 * 4 + pi] + S[r0 * 4 + pi + 1]) * (1.0f / 64.0f) + 1e-6f) * qsc;
            float sc1 = rsqrtf((S[(r0 + 8) * 4 + pi] + S[(r0 + 8) * 4 + pi + 1]) * (1.0f / 64.0f) + 1e-6f) * qsc;
#pragma unroll
            for (int nt = 0; nt < 4; nt++) {
                int cl = wn * 32 + nt * 8 + t * 2;
                float2 ww = *(const float2*)(normw + (cl & 63));
                float v0 = acc[mt][nt][0] + bb[nt].x;
                float v1 = acc[mt][nt][1] + bb[nt].y;
                float v2 = acc[mt][nt][2] + bb[nt].x;
                float v3 = acc[mt][nt][3] + bb[nt].y;
                uint2 o0 = {f2tf32(v0 * sc0 * ww.x), f2tf32(v1 * sc0 * ww.y)};
                uint2 o1 = {f2tf32(v2 * sc1 * ww.x), f2tf32(v3 * sc1 * ww.y)};
                *(uint2*)(Cu + (size_t)(bm + r0) * CD + bn + cl)     = o0;
                *(uint2*)(Cu + (size_t)(bm + r0 + 8) * CD + bn + cl) = o1;
            }
        }
    } else {
        // V: store TRANSPOSED tf32 bits: vt[((b*16+h)*64+hd)*512 + n]
#pragma unroll
        for (int mt = 0; mt < 4; mt++) {
            int m0 = bm + wm * 64 + mt * 16 + g;
#pragma unroll
            for (int nt = 0; nt < 4; nt++) {
                int d0 = bn + wn * 32 + nt * 8 + t * 2;
                float v00 = acc[mt][nt][0] + bb[nt].x;
                float v01 = acc[mt][nt][1] + bb[nt].y;
                float v10 = acc[mt][nt][2] + bb[nt].x;
                float v11 = acc[mt][nt][3] + bb[nt].y;
                size_t ib = ((size_t)((m0 >> 9) * CH + (d0 >> 6)) * CHD + (d0 & 63)) * CN
                          + (m0 & 511);
                Cu[ib]            = f2tf32(v00);
                Cu[ib + CN]       = f2tf32(v01);
                Cu[ib + 8]        = f2tf32(v10);
                Cu[ib + CN + 8]   = f2tf32(v11);
            }
        }
    }
}

// ---------------------------------------------------------------------------
// async tf32 GEMM (W transposed [n][k]); MODE 0: tf32 bits; MODE 2: gated f32
// ---------------------------------------------------------------------------
template <int MODE>
__global__ __launch_bounds__(256, 2) void gemm_a(
    const uint32_t* __restrict__ A, const uint32_t* __restrict__ W,
    const float* __restrict__ bias, float* __restrict__ C)
{
    extern __shared__ uint32_t sm[];
    const int tid  = threadIdx.x;
    const int lane = tid & 31;
    const int warp = tid >> 5;
    const int wm   = warp >> 2;
    const int wn   = warp & 3;
    const int bm   = blockIdx.y * 128;
    const int bn   = blockIdx.x * 128;
    const int g    = lane >> 2;
    const int t    = lane & 3;
    const int lrow = lane & 7;
    const int lmat = lane >> 3;
    const uint32_t sb = (uint32_t)__cvta_generic_to_shared(sm);
    const int a_loff = ((lmat & 1) * 8 + lrow) * APAD + (lmat >> 1) * 4;
    const int b_loff = ((lmat >> 1) * 8 + lrow) * APAD + (lmat & 1) * 4;

    float acc[4][4][4];
#pragma unroll
    for (int i = 0; i < 4; i++)
#pragma unroll
        for (int j = 0; j < 4; j++)
#pragma unroll
            for (int r = 0; r < 4; r++) acc[i][j][r] = 0.0f;

    auto load_stage = [&](int kt, int st) {
        uint32_t as = sb + (uint32_t)(st * GA_STAGE) * 4u;
        uint32_t bs = as + GA_AW * 4u;
#pragma unroll
        for (int p = 0; p < 4; p++) {
            int idx = p * 256 + tid;
            int r = idx >> 3, c4 = (idx & 7) << 2;
            cp16(as + (uint32_t)(r * APAD + c4) * 4u,
                 A + (size_t)(bm + r) * CD + kt + c4);
            cp16(bs + (uint32_t)(r * APAD + c4) * 4u,
                 W + (size_t)(bn + r) * CD + kt + c4);
        }
        CP_COMMIT();
    };

    load_stage(0, 0);
    int st = 0;
    for (int it = 0; it < 32; it++) {
        CP_WAIT0();
        __syncthreads();
        if (it < 31) load_stage((it + 1) * 32, st ^ 1);
        const uint32_t as_b = sb + (uint32_t)(st * GA_STAGE) * 4u;
        const uint32_t bs_b = as_b + GA_AW * 4u;
#pragma unroll
        for (int ks = 0; ks < 4; ks++) {
            const int kc = ks * 8;
            uint32_t af[4][4], bq4[2][4];
#pragma unroll
            for (int mt = 0; mt < 4; mt++)
                ldsm_x4(af[mt], as_b + (uint32_t)((wm * 64 + mt * 16) * APAD + kc + a_loff) * 4u);
#pragma unroll
            for (int h2 = 0; h2 < 2; h2++)
                ldsm_x4(bq4[h2], bs_b + (uint32_t)((wn * 32 + h2 * 16) * APAD + kc + b_loff) * 4u);
#pragma unroll
            for (int mt = 0; mt < 4; mt++)
#pragma unroll
                for (int nt = 0; nt < 4; nt++)
                    mma_tf32(acc[mt][nt], af[mt], &bq4[nt >> 1][(nt & 1) * 2]);
        }
        st ^= 1;
    }

    float2 bb[4];
#pragma unroll
    for (int nt = 0; nt < 4; nt++)
        bb[nt] = *(const float2*)(bias + bn + wn * 32 + nt * 8 + t * 2);

    if (MODE == 2) {
#pragma unroll
        for (int mt = 0; mt < 4; mt++) {
            int r0 = bm + wm * 64 + mt * 16 + g;
            float ga0 = 1.0f + g_gacc[r0]     * (1.0f / 512.0f);
            float ga1 = 1.0f + g_gacc[r0 + 8] * (1.0f / 512.0f);
#pragma unroll
            for (int nt = 0; nt < 4; nt++) {
                int col = bn + wn * 32 + nt * 8 + t * 2;
                float2 w0 = {acc[mt][nt][0] * ga0 + bb[nt].x, acc[mt][nt][1] * ga0 + bb[nt].y};
                float2 w1 = {acc[mt][nt][2] * ga1 + bb[nt].x, acc[mt][nt][3] * ga1 + bb[nt].y};
                *(float2*)(C + (size_t)r0 * CD + col)       = w0;
                *(float2*)(C + (size_t)(r0 + 8) * CD + col) = w1;
            }
        }
    } else {
        uint32_t* Cu = (uint32_t*)C;
#pragma unroll
        for (int mt = 0; mt < 4; mt++) {
            int r0 = bm + wm * 64 + mt * 16 + g;
#pragma unroll
            for (int nt = 0; nt < 4; nt++) {
                int col = bn + wn * 32 + nt * 8 + t * 2;
                uint2 o0 = {f2tf32(acc[mt][nt][0] + bb[nt].x), f2tf32(acc[mt][nt][1] + bb[nt].y)};
                uint2 o1 = {f2tf32(acc[mt][nt][2] + bb[nt].x), f2tf32(acc[mt][nt][3] + bb[nt].y)};
                *(uint2*)(Cu + (size_t)r0 * CD + col)       = o0;
                *(uint2*)(Cu + (size_t)(r0 + 8) * CD + col) = o1;
            }
        }
    }
}

// ---------------------------------------------------------------------------
// instance gate: both operands n-major [row][k] -> ldmatrix for A and B
// ---------------------------------------------------------------------------
__global__ __launch_bounds__(256, 2) void instgate_t(
    const uint32_t* __restrict__ iq, const uint32_t* __restrict__ ikp)
{
    extern __shared__ uint32_t sm[];
    const int tid  = threadIdx.x;
    const int lane = tid & 31;
    const int warp = tid >> 5;
    const int wm   = warp >> 2;
    const int wn   = warp & 3;
    const int b    = blockIdx.z;
    const int bm   = blockIdx.y * 128;
    const int bn   = blockIdx.x * 128;
    const int g    = lane >> 2;
    const int t    = lane & 3;
    const int lrow = lane & 7;
    const int lmat = lane >> 3;
    const uint32_t* Ab = iq  + (size_t)b * 512 * CD;
    const uint32_t* Bb = ikp + (size_t)b * 512 * CD;
    const uint32_t sb = (uint32_t)__cvta_generic_to_shared(sm);
    const int a_loff = ((lmat & 1) * 8 + lrow) * APAD + (lmat >> 1) * 4;
    const int b_loff = ((lmat >> 1) * 8 + lrow) * APAD + (lmat & 1) * 4;

    float acc[4][4][4];
#pragma unroll
    for (int i = 0; i < 4; i++)
#pragma unroll
        for (int j = 0; j < 4; j++)
#pragma unroll
            for (int r = 0; r < 4; r++) acc[i][j][r] = 0.0f;

    auto load_stage = [&](int kt, int st) {
        uint32_t as = sb + (uint32_t)(st * GA_STAGE) * 4u;
        uint32_t bs = as + GA_AW * 4u;
#pragma unroll
        for (int p = 0; p < 4; p++) {
            int idx = p * 256 + tid;
            int r = idx >> 3, c4 = (idx & 7) << 2;
            cp16(as + (uint32_t)(r * APAD + c4) * 4u, Ab + (size_t)(bm + r) * CD + kt + c4);
            cp16(bs + (uint32_t)(r * APAD + c4) * 4u, Bb + (size_t)(bn + r) * CD + kt + c4);
        }
        CP_COMMIT();
    };

    load_stage(0, 0);
    int st = 0;
    for (int it = 0; it < 32; it++) {
        CP_WAIT0();
        __syncthreads();
        if (it < 31) load_stage((it + 1) * 32, st ^ 1);
        const uint32_t as_b = sb + (uint32_t)(st * GA_STAGE) * 4u;
        const uint32_t bs_b = as_b + GA_AW * 4u;
#pragma unroll
        for (int ks = 0; ks < 4; ks++) {
            const int kc = ks * 8;
            uint32_t af[4][4], bq4[2][4];
#pragma unroll
            for (int mt = 0; mt < 4; mt++)
                ldsm_x4(af[mt], as_b + (uint32_t)((wm * 64 + mt * 16) * APAD + kc + a_loff) * 4u);
#pragma unroll
            for (int h2 = 0; h2 < 2; h2++)
                ldsm_x4(bq4[h2], bs_b + (uint32_t)((wn * 32 + h2 * 16) * APAD + kc + b_loff) * 4u);
#pragma unroll
            for (int mt = 0; mt < 4; mt++)
#pragma unroll
                for (int nt = 0; nt < 4; nt++)
                    mma_tf32(acc[mt][nt], af[mt], &bq4[nt >> 1][(nt & 1) * 2]);
        }
        st ^= 1;
    }

#pragma unroll
    for (int mt = 0; mt < 4; mt++) {
        float s0 = 0.0f, s1 = 0.0f;
#pragma unroll
        for (int nt = 0; nt < 4; nt++) {
            s0 += 1.0f / (1.0f + __expf(-acc[mt][nt][0] * INST_SCALE));
            s0 += 1.0f / (1.0f + __expf(-acc[mt][nt][1] * INST_SCALE));
            s1 += 1.0f / (1.0f + __expf(-acc[mt][nt][2] * INST_SCALE));
            s1 += 1.0f / (1.0f + __expf(-acc[mt][nt][3] * INST_SCALE));
        }
        s0 += __shfl_xor_sync(0xffffffffu, s0, 1);
        s0 += __shfl_xor_sync(0xffffffffu, s0, 2);
        s1 += __shfl_xor_sync(0xffffffffu, s1, 1);
        s1 += __shfl_xor_sync(0xffffffffu, s1, 2);
        if (t == 0) {
            int row = bm + wm * 64 + mt * 16 + g;
            atomicAdd(&g_gacc[b * 512 + row], s0);
            atomicAdd(&g_gacc[b * 512 + row + 8], s1);
        }
    }
}

// ---------------------------------------------------------------------------
// tf32 flash attention: fixed-bound softmax + ldmatrix fragments (R8-validated)
// ---------------------------------------------------------------------------
__global__ __launch_bounds__(256, 2) void attn_t(
    const uint32_t* __restrict__ q, const uint32_t* __restrict__ k,
    const uint32_t* __restrict__ vt, float* __restrict__ o)
{
    extern __shared__ uint32_t sm[];

    const int tid  = threadIdx.x;
    const int lane = tid & 31;
    const int warp = tid >> 5;
    const int g    = lane >> 2;
    const int t    = lane & 3;
    const int bq   = blockIdx.y;
    const int h    = blockIdx.z;
    const int n0   = blockIdx.x * 128;
    const int gb   = bq & ~3;
    const int qrow = n0 + warp * 16;
    const uint32_t sb = (uint32_t)__cvta_generic_to_shared(sm);

    uint32_t qf[8][4];
    {
        const uint32_t* qb = q + ((size_t)(bq * CN + qrow)) * CD + h * CHD;
#pragma unroll
        for (int ks = 0; ks < 8; ks++) {
            int c = ks * 8 + t;
            qf[ks][0] = qb[(size_t)g * CD + c];
            qf[ks][1] = qb[(size_t)(g + 8) * CD + c];
            qf[ks][2] = qb[(size_t)g * CD + c + 4];
            qf[ks][3] = qb[(size_t)(g + 8) * CD + c + 4];
        }
    }

    float oa[8][4];
#pragma unroll
    for (int nt = 0; nt < 8; nt++)
#pragma unroll
        for (int r = 0; r < 4; r++) oa[nt][r] = 0.0f;
    float li0 = 0.0f, li1 = 0.0f;

    uint32_t* Pw = sm + 2 * AT_STAGE + warp * 16 * PPAD;
    const uint32_t pw_sb = sb + (uint32_t)(2 * AT_STAGE + warp * 16 * PPAD) * 4u;
    const int lrow = lane & 7;
    const int lmat = lane >> 3;
    const uint32_t kv_off = (uint32_t)(lrow * KPAD + lmat * 4) * 4u;
    const uint32_t p_off = (uint32_t)(((lmat & 1) * 8 + lrow) * PPAD + (lmat >> 1) * 4) * 4u;

    auto load_kv = [&](int kc, int stg) {
        const int m0 = kc * 64;
        const int kb = gb + (m0 >> 9);
        const int kn = m0 & 511;
        uint32_t ksm = sb + (uint32_t)(stg * AT_STAGE) * 4u;
        uint32_t vsm = ksm + AT_KV * 4u;
#pragma unroll
        for (int p = 0; p < 4; p++) {
            int idx = p * 256 + tid;
            int r   = idx >> 4;
            int c4  = (idx & 15) << 2;
            uint32_t off = (uint32_t)(r * KPAD + c4) * 4u;
            cp16(ksm + off, k + ((size_t)(kb * CN + kn + r)) * CD + h * CHD + c4);
            cp16(vsm + off, vt + ((size_t)((kb * CH + h) * CHD + r)) * CN + kn + c4);
        }
        CP_COMMIT();
    };

    load_kv(0, 0);
    int st = 0;

    for (int kc = 0; kc < 32; kc++) {
        CP_WAIT0();
        __syncthreads();
        if (kc < 31) load_kv(kc + 1, st ^ 1);

        const uint32_t ks_sb = sb + (uint32_t)(st * AT_STAGE) * 4u;
        const uint32_t vs_sb = ks_sb + AT_KV * 4u;

        float sacc[8][4];
#pragma unroll
        for (int nt = 0; nt < 8; nt++)
#pragma unroll
            for (int r = 0; r < 4; r++) sacc[nt][r] = 0.0f;
#pragma unroll
        for (int nt = 0; nt < 8; nt++) {
            uint32_t rowa = ks_sb + (uint32_t)(nt * 8 * KPAD) * 4u + kv_off;
#pragma unroll
            for (int kp = 0; kp < 4; kp++) {
                uint32_t kb4[4];
                ldsm_x4(kb4, rowa + (uint32_t)(kp * 16) * 4u);
                mma_tf32(sacc[nt], qf[2 * kp],     kb4);
                mma_tf32(sacc[nt], qf[2 * kp + 1], kb4 + 2);
            }
        }

#pragma unroll
        for (int nt = 0; nt < 8; nt++) {
            float p0 = __expf(sacc[nt][0] - SOFT_SHIFT);
            float p1 = __expf(sacc[nt][1] - SOFT_SHIFT);
            float p2 = __expf(sacc[nt][2] - SOFT_SHIFT);
            float p3 = __expf(sacc[nt][3] - SOFT_SHIFT);
            li0 += p0 + p1;
            li1 += p2 + p3;
            int col = nt * 8 + 2 * t;
            uint2 w0 = {f2tf32(p0), f2tf32(p1)};
            uint2 w1 = {f2tf32(p2), f2tf32(p3)};
            *(uint2*)&Pw[g * PPAD + col]       = w0;
            *(uint2*)&Pw[(g + 8) * PPAD + col] = w1;
        }
        __syncwarp();

        uint32_t pf[8][4];
#pragma unroll
        for (int ks = 0; ks < 8; ks++)
            ldsm_x4(pf[ks], pw_sb + p_off + (uint32_t)(ks * 8) * 4u);

#pragma unroll
        for (int nt = 0; nt < 8; nt++) {
            uint32_t rowv = vs_sb + (uint32_t)(nt * 8 * KPAD) * 4u + kv_off;
#pragma unroll
            for (int kp = 0; kp < 4; kp++) {
                uint32_t vb4[4];
                ldsm_x4(vb4, rowv + (uint32_t)(kp * 16) * 4u);
                mma_tf32(oa[nt], pf[2 * kp],     vb4);
                mma_tf32(oa[nt], pf[2 * kp + 1], vb4 + 2);
            }
        }
        __syncwarp();
        st ^= 1;
    }

    li0 += __shfl_xor_sync(0xffffffffu, li0, 1);
    li0 += __shfl_xor_sync(0xffffffffu, li0, 2);
    li1 += __shfl_xor_sync(0xffffffffu, li1, 1);
    li1 += __shfl_xor_sync(0xffffffffu, li1, 2);
    float inv0 = 1.0f / li0, inv1 = 1.0f / li1;
    uint32_t* ob = (uint32_t*)(o + ((size_t)(bq * CN + qrow)) * CD + h * CHD);
#pragma unroll
    for (int nt = 0; nt < 8; nt++) {
        int col = nt * 8 + 2 * t;
        uint2 r0 = {f2tf32(oa[nt][0] * inv0), f2tf32(oa[nt][1] * inv0)};
        uint2 r1 = {f2tf32(oa[nt][2] * inv1), f2tf32(oa[nt][3] * inv1)};
        *(uint2*)(ob + (size_t)g * CD + col)       = r0;
        *(uint2*)(ob + (size_t)(g + 8) * CD + col) = r1;
    }
}

// ---------------------------------------------------------------------------
// E2 = emb[:4] @ Wik, k-split 8 ways with atomic accumulation.
// idx = kchunk*4096 + out  (out fastest -> coalesced Wik reads)
// g_e2 zeroed by zero_gacc_k.
// ---------------------------------------------------------------------------
__global__ void e2_k(const float* __restrict__ emb, const float* __restrict__ Wik) {
    int idx = blockIdx.x * 256 + threadIdx.x;   // 0..32767
    int out = idx & 4095;                        // 0..4095
    int kc  = idx >> 12;                         // 0..7
    int i = out >> 10;
    int c = out & 1023;
    const float* ep = emb + i * 1024 + kc * 128;
    const float* wp = Wik + (size_t)(kc * 128) * 1024 + c;
    float acc = 0.0f;
#pragma unroll 4
    for (int kk = 0; kk < 128; kk++)
        acc = fmaf(ep[kk], wp[(size_t)kk * 1024], acc);
    atomicAdd(&g_e2[out], acc);
}

__global__ void ikb_k(const float* __restrict__ mask, const float* __restrict__ bik,
                      uint32_t* __restrict__ ik) {
    int idx = blockIdx.x * 256 + threadIdx.x;
    int d  = idx & 1023;
    int bn = idx >> 10;
    const float* mp = mask + (size_t)bn * 4;
    float acc = bik[d];
    acc = fmaf(mp[0], g_e2[d],        acc);
    acc = fmaf(mp[1], g_e2[1024 + d], acc);
    acc = fmaf(mp[2], g_e2[2048 + d], acc);
    acc = fmaf(mp[3], g_e2[3072 + d], acc);
    ik[idx] = f2tf32(acc);
}

// ---------------------------------------------------------------------------
// launch
// ---------------------------------------------------------------------------
extern "C" void kernel_launch(void* const* d_in, const int* in_sizes, int n_in,
                              void* d_out, int out_size)
{
    (void)in_sizes; (void)n_in; (void)out_size;
    const float* x    = (const float*)d_in[0];
    const float* mask = (const float*)d_in[1];
    const float* Wq   = (const float*)d_in[2];
    const float* bq   = (const float*)d_in[3];
    const float* Wk   = (const float*)d_in[4];
    const float* bk   = (const float*)d_in[5];
    const float* Wv   = (const float*)d_in[6];
    const float* bv   = (const float*)d_in[7];
    const float* Wo   = (const float*)d_in[8];
    const float* bo   = (const float*)d_in[9];
    const float* Wiq  = (const float*)d_in[10];
    const float* biq  = (const float*)d_in[11];
    const float* Wik  = (const float*)d_in[12];
    const float* bik  = (const float*)d_in[13];
    const float* emb  = (const float*)d_in[14];
    const float* qw   = (const float*)d_in[15];
    const float* kw   = (const float*)d_in[16];
    float* out = (float*)d_out;

    float *qp, *kp, *vtp, *op, *iqp;
    uint32_t *xt, *wq, *wk, *wv, *wiq, *wo, *ikp;
    cudaGetSymbolAddress((void**)&qp,  g_q);
    cudaGetSymbolAddress((void**)&kp,  g_k);
    cudaGetSymbolAddress((void**)&vtp, g_vt);
    cudaGetSymbolAddress((void**)&op,  g_o);
    cudaGetSymbolAddress((void**)&iqp, g_iq);
    cudaGetSymbolAddress((void**)&ikp, g_ik);
    cudaGetSymbolAddress((void**)&xt,  g_xt);
    cudaGetSymbolAddress((void**)&wq,  g_wq);
    cudaGetSymbolAddress((void**)&wk,  g_wk);
    cudaGetSymbolAddress((void**)&wv,  g_wv);
    cudaGetSymbolAddress((void**)&wiq, g_wiq);
    cudaGetSymbolAddress((void**)&wo,  g_wo);

    static bool attr_done = false;
    if (!attr_done) {
        cudaFuncSetAttribute(gemm_qkv, cudaFuncAttributeMaxDynamicSharedMemorySize, SMEM_GEMM);
        cudaFuncSetAttribute(gemm_a<0>, cudaFuncAttributeMaxDynamicSharedMemorySize, SMEM_GEMM);
        cudaFuncSetAttribute(gemm_a<2>, cudaFuncAttributeMaxDynamicSharedMemorySize, SMEM_GEMM);
        cudaFuncSetAttribute(instgate_t, cudaFuncAttributeMaxDynamicSharedMemorySize, SMEM_GEMM);
        cudaFuncSetAttribute(attn_t, cudaFuncAttributeMaxDynamicSharedMemorySize, SMEM_ATTN);
        attr_done = true;
    }

    dim3 gemm_grid(8, 32);

    zero_gacc_k<<<16, 256>>>();

    cvt_x_k<<<4096, 256>>>(x, xt);
    wtr_k<<<dim3(32, 32, 5), 256>>>(Wq, Wk, Wv, Wiq, Wo, wq, wk, wv, wiq, wo);

    // e2/ikb only need inputs + zeroed g_e2; run early, off the critical tail
    e2_k<<<128, 256>>>(emb, Wik);
    ikb_k<<<16384, 256>>>(mask, bik, ikp);

    gemm_qkv<<<dim3(8, 32, 3), 256, SMEM_GEMM>>>(xt, wq, wk, wv, bq, bk, bv,
                                                 qw, kw, qp, kp, vtp);

    attn_t<<<dim3(4, 8, 16), 256, SMEM_ATTN>>>((const uint32_t*)qp, (const uint32_t*)kp,
                                               (const uint32_t*)vtp, op);

    gemm_a<0><<<gemm_grid, 256, SMEM_GEMM>>>((const uint32_t*)op, wiq, biq, iqp);

    instgate_t<<<dim3(4, 4, 8), 256, SMEM_GEMM>>>((const uint32_t*)iqp, ikp);

    gemm_a<2><<<gemm_grid, 256, SMEM_GEMM>>>((const uint32_t*)op, wo, bo, out);
}

// round 13
// speedup vs baseline: 3.7014x; 1.0033x over previous
#include <cuda_runtime.h>
#include <cstdint>
#include <cstddef>

// ---------------------------------------------------------------------------
// MIDIMultiInstanceAttention  (B=8, N=512, D=1024, H=16, HD=64, NI=4)
// tf32 tensor cores everywhere; ldmatrix fragment loads in ALL mma kernels;
// fixed-bound softmax; transposed weights; parallel k-split e2
// ---------------------------------------------------------------------------

#define CB 8
#define CN 512
#define CD 1024
#define CH 16
#define CHD 64
#define CM 4096
#define ATT_SCALE 0.125f
#define SOFT_SHIFT 8.0f
#define INST_SCALE (0.125f / 16.0f)

#define APAD 36
#define KPAD 68
#define PPAD 68

#define GA_AW (128 * APAD)                 // 4608 words
#define GA_STAGE (2 * GA_AW)               // A + B(t), 9216 words
#define SMEM_GEMM (2 * GA_STAGE * 4)       // 73728 B

#define AT_KV (64 * KPAD)                  // 4352 words
#define AT_STAGE (2 * AT_KV)               // K + Vt
#define SMEM_ATTN ((2 * AT_STAGE + 8 * 16 * PPAD) * 4)   // 104448 B

// scratch (device globals: allocation-free rule)
__device__ __align__(16) uint32_t g_xt[CM * CD];
__device__ __align__(16) uint32_t g_wq[CD * CD];    // transposed tf32 [n][k]
__device__ __align__(16) uint32_t g_wk[CD * CD];
__device__ __align__(16) uint32_t g_wv[CD * CD];
__device__ __align__(16) uint32_t g_wiq[CD * CD];
__device__ __align__(16) uint32_t g_wo[CD * CD];
__device__ __align__(16) float g_q [CM * CD];       // tf32 bits (pre-scaled)
__device__ __align__(16) float g_k [CM * CD];       // tf32 bits
__device__ __align__(16) float g_vt[CM * CD];       // tf32 bits, [b,h][d][n]
__device__ __align__(16) float g_o [CM * CD];       // tf32 bits
__device__ __align__(16) float g_iq[CM * CD];       // tf32 bits
__device__ __align__(16) uint32_t g_ik[CM * CD];    // tf32 bits
__device__ __align__(16) float g_e2[4 * CD];
__device__ float g_gacc[CM];

// zero gacc AND e2 partial-sum buffer (both 4096 floats)
__global__ void zero_gacc_k() {
    int i = blockIdx.x * 256 + threadIdx.x;
    if (i < CM) g_gacc[i] = 0.0f;
    if (i < 4 * CD) g_e2[i] = 0.0f;
}

// ---------------------------------------------------------------------------
// helpers
// ---------------------------------------------------------------------------
__device__ __forceinline__ uint32_t f2tf32(float x) {
    uint32_t r;
    asm("cvt.rna.tf32.f32 %0, %1;" : "=r"(r) : "f"(x));
    return r;
}

__device__ __forceinline__ void mma_tf32(float* d, const uint32_t* a, const uint32_t* b) {
    asm volatile(
        "mma.sync.aligned.m16n8k8.row.col.f32.tf32.tf32.f32 "
        "{%0,%1,%2,%3}, {%4,%5,%6,%7}, {%8,%9}, {%0,%1,%2,%3};\n"
        : "+f"(d[0]), "+f"(d[1]), "+f"(d[2]), "+f"(d[3])
        : "r"(a[0]), "r"(a[1]), "r"(a[2]), "r"(a[3]), "r"(b[0]), "r"(b[1]));
}

__device__ __forceinline__ void ldsm_x4(uint32_t* r, uint32_t saddr) {
    asm volatile("ldmatrix.sync.aligned.m8n8.x4.shared.b16 {%0,%1,%2,%3}, [%4];\n"
        : "=r"(r[0]), "=r"(r[1]), "=r"(r[2]), "=r"(r[3]) : "r"(saddr));
}

__device__ __forceinline__ void cp16(uint32_t dst, const void* src) {
    asm volatile("cp.async.cg.shared.global [%0], [%1], 16;\n" :: "r"(dst), "l"(src));
}
#define CP_COMMIT() asm volatile("cp.async.commit_group;\n")
#define CP_WAIT0()  asm volatile("cp.async.wait_group 0;\n")

// x -> tf32 bits (no transpose)
__global__ void cvt_x_k(const float* __restrict__ x, uint32_t* __restrict__ xt) {
    int i = blockIdx.x * 256 + threadIdx.x;
    float4 v = ((const float4*)x)[i];
    uint4 o = {f2tf32(v.x), f2tf32(v.y), f2tf32(v.z), f2tf32(v.w)};
    ((uint4*)xt)[i] = o;
}

// weights: cvt to tf32 bits AND transpose -> Wt[n][k]
__global__ void wtr_k(const float* __restrict__ w0, const float* __restrict__ w1,
                      const float* __restrict__ w2, const float* __restrict__ w3,
                      const float* __restrict__ w4,
                      uint32_t* __restrict__ o0, uint32_t* __restrict__ o1,
                      uint32_t* __restrict__ o2, uint32_t* __restrict__ o3,
                      uint32_t* __restrict__ o4)
{
    __shared__ uint32_t ts[32][33];
    const int z = blockIdx.z;
    const float* src = (z == 0) ? w0 : (z == 1) ? w1 : (z == 2) ? w2 : (z == 3) ? w3 : w4;
    uint32_t*    dst = (z == 0) ? o0 : (z == 1) ? o1 : (z == 2) ? o2 : (z == 3) ? o3 : o4;
    const int n0 = blockIdx.x * 32;
    const int k0 = blockIdx.y * 32;
    const int c  = threadIdx.x & 31;
    const int r8 = threadIdx.x >> 5;
#pragma unroll
    for (int i = 0; i < 4; i++) {
        int r = r8 + i * 8;
        ts[r][c] = f2tf32(src[(size_t)(k0 + r) * CD + n0 + c]);
    }
    __syncthreads();
#pragma unroll
    for (int i = 0; i < 4; i++) {
        int r = r8 + i * 8;
        dst[(size_t)(n0 + r) * CD + k0 + c] = ts[c][r];
    }
}

// ---------------------------------------------------------------------------
// fused QKV projection: z selects {Wq,Wk,Wv} (transposed). z<2 -> fused
// per-head RMSNorm (Q pre-scaled by ATT_SCALE). z==2 -> V stored transposed.
// ---------------------------------------------------------------------------
__global__ __launch_bounds__(256, 2) void gemm_qkv(
    const uint32_t* __restrict__ A,
    const uint32_t* __restrict__ Wq_, const uint32_t* __restrict__ Wk_,
    const uint32_t* __restrict__ Wv_,
    const float* __restrict__ bq_, const float* __restrict__ bk_,
    const float* __restrict__ bv_,
    const float* __restrict__ qw_, const float* __restrict__ kw_,
    float* __restrict__ oq_, float* __restrict__ ok_, float* __restrict__ ov_)
{
    extern __shared__ uint32_t sm[];
    const int z = blockIdx.z;
    const uint32_t* W   = (z == 0) ? Wq_ : (z == 1) ? Wk_ : Wv_;
    const float* bias   = (z == 0) ? bq_ : (z == 1) ? bk_ : bv_;
    const float* normw  = (z == 0) ? qw_ : kw_;
    float* C            = (z == 0) ? oq_ : (z == 1) ? ok_ : ov_;
    const float qsc     = (z == 0) ? ATT_SCALE : 1.0f;

    const int tid  = threadIdx.x;
    const int lane = tid & 31;
    const int warp = tid >> 5;
    const int wm   = warp >> 2;
    const int wn   = warp & 3;
    const int bm   = blockIdx.y * 128;
    const int bn   = blockIdx.x * 128;
    const int g    = lane >> 2;
    const int t    = lane & 3;
    const int lrow = lane & 7;
    const int lmat = lane >> 3;
    const uint32_t sb = (uint32_t)__cvta_generic_to_shared(sm);
    // ldmatrix lane-offsets (words)
    const int a_loff = ((lmat & 1) * 8 + lrow) * APAD + (lmat >> 1) * 4;
    const int b_loff = ((lmat >> 1) * 8 + lrow) * APAD + (lmat & 1) * 4;

    float acc[4][4][4];
#pragma unroll
    for (int i = 0; i < 4; i++)
#pragma unroll
        for (int j = 0; j < 4; j++)
#pragma unroll
            for (int r = 0; r < 4; r++) acc[i][j][r] = 0.0f;

    auto load_stage = [&](int kt, int st) {
        uint32_t as = sb + (uint32_t)(st * GA_STAGE) * 4u;
        uint32_t bs = as + GA_AW * 4u;
#pragma unroll
        for (int p = 0; p < 4; p++) {
            int idx = p * 256 + tid;
            int r = idx >> 3, c4 = (idx & 7) << 2;
            cp16(as + (uint32_t)(r * APAD + c4) * 4u,
                 A + (size_t)(bm + r) * CD + kt + c4);
            cp16(bs + (uint32_t)(r * APAD + c4) * 4u,
                 W + (size_t)(bn + r) * CD + kt + c4);
        }
        CP_COMMIT();
    };

    load_stage(0, 0);
    int st = 0;
    for (int it = 0; it < 32; it++) {
        CP_WAIT0();
        __syncthreads();
        if (it < 31) load_stage((it + 1) * 32, st ^ 1);
        const uint32_t as_b = sb + (uint32_t)(st * GA_STAGE) * 4u;
        const uint32_t bs_b = as_b + GA_AW * 4u;
#pragma unroll
        for (int ks = 0; ks < 4; ks++) {
            const int kc = ks * 8;
            uint32_t af[4][4], bq4[2][4];
#pragma unroll
            for (int mt = 0; mt < 4; mt++)
                ldsm_x4(af[mt], as_b + (uint32_t)((wm * 64 + mt * 16) * APAD + kc + a_loff) * 4u);
#pragma unroll
            for (int h2 = 0; h2 < 2; h2++)
                ldsm_x4(bq4[h2], bs_b + (uint32_t)((wn * 32 + h2 * 16) * APAD + kc + b_loff) * 4u);
#pragma unroll
            for (int mt = 0; mt < 4; mt++)
#pragma unroll
                for (int nt = 0; nt < 4; nt++)
                    mma_tf32(acc[mt][nt], af[mt], &bq4[nt >> 1][(nt & 1) * 2]);
        }
        st ^= 1;
    }
    __syncthreads();

    float2 bb[4];
#pragma unroll
    for (int nt = 0; nt < 4; nt++)
        bb[nt] = *(const float2*)(bias + bn + wn * 32 + nt * 8 + t * 2);

    uint32_t* Cu = (uint32_t*)C;
    if (z < 2) {
        float ssA[4], ssB[4];
#pragma unroll
        for (int mt = 0; mt < 4; mt++) {
            float s0 = 0.0f, s1 = 0.0f;
#pragma unroll
            for (int nt = 0; nt < 4; nt++) {
                float v0 = acc[mt][nt][0] + bb[nt].x;
                float v1 = acc[mt][nt][1] + bb[nt].y;
                float v2 = acc[mt][nt][2] + bb[nt].x;
                float v3 = acc[mt][nt][3] + bb[nt].y;
                s0 = fmaf(v0, v0, s0); s0 = fmaf(v1, v1, s0);
                s1 = fmaf(v2, v2, s1); s1 = fmaf(v3, v3, s1);
            }
            s0 += __shfl_xor_sync(0xffffffffu, s0, 1);
            s0 += __shfl_xor_sync(0xffffffffu, s0, 2);
            s1 += __shfl_xor_sync(0xffffffffu, s1, 1);
            s1 += __shfl_xor_sync(0xffffffffu, s1, 2);
            ssA[mt] = s0; ssB[mt] = s1;
        }
        float* S = (float*)sm;
        if (t == 0) {
#pragma unroll
            for (int mt = 0; mt < 4; mt++) {
                int r0 = wm * 64 + mt * 16 + g;
                S[r0 * 4 + wn]       = ssA[mt];
                S[(r0 + 8) * 4 + wn] = ssB[mt];
            }
        }
        __syncthreads();
        const int pi = wn & ~1;
#pragma unroll
        for (int mt = 0; mt < 4; mt++) {
            int r0 = wm * 64 + mt * 16 + g;
            float sc0 = rsqrtf((S[r0 * 4 + pi] + S[r0 * 4 + pi + 1]) * (1.0f / 64.0f) + 1e-6f) * qsc;
            float sc1 = rsqrtf((S[(r0 + 8) * 4 + pi] + S[(r0 + 8) * 4 + pi + 1]) * (1.0f / 64.0f) + 1e-6f) * qsc;
#pragma unroll
            for (int nt = 0; nt < 4; nt++) {
                int cl = wn * 32 + nt * 8 + t * 2;
                float2 ww = *(const float2*)(normw + (cl & 63));
                float v0 = acc[mt][nt][0] + bb[nt].x;
                float v1 = acc[mt][nt][1] + bb[nt].y;
                float v2 = acc[mt][nt][2] + bb[nt].x;
                float v3 = acc[mt][nt][3] + bb[nt].y;
                uint2 o0 = {f2tf32(v0 * sc0 * ww.x), f2tf32(v1 * sc0 * ww.y)};
                uint2 o1 = {f2tf32(v2 * sc1 * ww.x), f2tf32(v3 * sc1 * ww.y)};
                *(uint2*)(Cu + (size_t)(bm + r0) * CD + bn + cl)     = o0;
                *(uint2*)(Cu + (size_t)(bm + r0 + 8) * CD + bn + cl) = o1;
            }
        }
    } else {
        // V: store TRANSPOSED tf32 bits: vt[((b*16+h)*64+hd)*512 + n]
#pragma unroll
        for (int mt = 0; mt < 4; mt++) {
            int m0 = bm + wm * 64 + mt * 16 + g;
#pragma unroll
            for (int nt = 0; nt < 4; nt++) {
                int d0 = bn + wn * 32 + nt * 8 + t * 2;
                float v00 = acc[mt][nt][0] + bb[nt].x;
                float v01 = acc[mt][nt][1] + bb[nt].y;
                float v10 = acc[mt][nt][2] + bb[nt].x;
                float v11 = acc[mt][nt][3] + bb[nt].y;
                size_t ib = ((size_t)((m0 >> 9) * CH + (d0 >> 6)) * CHD + (d0 & 63)) * CN
                          + (m0 & 511);
                Cu[ib]            = f2tf32(v00);
                Cu[ib + CN]       = f2tf32(v01);
                Cu[ib + 8]        = f2tf32(v10);
                Cu[ib + CN + 8]   = f2tf32(v11);
            }
        }
    }
}

// ---------------------------------------------------------------------------
// async tf32 GEMM (W transposed [n][k]); MODE 0: tf32 bits; MODE 2: gated f32
// ---------------------------------------------------------------------------
template <int MODE>
__global__ __launch_bounds__(256, 2) void gemm_a(
    const uint32_t* __restrict__ A, const uint32_t* __restrict__ W,
    const float* __restrict__ bias, float* __restrict__ C)
{
    extern __shared__ uint32_t sm[];
    const int tid  = threadIdx.x;
    const int lane = tid & 31;
    const int warp = tid >> 5;
    const int wm   = warp >> 2;
    const int wn   = warp & 3;
    const int bm   = blockIdx.y * 128;
    const int bn   = blockIdx.x * 128;
    const int g    = lane >> 2;
    const int t    = lane & 3;
    const int lrow = lane & 7;
    const int lmat = lane >> 3;
    const uint32_t sb = (uint32_t)__cvta_generic_to_shared(sm);
    const int a_loff = ((lmat & 1) * 8 + lrow) * APAD + (lmat >> 1) * 4;
    const int b_loff = ((lmat >> 1) * 8 + lrow) * APAD + (lmat & 1) * 4;

    float acc[4][4][4];
#pragma unroll
    for (int i = 0; i < 4; i++)
#pragma unroll
        for (int j = 0; j < 4; j++)
#pragma unroll
            for (int r = 0; r < 4; r++) acc[i][j][r] = 0.0f;

    auto load_stage = [&](int kt, int st) {
        uint32_t as = sb + (uint32_t)(st * GA_STAGE) * 4u;
        uint32_t bs = as + GA_AW * 4u;
#pragma unroll
        for (int p = 0; p < 4; p++) {
            int idx = p * 256 + tid;
            int r = idx >> 3, c4 = (idx & 7) << 2;
            cp16(as + (uint32_t)(r * APAD + c4) * 4u,
                 A + (size_t)(bm + r) * CD + kt + c4);
            cp16(bs + (uint32_t)(r * APAD + c4) * 4u,
                 W + (size_t)(bn + r) * CD + kt + c4);
        }
        CP_COMMIT();
    };

    load_stage(0, 0);
    int st = 0;
    for (int it = 0; it < 32; it++) {
        CP_WAIT0();
        __syncthreads();
        if (it < 31) load_stage((it + 1) * 32, st ^ 1);
        const uint32_t as_b = sb + (uint32_t)(st * GA_STAGE) * 4u;
        const uint32_t bs_b = as_b + GA_AW * 4u;
#pragma unroll
        for (int ks = 0; ks < 4; ks++) {
            const int kc = ks * 8;
            uint32_t af[4][4], bq4[2][4];
#pragma unroll
            for (int mt = 0; mt < 4; mt++)
                ldsm_x4(af[mt], as_b + (uint32_t)((wm * 64 + mt * 16) * APAD + kc + a_loff) * 4u);
#pragma unroll
            for (int h2 = 0; h2 < 2; h2++)
                ldsm_x4(bq4[h2], bs_b + (uint32_t)((wn * 32 + h2 * 16) * APAD + kc + b_loff) * 4u);
#pragma unroll
            for (int mt = 0; mt < 4; mt++)
#pragma unroll
                for (int nt = 0; nt < 4; nt++)
                    mma_tf32(acc[mt][nt], af[mt], &bq4[nt >> 1][(nt & 1) * 2]);
        }
        st ^= 1;
    }

    float2 bb[4];
#pragma unroll
    for (int nt = 0; nt < 4; nt++)
        bb[nt] = *(const float2*)(bias + bn + wn * 32 + nt * 8 + t * 2);

    if (MODE == 2) {
#pragma unroll
        for (int mt = 0; mt < 4; mt++) {
            int r0 = bm + wm * 64 + mt * 16 + g;
            float ga0 = 1.0f + g_gacc[r0]     * (1.0f / 512.0f);
            float ga1 = 1.0f + g_gacc[r0 + 8] * (1.0f / 512.0f);
#pragma unroll
            for (int nt = 0; nt < 4; nt++) {
                int col = bn + wn * 32 + nt * 8 + t * 2;
                float2 w0 = {acc[mt][nt][0] * ga0 + bb[nt].x, acc[mt][nt][1] * ga0 + bb[nt].y};
                float2 w1 = {acc[mt][nt][2] * ga1 + bb[nt].x, acc[mt][nt][3] * ga1 + bb[nt].y};
                *(float2*)(C + (size_t)r0 * CD + col)       = w0;
                *(float2*)(C + (size_t)(r0 + 8) * CD + col) = w1;
            }
        }
    } else {
        uint32_t* Cu = (uint32_t*)C;
#pragma unroll
        for (int mt = 0; mt < 4; mt++) {
            int r0 = bm + wm * 64 + mt * 16 + g;
#pragma unroll
            for (int nt = 0; nt < 4; nt++) {
                int col = bn + wn * 32 + nt * 8 + t * 2;
                uint2 o0 = {f2tf32(acc[mt][nt][0] + bb[nt].x), f2tf32(acc[mt][nt][1] + bb[nt].y)};
                uint2 o1 = {f2tf32(acc[mt][nt][2] + bb[nt].x), f2tf32(acc[mt][nt][3] + bb[nt].y)};
                *(uint2*)(Cu + (size_t)r0 * CD + col)       = o0;
                *(uint2*)(Cu + (size_t)(r0 + 8) * CD + col) = o1;
            }
        }
    }
}

// ---------------------------------------------------------------------------
// instance gate: both operands n-major [row][k] -> ldmatrix for A and B
// ---------------------------------------------------------------------------
__global__ __launch_bounds__(256, 2) void instgate_t(
    const uint32_t* __restrict__ iq, const uint32_t* __restrict__ ikp)
{
    extern __shared__ uint32_t sm[];
    const int tid  = threadIdx.x;
    const int lane = tid & 31;
    const int warp = tid >> 5;
    const int wm   = warp >> 2;
    const int wn   = warp & 3;
    const int b    = blockIdx.z;
    const int bm   = blockIdx.y * 128;
    const int bn   = blockIdx.x * 128;
    const int g    = lane >> 2;
    const int t    = lane & 3;
    const int lrow = lane & 7;
    const int lmat = lane >> 3;
    const uint32_t* Ab = iq  + (size_t)b * 512 * CD;
    const uint32_t* Bb = ikp + (size_t)b * 512 * CD;
    const uint32_t sb = (uint32_t)__cvta_generic_to_shared(sm);
    const int a_loff = ((lmat & 1) * 8 + lrow) * APAD + (lmat >> 1) * 4;
    const int b_loff = ((lmat >> 1) * 8 + lrow) * APAD + (lmat & 1) * 4;

    float acc[4][4][4];
#pragma unroll
    for (int i = 0; i < 4; i++)
#pragma unroll
        for (int j = 0; j < 4; j++)
#pragma unroll
            for (int r = 0; r < 4; r++) acc[i][j][r] = 0.0f;

    auto load_stage = [&](int kt, int st) {
        uint32_t as = sb + (uint32_t)(st * GA_STAGE) * 4u;
        uint32_t bs = as + GA_AW * 4u;
#pragma unroll
        for (int p = 0; p < 4; p++) {
            int idx = p * 256 + tid;
            int r = idx >> 3, c4 = (idx & 7) << 2;
            cp16(as + (uint32_t)(r * APAD + c4) * 4u, Ab + (size_t)(bm + r) * CD + kt + c4);
            cp16(bs + (uint32_t)(r * APAD + c4) * 4u, Bb + (size_t)(bn + r) * CD + kt + c4);
        }
        CP_COMMIT();
    };

    load_stage(0, 0);
    int st = 0;
    for (int it = 0; it < 32; it++) {
        CP_WAIT0();
        __syncthreads();
        if (it < 31) load_stage((it + 1) * 32, st ^ 1);
        const uint32_t as_b = sb + (uint32_t)(st * GA_STAGE) * 4u;
        const uint32_t bs_b = as_b + GA_AW * 4u;
#pragma unroll
        for (int ks = 0; ks < 4; ks++) {
            const int kc = ks * 8;
            uint32_t af[4][4], bq4[2][4];
#pragma unroll
            for (int mt = 0; mt < 4; mt++)
                ldsm_x4(af[mt], as_b + (uint32_t)((wm * 64 + mt * 16) * APAD + kc + a_loff) * 4u);
#pragma unroll
            for (int h2 = 0; h2 < 2; h2++)
                ldsm_x4(bq4[h2], bs_b + (uint32_t)((wn * 32 + h2 * 16) * APAD + kc + b_loff) * 4u);
#pragma unroll
            for (int mt = 0; mt < 4; mt++)
#pragma unroll
                for (int nt = 0; nt < 4; nt++)
                    mma_tf32(acc[mt][nt], af[mt], &bq4[nt >> 1][(nt & 1) * 2]);
        }
        st ^= 1;
    }

#pragma unroll
    for (int mt = 0; mt < 4; mt++) {
        float s0 = 0.0f, s1 = 0.0f;
#pragma unroll
        for (int nt = 0; nt < 4; nt++) {
            s0 += 1.0f / (1.0f + __expf(-acc[mt][nt][0] * INST_SCALE));
            s0 += 1.0f / (1.0f + __expf(-acc[mt][nt][1] * INST_SCALE));
            s1 += 1.0f / (1.0f + __expf(-acc[mt][nt][2] * INST_SCALE));
            s1 += 1.0f / (1.0f + __expf(-acc[mt][nt][3] * INST_SCALE));
        }
        s0 += __shfl_xor_sync(0xffffffffu, s0, 1);
        s0 += __shfl_xor_sync(0xffffffffu, s0, 2);
        s1 += __shfl_xor_sync(0xffffffffu, s1, 1);
        s1 += __shfl_xor_sync(0xffffffffu, s1, 2);
        if (t == 0) {
            int row = bm + wm * 64 + mt * 16 + g;
            atomicAdd(&g_gacc[b * 512 + row], s0);
            atomicAdd(&g_gacc[b * 512 + row + 8], s1);
        }
    }
}

// ---------------------------------------------------------------------------
// tf32 flash attention: fixed-bound softmax + ldmatrix fragments (R8-validated)
// ---------------------------------------------------------------------------
__global__ __launch_bounds__(256, 2) void attn_t(
    const uint32_t* __restrict__ q, const uint32_t* __restrict__ k,
    const uint32_t* __restrict__ vt, float* __restrict__ o)
{
    extern __shared__ uint32_t sm[];

    const int tid  = threadIdx.x;
    const int lane = tid & 31;
    const int warp = tid >> 5;
    const int g    = lane >> 2;
    const int t    = lane & 3;
    const int bq   = blockIdx.y;
    const int h    = blockIdx.z;
    const int n0   = blockIdx.x * 128;
    const int gb   = bq & ~3;
    const int qrow = n0 + warp * 16;
    const uint32_t sb = (uint32_t)__cvta_generic_to_shared(sm);

    uint32_t qf[8][4];
    {
        const uint32_t* qb = q + ((size_t)(bq * CN + qrow)) * CD + h * CHD;
#pragma unroll
        for (int ks = 0; ks < 8; ks++) {
            int c = ks * 8 + t;
            qf[ks][0] = qb[(size_t)g * CD + c];
            qf[ks][1] = qb[(size_t)(g + 8) * CD + c];
            qf[ks][2] = qb[(size_t)g * CD + c + 4];
            qf[ks][3] = qb[(size_t)(g + 8) * CD + c + 4];
        }
    }

    float oa[8][4];
#pragma unroll
    for (int nt = 0; nt < 8; nt++)
#pragma unroll
        for (int r = 0; r < 4; r++) oa[nt][r] = 0.0f;
    float li0 = 0.0f, li1 = 0.0f;

    uint32_t* Pw = sm + 2 * AT_STAGE + warp * 16 * PPAD;
    const uint32_t pw_sb = sb + (uint32_t)(2 * AT_STAGE + warp * 16 * PPAD) * 4u;
    const int lrow = lane & 7;
    const int lmat = lane >> 3;
    const uint32_t kv_off = (uint32_t)(lrow * KPAD + lmat * 4) * 4u;
    const uint32_t p_off = (uint32_t)(((lmat & 1) * 8 + lrow) * PPAD + (lmat >> 1) * 4) * 4u;

    auto load_kv = [&](int kc, int stg) {
        const int m0 = kc * 64;
        const int kb = gb + (m0 >> 9);
        const int kn = m0 & 511;
        uint32_t ksm = sb + (uint32_t)(stg * AT_STAGE) * 4u;
        uint32_t vsm = ksm + AT_KV * 4u;
#pragma unroll
        for (int p = 0; p < 4; p++) {
            int idx = p * 256 + tid;
            int r   = idx >> 4;
            int c4  = (idx & 15) << 2;
            uint32_t off = (uint32_t)(r * KPAD + c4) * 4u;
            cp16(ksm + off, k + ((size_t)(kb * CN + kn + r)) * CD + h * CHD + c4);
            cp16(vsm + off, vt + ((size_t)((kb * CH + h) * CHD + r)) * CN + kn + c4);
        }
        CP_COMMIT();
    };

    load_kv(0, 0);
    int st = 0;

    for (int kc = 0; kc < 32; kc++) {
        CP_WAIT0();
        __syncthreads();
        if (kc < 31) load_kv(kc + 1, st ^ 1);

        const uint32_t ks_sb = sb + (uint32_t)(st * AT_STAGE) * 4u;
        const uint32_t vs_sb = ks_sb + AT_KV * 4u;

        float sacc[8][4];
#pragma unroll
        for (int nt = 0; nt < 8; nt++)
#pragma unroll
            for (int r = 0; r < 4; r++) sacc[nt][r] = 0.0f;
#pragma unroll
        for (int nt = 0; nt < 8; nt++) {
            uint32_t rowa = ks_sb + (uint32_t)(nt * 8 * KPAD) * 4u + kv_off;
#pragma unroll
            for (int kp = 0; kp < 4; kp++) {
                uint32_t kb4[4];
                ldsm_x4(kb4, rowa + (uint32_t)(kp * 16) * 4u);
                mma_tf32(sacc[nt], qf[2 * kp],     kb4);
                mma_tf32(sacc[nt], qf[2 * kp + 1], kb4 + 2);
            }
        }

#pragma unroll
        for (int nt = 0; nt < 8; nt++) {
            float p0 = __expf(sacc[nt][0] - SOFT_SHIFT);
            float p1 = __expf(sacc[nt][1] - SOFT_SHIFT);
            float p2 = __expf(sacc[nt][2] - SOFT_SHIFT);
            float p3 = __expf(sacc[nt][3] - SOFT_SHIFT);
            li0 += p0 + p1;
            li1 += p2 + p3;
            int col = nt * 8 + 2 * t;
            uint2 w0 = {f2tf32(p0), f2tf32(p1)};
            uint2 w1 = {f2tf32(p2), f2tf32(p3)};
            *(uint2*)&Pw[g * PPAD + col]       = w0;
            *(uint2*)&Pw[(g + 8) * PPAD + col] = w1;
        }
        __syncwarp();

        uint32_t pf[8][4];
#pragma unroll
        for (int ks = 0; ks < 8; ks++)
            ldsm_x4(pf[ks], pw_sb + p_off + (uint32_t)(ks * 8) * 4u);

#pragma unroll
        for (int nt = 0; nt < 8; nt++) {
            uint32_t rowv = vs_sb + (uint32_t)(nt * 8 * KPAD) * 4u + kv_off;
#pragma unroll
            for (int kp = 0; kp < 4; kp++) {
                uint32_t vb4[4];
                ldsm_x4(vb4, rowv + (uint32_t)(kp * 16) * 4u);
                mma_tf32(oa[nt], pf[2 * kp],     vb4);
                mma_tf32(oa[nt], pf[2 * kp + 1], vb4 + 2);
            }
        }
        __syncwarp();
        st ^= 1;
    }

    li0 += __shfl_xor_sync(0xffffffffu, li0, 1);
    li0 += __shfl_xor_sync(0xffffffffu, li0, 2);
    li1 += __shfl_xor_sync(0xffffffffu, li1, 1);
    li1 += __shfl_xor_sync(0xffffffffu, li1, 2);
    float inv0 = 1.0f / li0, inv1 = 1.0f / li1;
    uint32_t* ob = (uint32_t*)(o + ((size_t)(bq * CN + qrow)) * CD + h * CHD);
#pragma unroll
    for (int nt = 0; nt < 8; nt++) {
        int col = nt * 8 + 2 * t;
        uint2 r0 = {f2tf32(oa[nt][0] * inv0), f2tf32(oa[nt][1] * inv0)};
        uint2 r1 = {f2tf32(oa[nt][2] * inv1), f2tf32(oa[nt][3] * inv1)};
        *(uint2*)(ob + (size_t)g * CD + col)       = r0;
        *(uint2*)(ob + (size_t)(g + 8) * CD + col) = r1;
    }
}

// ---------------------------------------------------------------------------
// E2 = emb[:4] @ Wik, k-split 8 ways with atomic accumulation.
// idx = kchunk*4096 + out  (out fastest -> coalesced Wik reads)
// g_e2 zeroed by zero_gacc_k.
// ---------------------------------------------------------------------------
__global__ void e2_k(const float* __restrict__ emb, const float* __restrict__ Wik) {
    int idx = blockIdx.x * 256 + threadIdx.x;   // 0..32767
    int out = idx & 4095;                        // 0..4095
    int kc  = idx >> 12;                         // 0..7
    int i = out >> 10;
    int c = out & 1023;
    const float* ep = emb + i * 1024 + kc * 128;
    const float* wp = Wik + (size_t)(kc * 128) * 1024 + c;
    float acc = 0.0f;
#pragma unroll 4
    for (int kk = 0; kk < 128; kk++)
        acc = fmaf(ep[kk], wp[(size_t)kk * 1024], acc);
    atomicAdd(&g_e2[out], acc);
}

__global__ void ikb_k(const float* __restrict__ mask, const float* __restrict__ bik,
                      uint32_t* __restrict__ ik) {
    int idx = blockIdx.x * 256 + threadIdx.x;
    int d  = idx & 1023;
    int bn = idx >> 10;
    const float* mp = mask + (size_t)bn * 4;
    float acc = bik[d];
    acc = fmaf(mp[0], g_e2[d],        acc);
    acc = fmaf(mp[1], g_e2[1024 + d], acc);
    acc = fmaf(mp[2], g_e2[2048 + d], acc);
    acc = fmaf(mp[3], g_e2[3072 + d], acc);
    ik[idx] = f2tf32(acc);
}

// ---------------------------------------------------------------------------
// launch
// ---------------------------------------------------------------------------
extern "C" void kernel_launch(void* const* d_in, const int* in_sizes, int n_in,
                              void* d_out, int out_size)
{
    (void)in_sizes; (void)n_in; (void)out_size;
    const float* x    = (const float*)d_in[0];
    const float* mask = (const float*)d_in[1];
    const float* Wq   = (const float*)d_in[2];
    const float* bq   = (const float*)d_in[3];
    const float* Wk   = (const float*)d_in[4];
    const float* bk   = (const float*)d_in[5];
    const float* Wv   = (const float*)d_in[6];
    const float* bv   = (const float*)d_in[7];
    const float* Wo   = (const float*)d_in[8];
    const float* bo   = (const float*)d_in[9];
    const float* Wiq  = (const float*)d_in[10];
    const float* biq  = (const float*)d_in[11];
    const float* Wik  = (const float*)d_in[12];
    const float* bik  = (const float*)d_in[13];
    const float* emb  = (const float*)d_in[14];
    const float* qw   = (const float*)d_in[15];
    const float* kw   = (const float*)d_in[16];
    float* out = (float*)d_out;

    float *qp, *kp, *vtp, *op, *iqp;
    uint32_t *xt, *wq, *wk, *wv, *wiq, *wo, *ikp;
    cudaGetSymbolAddress((void**)&qp,  g_q);
    cudaGetSymbolAddress((void**)&kp,  g_k);
    cudaGetSymbolAddress((void**)&vtp, g_vt);
    cudaGetSymbolAddress((void**)&op,  g_o);
    cudaGetSymbolAddress((void**)&iqp, g_iq);
    cudaGetSymbolAddress((void**)&ikp, g_ik);
    cudaGetSymbolAddress((void**)&xt,  g_xt);
    cudaGetSymbolAddress((void**)&wq,  g_wq);
    cudaGetSymbolAddress((void**)&wk,  g_wk);
    cudaGetSymbolAddress((void**)&wv,  g_wv);
    cudaGetSymbolAddress((void**)&wiq, g_wiq);
    cudaGetSymbolAddress((void**)&wo,  g_wo);

    static bool attr_done = false;
    if (!attr_done) {
        cudaFuncSetAttribute(gemm_qkv, cudaFuncAttributeMaxDynamicSharedMemorySize, SMEM_GEMM);
        cudaFuncSetAttribute(gemm_a<0>, cudaFuncAttributeMaxDynamicSharedMemorySize, SMEM_GEMM);
        cudaFuncSetAttribute(gemm_a<2>, cudaFuncAttributeMaxDynamicSharedMemorySize, SMEM_GEMM);
        cudaFuncSetAttribute(instgate_t, cudaFuncAttributeMaxDynamicSharedMemorySize, SMEM_GEMM);
        cudaFuncSetAttribute(attn_t, cudaFuncAttributeMaxDynamicSharedMemorySize, SMEM_ATTN);
        attr_done = true;
    }

    dim3 gemm_grid(8, 32);

    zero_gacc_k<<<16, 256>>>();

    cvt_x_k<<<4096, 256>>>(x, xt);
    wtr_k<<<dim3(32, 32, 5), 256>>>(Wq, Wk, Wv, Wiq, Wo, wq, wk, wv, wiq, wo);

    // e2/ikb only need inputs + zeroed g_e2; run early, off the critical tail
    e2_k<<<128, 256>>>(emb, Wik);
    ikb_k<<<16384, 256>>>(mask, bik, ikp);

    gemm_qkv<<<dim3(8, 32, 3), 256, SMEM_GEMM>>>(xt, wq, wk, wv, bq, bk, bv,
                                                 qw, kw, qp, kp, vtp);

    attn_t<<<dim3(4, 8, 16), 256, SMEM_ATTN>>>((const uint32_t*)qp, (const uint32_t*)kp,
                                               (const uint32_t*)vtp, op);

    gemm_a<0><<<gemm_grid, 256, SMEM_GEMM>>>((const uint32_t*)op, wiq, biq, iqp);

    instgate_t<<<dim3(4, 4, 8), 256, SMEM_GEMM>>>((const uint32_t*)iqp, ikp);

    gemm_a<2><<<gemm_grid, 256, SMEM_GEMM>>>((const uint32_t*)op, wo, bo, out);
}

// round 15
// speedup vs baseline: 3.8953x; 1.0524x over previous
#include <cuda_runtime.h>
#include <cstdint>
#include <cstddef>

// ---------------------------------------------------------------------------
// MIDIMultiInstanceAttention  (B=8, N=512, D=1024, H=16, HD=64, NI=4)
// tf32 tensor cores everywhere; ldmatrix fragment loads; fixed-bound softmax;
// transposed weights; k-split e2; attention = 4 warps x 32 q-rows (2 m16/warp)
// ---------------------------------------------------------------------------

#define CB 8
#define CN 512
#define CD 1024
#define CH 16
#define CHD 64
#define CM 4096
#define ATT_SCALE 0.125f
#define SOFT_SHIFT 8.0f
#define INST_SCALE (0.125f / 16.0f)

#define APAD 36
#define KPAD 68
#define PPAD 68

#define GA_AW (128 * APAD)                 // 4608 words
#define GA_STAGE (2 * GA_AW)               // A + B(t), 9216 words
#define SMEM_GEMM (2 * GA_STAGE * 4)       // 73728 B

#define AT_KV (64 * KPAD)                  // 4352 words
#define AT_STAGE (2 * AT_KV)               // K + Vt
#define SMEM_ATTN ((2 * AT_STAGE + 4 * 32 * PPAD) * 4)   // 104448 B

// scratch (device globals: allocation-free rule)
__device__ __align__(16) uint32_t g_xt[CM * CD];
__device__ __align__(16) uint32_t g_wq[CD * CD];    // transposed tf32 [n][k]
__device__ __align__(16) uint32_t g_wk[CD * CD];
__device__ __align__(16) uint32_t g_wv[CD * CD];
__device__ __align__(16) uint32_t g_wiq[CD * CD];
__device__ __align__(16) uint32_t g_wo[CD * CD];
__device__ __align__(16) float g_q [CM * CD];       // tf32 bits (pre-scaled)
__device__ __align__(16) float g_k [CM * CD];       // tf32 bits
__device__ __align__(16) float g_vt[CM * CD];       // tf32 bits, [b,h][d][n]
__device__ __align__(16) float g_o [CM * CD];       // tf32 bits
__device__ __align__(16) float g_iq[CM * CD];       // tf32 bits
__device__ __align__(16) uint32_t g_ik[CM * CD];    // tf32 bits
__device__ __align__(16) float g_e2[4 * CD];
__device__ float g_gacc[CM];

// zero gacc AND e2 partial-sum buffer (both 4096 floats)
__global__ void zero_gacc_k() {
    int i = blockIdx.x * 256 + threadIdx.x;
    if (i < CM) g_gacc[i] = 0.0f;
    if (i < 4 * CD) g_e2[i] = 0.0f;
}

// ---------------------------------------------------------------------------
// helpers
// ---------------------------------------------------------------------------
__device__ __forceinline__ uint32_t f2tf32(float x) {
    uint32_t r;
    asm("cvt.rna.tf32.f32 %0, %1;" : "=r"(r) : "f"(x));
    return r;
}

__device__ __forceinline__ void mma_tf32(float* d, const uint32_t* a, const uint32_t* b) {
    asm volatile(
        "mma.sync.aligned.m16n8k8.row.col.f32.tf32.tf32.f32 "
        "{%0,%1,%2,%3}, {%4,%5,%6,%7}, {%8,%9}, {%0,%1,%2,%3};\n"
        : "+f"(d[0]), "+f"(d[1]), "+f"(d[2]), "+f"(d[3])
        : "r"(a[0]), "r"(a[1]), "r"(a[2]), "r"(a[3]), "r"(b[0]), "r"(b[1]));
}

__device__ __forceinline__ void ldsm_x4(uint32_t* r, uint32_t saddr) {
    asm volatile("ldmatrix.sync.aligned.m8n8.x4.shared.b16 {%0,%1,%2,%3}, [%4];\n"
        : "=r"(r[0]), "=r"(r[1]), "=r"(r[2]), "=r"(r[3]) : "r"(saddr));
}

__device__ __forceinline__ void cp16(uint32_t dst, const void* src) {
    asm volatile("cp.async.cg.shared.global [%0], [%1], 16;\n" :: "r"(dst), "l"(src));
}
#define CP_COMMIT() asm volatile("cp.async.commit_group;\n")
#define CP_WAIT0()  asm volatile("cp.async.wait_group 0;\n")

// x -> tf32 bits (no transpose)
__global__ void cvt_x_k(const float* __restrict__ x, uint32_t* __restrict__ xt) {
    int i = blockIdx.x * 256 + threadIdx.x;
    float4 v = ((const float4*)x)[i];
    uint4 o = {f2tf32(v.x), f2tf32(v.y), f2tf32(v.z), f2tf32(v.w)};
    ((uint4*)xt)[i] = o;
}

// weights: cvt to tf32 bits AND transpose -> Wt[n][k]
__global__ void wtr_k(const float* __restrict__ w0, const float* __restrict__ w1,
                      const float* __restrict__ w2, const float* __restrict__ w3,
                      const float* __restrict__ w4,
                      uint32_t* __restrict__ o0, uint32_t* __restrict__ o1,
                      uint32_t* __restrict__ o2, uint32_t* __restrict__ o3,
                      uint32_t* __restrict__ o4)
{
    __shared__ uint32_t ts[32][33];
    const int z = blockIdx.z;
    const float* src = (z == 0) ? w0 : (z == 1) ? w1 : (z == 2) ? w2 : (z == 3) ? w3 : w4;
    uint32_t*    dst = (z == 0) ? o0 : (z == 1) ? o1 : (z == 2) ? o2 : (z == 3) ? o3 : o4;
    const int n0 = blockIdx.x * 32;
    const int k0 = blockIdx.y * 32;
    const int c  = threadIdx.x & 31;
    const int r8 = threadIdx.x >> 5;
#pragma unroll
    for (int i = 0; i < 4; i++) {
        int r = r8 + i * 8;
        ts[r][c] = f2tf32(src[(size_t)(k0 + r) * CD + n0 + c]);
    }
    __syncthreads();
#pragma unroll
    for (int i = 0; i < 4; i++) {
        int r = r8 + i * 8;
        dst[(size_t)(n0 + r) * CD + k0 + c] = ts[c][r];
    }
}

// ---------------------------------------------------------------------------
// fused QKV projection: z selects {Wq,Wk,Wv} (transposed). z<2 -> fused
// per-head RMSNorm (Q pre-scaled by ATT_SCALE). z==2 -> V stored transposed.
// ---------------------------------------------------------------------------
__global__ __launch_bounds__(256, 2) void gemm_qkv(
    const uint32_t* __restrict__ A,
    const uint32_t* __restrict__ Wq_, const uint32_t* __restrict__ Wk_,
    const uint32_t* __restrict__ Wv_,
    const float* __restrict__ bq_, const float* __restrict__ bk_,
    const float* __restrict__ bv_,
    const float* __restrict__ qw_, const float* __restrict__ kw_,
    float* __restrict__ oq_, float* __restrict__ ok_, float* __restrict__ ov_)
{
    extern __shared__ uint32_t sm[];
    const int z = blockIdx.z;
    const uint32_t* W   = (z == 0) ? Wq_ : (z == 1) ? Wk_ : Wv_;
    const float* bias   = (z == 0) ? bq_ : (z == 1) ? bk_ : bv_;
    const float* normw  = (z == 0) ? qw_ : kw_;
    float* C            = (z == 0) ? oq_ : (z == 1) ? ok_ : ov_;
    const float qsc     = (z == 0) ? ATT_SCALE : 1.0f;

    const int tid  = threadIdx.x;
    const int lane = tid & 31;
    const int warp = tid >> 5;
    const int wm   = warp >> 2;
    const int wn   = warp & 3;
    const int bm   = blockIdx.y * 128;
    const int bn   = blockIdx.x * 128;
    const int g    = lane >> 2;
    const int t    = lane & 3;
    const int lrow = lane & 7;
    const int lmat = lane >> 3;
    const uint32_t sb = (uint32_t)__cvta_generic_to_shared(sm);
    const int a_loff = ((lmat & 1) * 8 + lrow) * APAD + (lmat >> 1) * 4;
    const int b_loff = ((lmat >> 1) * 8 + lrow) * APAD + (lmat & 1) * 4;

    float acc[4][4][4];
#pragma unroll
    for (int i = 0; i < 4; i++)
#pragma unroll
        for (int j = 0; j < 4; j++)
#pragma unroll
            for (int r = 0; r < 4; r++) acc[i][j][r] = 0.0f;

    auto load_stage = [&](int kt, int st) {
        uint32_t as = sb + (uint32_t)(st * GA_STAGE) * 4u;
        uint32_t bs = as + GA_AW * 4u;
#pragma unroll
        for (int p = 0; p < 4; p++) {
            int idx = p * 256 + tid;
            int r = idx >> 3, c4 = (idx & 7) << 2;
            cp16(as + (uint32_t)(r * APAD + c4) * 4u,
                 A + (size_t)(bm + r) * CD + kt + c4);
            cp16(bs + (uint32_t)(r * APAD + c4) * 4u,
                 W + (size_t)(bn + r) * CD + kt + c4);
        }
        CP_COMMIT();
    };

    load_stage(0, 0);
    int st = 0;
    for (int it = 0; it < 32; it++) {
        CP_WAIT0();
        __syncthreads();
        if (it < 31) load_stage((it + 1) * 32, st ^ 1);
        const uint32_t as_b = sb + (uint32_t)(st * GA_STAGE) * 4u;
        const uint32_t bs_b = as_b + GA_AW * 4u;
#pragma unroll
        for (int ks = 0; ks < 4; ks++) {
            const int kc = ks * 8;
            uint32_t af[4][4], bq4[2][4];
#pragma unroll
            for (int mt = 0; mt < 4; mt++)
                ldsm_x4(af[mt], as_b + (uint32_t)((wm * 64 + mt * 16) * APAD + kc + a_loff) * 4u);
#pragma unroll
            for (int h2 = 0; h2 < 2; h2++)
                ldsm_x4(bq4[h2], bs_b + (uint32_t)((wn * 32 + h2 * 16) * APAD + kc + b_loff) * 4u);
#pragma unroll
            for (int mt = 0; mt < 4; mt++)
#pragma unroll
                for (int nt = 0; nt < 4; nt++)
                    mma_tf32(acc[mt][nt], af[mt], &bq4[nt >> 1][(nt & 1) * 2]);
        }
        st ^= 1;
    }
    __syncthreads();

    float2 bb[4];
#pragma unroll
    for (int nt = 0; nt < 4; nt++)
        bb[nt] = *(const float2*)(bias + bn + wn * 32 + nt * 8 + t * 2);

    uint32_t* Cu = (uint32_t*)C;
    if (z < 2) {
        float ssA[4], ssB[4];
#pragma unroll
        for (int mt = 0; mt < 4; mt++) {
            float s0 = 0.0f, s1 = 0.0f;
#pragma unroll
            for (int nt = 0; nt < 4; nt++) {
                float v0 = acc[mt][nt][0] + bb[nt].x;
                float v1 = acc[mt][nt][1] + bb[nt].y;
                float v2 = acc[mt][nt][2] + bb[nt].x;
                float v3 = acc[mt][nt][3] + bb[nt].y;
                s0 = fmaf(v0, v0, s0); s0 = fmaf(v1, v1, s0);
                s1 = fmaf(v2, v2, s1); s1 = fmaf(v3, v3, s1);
            }
            s0 += __shfl_xor_sync(0xffffffffu, s0, 1);
            s0 += __shfl_xor_sync(0xffffffffu, s0, 2);
            s1 += __shfl_xor_sync(0xffffffffu, s1, 1);
            s1 += __shfl_xor_sync(0xffffffffu, s1, 2);
            ssA[mt] = s0; ssB[mt] = s1;
        }
        float* S = (float*)sm;
        if (t == 0) {
#pragma unroll
            for (int mt = 0; mt < 4; mt++) {
                int r0 = wm * 64 + mt * 16 + g;
                S[r0 * 4 + wn]       = ssA[mt];
                S[(r0 + 8) * 4 + wn] = ssB[mt];
            }
        }
        __syncthreads();
        const int pi = wn & ~1;
#pragma unroll
        for (int mt = 0; mt < 4; mt++) {
            int r0 = wm * 64 + mt * 16 + g;
            float sc0 = rsqrtf((S[r0 * 4 + pi] + S[r0 * 4 + pi + 1]) * (1.0f / 64.0f) + 1e-6f) * qsc;
            float sc1 = rsqrtf((S[(r0 + 8) * 4 + pi] + S[(r0 + 8) * 4 + pi + 1]) * (1.0f / 64.0f) + 1e-6f) * qsc;
#pragma unroll
            for (int nt = 0; nt < 4; nt++) {
                int cl = wn * 32 + nt * 8 + t * 2;
                float2 ww = *(const float2*)(normw + (cl & 63));
                float v0 = acc[mt][nt][0] + bb[nt].x;
                float v1 = acc[mt][nt][1] + bb[nt].y;
                float v2 = acc[mt][nt][2] + bb[nt].x;
                float v3 = acc[mt][nt][3] + bb[nt].y;
                uint2 o0 = {f2tf32(v0 * sc0 * ww.x), f2tf32(v1 * sc0 * ww.y)};
                uint2 o1 = {f2tf32(v2 * sc1 * ww.x), f2tf32(v3 * sc1 * ww.y)};
                *(uint2*)(Cu + (size_t)(bm + r0) * CD + bn + cl)     = o0;
                *(uint2*)(Cu + (size_t)(bm + r0 + 8) * CD + bn + cl) = o1;
            }
        }
    } else {
        // V: store TRANSPOSED tf32 bits: vt[((b*16+h)*64+hd)*512 + n]
#pragma unroll
        for (int mt = 0; mt < 4; mt++) {
            int m0 = bm + wm * 64 + mt * 16 + g;
#pragma unroll
            for (int nt = 0; nt < 4; nt++) {
                int d0 = bn + wn * 32 + nt * 8 + t * 2;
                float v00 = acc[mt][nt][0] + bb[nt].x;
                float v01 = acc[mt][nt][1] + bb[nt].y;
                float v10 = acc[mt][nt][2] + bb[nt].x;
                float v11 = acc[mt][nt][3] + bb[nt].y;
                size_t ib = ((size_t)((m0 >> 9) * CH + (d0 >> 6)) * CHD + (d0 & 63)) * CN
                          + (m0 & 511);
                Cu[ib]            = f2tf32(v00);
                Cu[ib + CN]       = f2tf32(v01);
                Cu[ib + 8]        = f2tf32(v10);
                Cu[ib + CN + 8]   = f2tf32(v11);
            }
        }
    }
}

// ---------------------------------------------------------------------------
// async tf32 GEMM (W transposed [n][k]); MODE 0: tf32 bits; MODE 2: gated f32
// ---------------------------------------------------------------------------
template <int MODE>
__global__ __launch_bounds__(256, 2) void gemm_a(
    const uint32_t* __restrict__ A, const uint32_t* __restrict__ W,
    const float* __restrict__ bias, float* __restrict__ C)
{
    extern __shared__ uint32_t sm[];
    const int tid  = threadIdx.x;
    const int lane = tid & 31;
    const int warp = tid >> 5;
    const int wm   = warp >> 2;
    const int wn   = warp & 3;
    const int bm   = blockIdx.y * 128;
    const int bn   = blockIdx.x * 128;
    const int g    = lane >> 2;
    const int t    = lane & 3;
    const int lrow = lane & 7;
    const int lmat = lane >> 3;
    const uint32_t sb = (uint32_t)__cvta_generic_to_shared(sm);
    const int a_loff = ((lmat & 1) * 8 + lrow) * APAD + (lmat >> 1) * 4;
    const int b_loff = ((lmat >> 1) * 8 + lrow) * APAD + (lmat & 1) * 4;

    float acc[4][4][4];
#pragma unroll
    for (int i = 0; i < 4; i++)
#pragma unroll
        for (int j = 0; j < 4; j++)
#pragma unroll
            for (int r = 0; r < 4; r++) acc[i][j][r] = 0.0f;

    auto load_stage = [&](int kt, int st) {
        uint32_t as = sb + (uint32_t)(st * GA_STAGE) * 4u;
        uint32_t bs = as + GA_AW * 4u;
#pragma unroll
        for (int p = 0; p < 4; p++) {
            int idx = p * 256 + tid;
            int r = idx >> 3, c4 = (idx & 7) << 2;
            cp16(as + (uint32_t)(r * APAD + c4) * 4u,
                 A + (size_t)(bm + r) * CD + kt + c4);
            cp16(bs + (uint32_t)(r * APAD + c4) * 4u,
                 W + (size_t)(bn + r) * CD + kt + c4);
        }
        CP_COMMIT();
    };

    load_stage(0, 0);
    int st = 0;
    for (int it = 0; it < 32; it++) {
        CP_WAIT0();
        __syncthreads();
        if (it < 31) load_stage((it + 1) * 32, st ^ 1);
        const uint32_t as_b = sb + (uint32_t)(st * GA_STAGE) * 4u;
        const uint32_t bs_b = as_b + GA_AW * 4u;
#pragma unroll
        for (int ks = 0; ks < 4; ks++) {
            const int kc = ks * 8;
            uint32_t af[4][4], bq4[2][4];
#pragma unroll
            for (int mt = 0; mt < 4; mt++)
                ldsm_x4(af[mt], as_b + (uint32_t)((wm * 64 + mt * 16) * APAD + kc + a_loff) * 4u);
#pragma unroll
            for (int h2 = 0; h2 < 2; h2++)
                ldsm_x4(bq4[h2], bs_b + (uint32_t)((wn * 32 + h2 * 16) * APAD + kc + b_loff) * 4u);
#pragma unroll
            for (int mt = 0; mt < 4; mt++)
#pragma unroll
                for (int nt = 0; nt < 4; nt++)
                    mma_tf32(acc[mt][nt], af[mt], &bq4[nt >> 1][(nt & 1) * 2]);
        }
        st ^= 1;
    }

    float2 bb[4];
#pragma unroll
    for (int nt = 0; nt < 4; nt++)
        bb[nt] = *(const float2*)(bias + bn + wn * 32 + nt * 8 + t * 2);

    if (MODE == 2) {
#pragma unroll
        for (int mt = 0; mt < 4; mt++) {
            int r0 = bm + wm * 64 + mt * 16 + g;
            float ga0 = 1.0f + g_gacc[r0]     * (1.0f / 512.0f);
            float ga1 = 1.0f + g_gacc[r0 + 8] * (1.0f / 512.0f);
#pragma unroll
            for (int nt = 0; nt < 4; nt++) {
                int col = bn + wn * 32 + nt * 8 + t * 2;
                float2 w0 = {acc[mt][nt][0] * ga0 + bb[nt].x, acc[mt][nt][1] * ga0 + bb[nt].y};
                float2 w1 = {acc[mt][nt][2] * ga1 + bb[nt].x, acc[mt][nt][3] * ga1 + bb[nt].y};
                *(float2*)(C + (size_t)r0 * CD + col)       = w0;
                *(float2*)(C + (size_t)(r0 + 8) * CD + col) = w1;
            }
        }
    } else {
        uint32_t* Cu = (uint32_t*)C;
#pragma unroll
        for (int mt = 0; mt < 4; mt++) {
            int r0 = bm + wm * 64 + mt * 16 + g;
#pragma unroll
            for (int nt = 0; nt < 4; nt++) {
                int col = bn + wn * 32 + nt * 8 + t * 2;
                uint2 o0 = {f2tf32(acc[mt][nt][0] + bb[nt].x), f2tf32(acc[mt][nt][1] + bb[nt].y)};
                uint2 o1 = {f2tf32(acc[mt][nt][2] + bb[nt].x), f2tf32(acc[mt][nt][3] + bb[nt].y)};
                *(uint2*)(Cu + (size_t)r0 * CD + col)       = o0;
                *(uint2*)(Cu + (size_t)(r0 + 8) * CD + col) = o1;
            }
        }
    }
}

// ---------------------------------------------------------------------------
// instance gate: both operands n-major [row][k] -> ldmatrix for A and B
// ---------------------------------------------------------------------------
__global__ __launch_bounds__(256, 2) void instgate_t(
    const uint32_t* __restrict__ iq, const uint32_t* __restrict__ ikp)
{
    extern __shared__ uint32_t sm[];
    const int tid  = threadIdx.x;
    const int lane = tid & 31;
    const int warp = tid >> 5;
    const int wm   = warp >> 2;
    const int wn   = warp & 3;
    const int b    = blockIdx.z;
    const int bm   = blockIdx.y * 128;
    const int bn   = blockIdx.x * 128;
    const int g    = lane >> 2;
    const int t    = lane & 3;
    const int lrow = lane & 7;
    const int lmat = lane >> 3;
    const uint32_t* Ab = iq  + (size_t)b * 512 * CD;
    const uint32_t* Bb = ikp + (size_t)b * 512 * CD;
    const uint32_t sb = (uint32_t)__cvta_generic_to_shared(sm);
    const int a_loff = ((lmat & 1) * 8 + lrow) * APAD + (lmat >> 1) * 4;
    const int b_loff = ((lmat >> 1) * 8 + lrow) * APAD + (lmat & 1) * 4;

    float acc[4][4][4];
#pragma unroll
    for (int i = 0; i < 4; i++)
#pragma unroll
        for (int j = 0; j < 4; j++)
#pragma unroll
            for (int r = 0; r < 4; r++) acc[i][j][r] = 0.0f;

    auto load_stage = [&](int kt, int st) {
        uint32_t as = sb + (uint32_t)(st * GA_STAGE) * 4u;
        uint32_t bs = as + GA_AW * 4u;
#pragma unroll
        for (int p = 0; p < 4; p++) {
            int idx = p * 256 + tid;
            int r = idx >> 3, c4 = (idx & 7) << 2;
            cp16(as + (uint32_t)(r * APAD + c4) * 4u, Ab + (size_t)(bm + r) * CD + kt + c4);
            cp16(bs + (uint32_t)(r * APAD + c4) * 4u, Bb + (size_t)(bn + r) * CD + kt + c4);
        }
        CP_COMMIT();
    };

    load_stage(0, 0);
    int st = 0;
    for (int it = 0; it < 32; it++) {
        CP_WAIT0();
        __syncthreads();
        if (it < 31) load_stage((it + 1) * 32, st ^ 1);
        const uint32_t as_b = sb + (uint32_t)(st * GA_STAGE) * 4u;
        const uint32_t bs_b = as_b + GA_AW * 4u;
#pragma unroll
        for (int ks = 0; ks < 4; ks++) {
            const int kc = ks * 8;
            uint32_t af[4][4], bq4[2][4];
#pragma unroll
            for (int mt = 0; mt < 4; mt++)
                ldsm_x4(af[mt], as_b + (uint32_t)((wm * 64 + mt * 16) * APAD + kc + a_loff) * 4u);
#pragma unroll
            for (int h2 = 0; h2 < 2; h2++)
                ldsm_x4(bq4[h2], bs_b + (uint32_t)((wn * 32 + h2 * 16) * APAD + kc + b_loff) * 4u);
#pragma unroll
            for (int mt = 0; mt < 4; mt++)
#pragma unroll
                for (int nt = 0; nt < 4; nt++)
                    mma_tf32(acc[mt][nt], af[mt], &bq4[nt >> 1][(nt & 1) * 2]);
        }
        st ^= 1;
    }

#pragma unroll
    for (int mt = 0; mt < 4; mt++) {
        float s0 = 0.0f, s1 = 0.0f;
#pragma unroll
        for (int nt = 0; nt < 4; nt++) {
            s0 += 1.0f / (1.0f + __expf(-acc[mt][nt][0] * INST_SCALE));
            s0 += 1.0f / (1.0f + __expf(-acc[mt][nt][1] * INST_SCALE));
            s1 += 1.0f / (1.0f + __expf(-acc[mt][nt][2] * INST_SCALE));
            s1 += 1.0f / (1.0f + __expf(-acc[mt][nt][3] * INST_SCALE));
        }
        s0 += __shfl_xor_sync(0xffffffffu, s0, 1);
        s0 += __shfl_xor_sync(0xffffffffu, s0, 2);
        s1 += __shfl_xor_sync(0xffffffffu, s1, 1);
        s1 += __shfl_xor_sync(0xffffffffu, s1, 2);
        if (t == 0) {
            int row = bm + wm * 64 + mt * 16 + g;
            atomicAdd(&g_gacc[b * 512 + row], s0);
            atomicAdd(&g_gacc[b * 512 + row + 8], s1);
        }
    }
}

// ---------------------------------------------------------------------------
// tf32 flash attention: fixed-bound softmax + ldmatrix fragments.
// 4 warps x 32 q-rows (two m16 tiles per warp): each K/V fragment feeds
// 4 MMAs instead of 2 -> block smem-read traffic drops ~45%.
// ---------------------------------------------------------------------------
__global__ __launch_bounds__(128, 2) void attn_t(
    const uint32_t* __restrict__ q, const uint32_t* __restrict__ k,
    const uint32_t* __restrict__ vt, float* __restrict__ o)
{
    extern __shared__ uint32_t sm[];

    const int tid  = threadIdx.x;
    const int lane = tid & 31;
    const int warp = tid >> 5;          // 0..3
    const int g    = lane >> 2;
    const int t    = lane & 3;
    const int bq   = blockIdx.y;
    const int h    = blockIdx.z;
    const int n0   = blockIdx.x * 128;
    const int gb   = bq & ~3;
    const int qrow = n0 + warp * 32;    // 32 q rows per warp
    const uint32_t sb = (uint32_t)__cvta_generic_to_shared(sm);

    uint32_t qf[2][8][4];
#pragma unroll
    for (int u = 0; u < 2; u++) {
        const uint32_t* qb = q + ((size_t)(bq * CN + qrow + u * 16)) * CD + h * CHD;
#pragma unroll
        for (int ks = 0; ks < 8; ks++) {
            int c = ks * 8 + t;
            qf[u][ks][0] = qb[(size_t)g * CD + c];
            qf[u][ks][1] = qb[(size_t)(g + 8) * CD + c];
            qf[u][ks][2] = qb[(size_t)g * CD + c + 4];
            qf[u][ks][3] = qb[(size_t)(g + 8) * CD + c + 4];
        }
    }

    float oa[2][8][4];
#pragma unroll
    for (int u = 0; u < 2; u++)
#pragma unroll
        for (int nt = 0; nt < 8; nt++)
#pragma unroll
            for (int r = 0; r < 4; r++) oa[u][nt][r] = 0.0f;
    float li[2][2] = {{0.0f, 0.0f}, {0.0f, 0.0f}};

    uint32_t* Pw = sm + 2 * AT_STAGE + warp * 32 * PPAD;
    const uint32_t pw_sb = sb + (uint32_t)(2 * AT_STAGE + warp * 32 * PPAD) * 4u;
    const int lrow = lane & 7;
    const int lmat = lane >> 3;
    const uint32_t kv_off = (uint32_t)(lrow * KPAD + lmat * 4) * 4u;
    const uint32_t p_off = (uint32_t)(((lmat & 1) * 8 + lrow) * PPAD + (lmat >> 1) * 4) * 4u;

    auto load_kv = [&](int kc, int stg) {
        const int m0 = kc * 64;
        const int kb = gb + (m0 >> 9);
        const int kn = m0 & 511;
        uint32_t ksm = sb + (uint32_t)(stg * AT_STAGE) * 4u;
        uint32_t vsm = ksm + AT_KV * 4u;
#pragma unroll
        for (int p = 0; p < 8; p++) {
            int idx = p * 128 + tid;
            int r   = idx >> 4;
            int c4  = (idx & 15) << 2;
            uint32_t off = (uint32_t)(r * KPAD + c4) * 4u;
            cp16(ksm + off, k + ((size_t)(kb * CN + kn + r)) * CD + h * CHD + c4);
            cp16(vsm + off, vt + ((size_t)((kb * CH + h) * CHD + r)) * CN + kn + c4);
        }
        CP_COMMIT();
    };

    load_kv(0, 0);
    int st = 0;

    for (int kc = 0; kc < 32; kc++) {
        CP_WAIT0();
        __syncthreads();
        if (kc < 31) load_kv(kc + 1, st ^ 1);

        const uint32_t ks_sb = sb + (uint32_t)(st * AT_STAGE) * 4u;
        const uint32_t vs_sb = ks_sb + AT_KV * 4u;

        // ---- S = Q @ K^T for BOTH m16 tiles (K fragment loaded once) ----
        float sacc[2][8][4];
#pragma unroll
        for (int u = 0; u < 2; u++)
#pragma unroll
            for (int nt = 0; nt < 8; nt++)
#pragma unroll
                for (int r = 0; r < 4; r++) sacc[u][nt][r] = 0.0f;
#pragma unroll
        for (int nt = 0; nt < 8; nt++) {
            uint32_t rowa = ks_sb + (uint32_t)(nt * 8 * KPAD) * 4u + kv_off;
#pragma unroll
            for (int kp = 0; kp < 4; kp++) {
                uint32_t kb4[4];
                ldsm_x4(kb4, rowa + (uint32_t)(kp * 16) * 4u);
                mma_tf32(sacc[0][nt], qf[0][2 * kp],     kb4);
                mma_tf32(sacc[0][nt], qf[0][2 * kp + 1], kb4 + 2);
                mma_tf32(sacc[1][nt], qf[1][2 * kp],     kb4);
                mma_tf32(sacc[1][nt], qf[1][2 * kp + 1], kb4 + 2);
            }
        }

        // ---- fixed-shift softmax: p = exp(s - 8), both tiles ----
#pragma unroll
        for (int u = 0; u < 2; u++) {
#pragma unroll
            for (int nt = 0; nt < 8; nt++) {
                float p0 = __expf(sacc[u][nt][0] - SOFT_SHIFT);
                float p1 = __expf(sacc[u][nt][1] - SOFT_SHIFT);
                float p2 = __expf(sacc[u][nt][2] - SOFT_SHIFT);
                float p3 = __expf(sacc[u][nt][3] - SOFT_SHIFT);
                li[u][0] += p0 + p1;
                li[u][1] += p2 + p3;
                int col = nt * 8 + 2 * t;
                uint2 w0 = {f2tf32(p0), f2tf32(p1)};
                uint2 w1 = {f2tf32(p2), f2tf32(p3)};
                *(uint2*)&Pw[(u * 16 + g) * PPAD + col]       = w0;
                *(uint2*)&Pw[(u * 16 + g + 8) * PPAD + col]   = w1;
            }
        }
        __syncwarp();

        // ---- load P fragments for both tiles ----
        uint32_t pf[2][8][4];
#pragma unroll
        for (int u = 0; u < 2; u++)
#pragma unroll
            for (int ks = 0; ks < 8; ks++)
                ldsm_x4(pf[u][ks],
                        pw_sb + (uint32_t)(u * 16 * PPAD) * 4u + p_off + (uint32_t)(ks * 8) * 4u);

        // ---- O += P @ V for BOTH tiles (V fragment loaded once) ----
#pragma unroll
        for (int nt = 0; nt < 8; nt++) {
            uint32_t rowv = vs_sb + (uint32_t)(nt * 8 * KPAD) * 4u + kv_off;
#pragma unroll
            for (int kp = 0; kp < 4; kp++) {
                uint32_t vb4[4];
                ldsm_x4(vb4, rowv + (uint32_t)(kp * 16) * 4u);
                mma_tf32(oa[0][nt], pf[0][2 * kp],     vb4);
                mma_tf32(oa[0][nt], pf[0][2 * kp + 1], vb4 + 2);
                mma_tf32(oa[1][nt], pf[1][2 * kp],     vb4);
                mma_tf32(oa[1][nt], pf[1][2 * kp + 1], vb4 + 2);
            }
        }
        __syncwarp();
        st ^= 1;
    }

    // ---- epilogue: reduce li, normalize, store tf32 bits (both tiles) ----
#pragma unroll
    for (int u = 0; u < 2; u++) {
        float l0 = li[u][0], l1 = li[u][1];
        l0 += __shfl_xor_sync(0xffffffffu, l0, 1);
        l0 += __shfl_xor_sync(0xffffffffu, l0, 2);
        l1 += __shfl_xor_sync(0xffffffffu, l1, 1);
        l1 += __shfl_xor_sync(0xffffffffu, l1, 2);
        float inv0 = 1.0f / l0, inv1 = 1.0f / l1;
        uint32_t* ob = (uint32_t*)(o + ((size_t)(bq * CN + qrow + u * 16)) * CD + h * CHD);
#pragma unroll
        for (int nt = 0; nt < 8; nt++) {
            int col = nt * 8 + 2 * t;
            uint2 r0 = {f2tf32(oa[u][nt][0] * inv0), f2tf32(oa[u][nt][1] * inv0)};
            uint2 r1 = {f2tf32(oa[u][nt][2] * inv1), f2tf32(oa[u][nt][3] * inv1)};
            *(uint2*)(ob + (size_t)g * CD + col)       = r0;
            *(uint2*)(ob + (size_t)(g + 8) * CD + col) = r1;
        }
    }
}

// ---------------------------------------------------------------------------
// E2 = emb[:4] @ Wik, k-split 8 ways with atomic accumulation.
// ---------------------------------------------------------------------------
__global__ void e2_k(const float* __restrict__ emb, const float* __restrict__ Wik) {
    int idx = blockIdx.x * 256 + threadIdx.x;   // 0..32767
    int out = idx & 4095;
    int kc  = idx >> 12;
    int i = out >> 10;
    int c = out & 1023;
    const float* ep = emb + i * 1024 + kc * 128;
    const float* wp = Wik + (size_t)(kc * 128) * 1024 + c;
    float acc = 0.0f;
#pragma unroll 4
    for (int kk = 0; kk < 128; kk++)
        acc = fmaf(ep[kk], wp[(size_t)kk * 1024], acc);
    atomicAdd(&g_e2[out], acc);
}

__global__ void ikb_k(const float* __restrict__ mask, const float* __restrict__ bik,
                      uint32_t* __restrict__ ik) {
    int idx = blockIdx.x * 256 + threadIdx.x;
    int d  = idx & 1023;
    int bn = idx >> 10;
    const float* mp = mask + (size_t)bn * 4;
    float acc = bik[d];
    acc = fmaf(mp[0], g_e2[d],        acc);
    acc = fmaf(mp[1], g_e2[1024 + d], acc);
    acc = fmaf(mp[2], g_e2[2048 + d], acc);
    acc = fmaf(mp[3], g_e2[3072 + d], acc);
    ik[idx] = f2tf32(acc);
}

// ---------------------------------------------------------------------------
// launch
// ---------------------------------------------------------------------------
extern "C" void kernel_launch(void* const* d_in, const int* in_sizes, int n_in,
                              void* d_out, int out_size)
{
    (void)in_sizes; (void)n_in; (void)out_size;
    const float* x    = (const float*)d_in[0];
    const float* mask = (const float*)d_in[1];
    const float* Wq   = (const float*)d_in[2];
    const float* bq   = (const float*)d_in[3];
    const float* Wk   = (const float*)d_in[4];
    const float* bk   = (const float*)d_in[5];
    const float* Wv   = (const float*)d_in[6];
    const float* bv   = (const float*)d_in[7];
    const float* Wo   = (const float*)d_in[8];
    const float* bo   = (const float*)d_in[9];
    const float* Wiq  = (const float*)d_in[10];
    const float* biq  = (const float*)d_in[11];
    const float* Wik  = (const float*)d_in[12];
    const float* bik  = (const float*)d_in[13];
    const float* emb  = (const float*)d_in[14];
    const float* qw   = (const float*)d_in[15];
    const float* kw   = (const float*)d_in[16];
    float* out = (float*)d_out;

    float *qp, *kp, *vtp, *op, *iqp;
    uint32_t *xt, *wq, *wk, *wv, *wiq, *wo, *ikp;
    cudaGetSymbolAddress((void**)&qp,  g_q);
    cudaGetSymbolAddress((void**)&kp,  g_k);
    cudaGetSymbolAddress((void**)&vtp, g_vt);
    cudaGetSymbolAddress((void**)&op,  g_o);
    cudaGetSymbolAddress((void**)&iqp, g_iq);
    cudaGetSymbolAddress((void**)&ikp, g_ik);
    cudaGetSymbolAddress((void**)&xt,  g_xt);
    cudaGetSymbolAddress((void**)&wq,  g_wq);
    cudaGetSymbolAddress((void**)&wk,  g_wk);
    cudaGetSymbolAddress((void**)&wv,  g_wv);
    cudaGetSymbolAddress((void**)&wiq, g_wiq);
    cudaGetSymbolAddress((void**)&wo,  g_wo);

    static bool attr_done = false;
    if (!attr_done) {
        cudaFuncSetAttribute(gemm_qkv, cudaFuncAttributeMaxDynamicSharedMemorySize, SMEM_GEMM);
        cudaFuncSetAttribute(gemm_a<0>, cudaFuncAttributeMaxDynamicSharedMemorySize, SMEM_GEMM);
        cudaFuncSetAttribute(gemm_a<2>, cudaFuncAttributeMaxDynamicSharedMemorySize, SMEM_GEMM);
        cudaFuncSetAttribute(instgate_t, cudaFuncAttributeMaxDynamicSharedMemorySize, SMEM_GEMM);
        cudaFuncSetAttribute(attn_t, cudaFuncAttributeMaxDynamicSharedMemorySize, SMEM_ATTN);
        attr_done = true;
    }

    dim3 gemm_grid(8, 32);

    zero_gacc_k<<<16, 256>>>();

    cvt_x_k<<<4096, 256>>>(x, xt);
    wtr_k<<<dim3(32, 32, 5), 256>>>(Wq, Wk, Wv, Wiq, Wo, wq, wk, wv, wiq, wo);

    // e2/ikb only need inputs + zeroed g_e2; run early, off the critical tail
    e2_k<<<128, 256>>>(emb, Wik);
    ikb_k<<<16384, 256>>>(mask, bik, ikp);

    gemm_qkv<<<dim3(8, 32, 3), 256, SMEM_GEMM>>>(xt, wq, wk, wv, bq, bk, bv,
                                                 qw, kw, qp, kp, vtp);

    attn_t<<<dim3(4, 8, 16), 128, SMEM_ATTN>>>((const uint32_t*)qp, (const uint32_t*)kp,
                                               (const uint32_t*)vtp, op);

    gemm_a<0><<<gemm_grid, 256, SMEM_GEMM>>>((const uint32_t*)op, wiq, biq, iqp);

    instgate_t<<<dim3(4, 4, 8), 256, SMEM_GEMM>>>((const uint32_t*)iqp, ikp);

    gemm_a<2><<<gemm_grid, 256, SMEM_GEMM>>>((const uint32_t*)op, wo, bo, out);
}

// round 16
// speedup vs baseline: 4.5880x; 1.1778x over previous
#include <cuda_runtime.h>
#include <cstdint>
#include <cstddef>

// ---------------------------------------------------------------------------
// MIDIMultiInstanceAttention  (B=8, N=512, D=1024, H=16, HD=64, NI=4)
// tf32 tensor cores; ldmatrix fragments; fixed-bound softmax; transposed
// weights; rank-5 factorized instance gate (no iq GEMM, no instgate GEMM)
// ---------------------------------------------------------------------------

#define CB 8
#define CN 512
#define CD 1024
#define CH 16
#define CHD 64
#define CM 4096
#define ATT_SCALE 0.125f
#define SOFT_SHIFT 8.0f
#define INST_SCALE (0.125f / 16.0f)

#define APAD 36
#define KPAD 68
#define PPAD 68

#define GA_AW (128 * APAD)                 // 4608 words
#define GA_STAGE (2 * GA_AW)               // A + B(t), 9216 words
#define SMEM_GEMM (2 * GA_STAGE * 4)       // 73728 B

#define AT_KV (64 * KPAD)                  // 4352 words
#define AT_STAGE (2 * AT_KV)               // K + Vt
#define SMEM_ATTN ((2 * AT_STAGE + 4 * 32 * PPAD) * 4)   // 104448 B

// scratch (device globals: allocation-free rule)
__device__ __align__(16) uint32_t g_xt[CM * CD];
__device__ __align__(16) uint32_t g_wq[CD * CD];    // transposed tf32 [n][k]
__device__ __align__(16) uint32_t g_wk[CD * CD];
__device__ __align__(16) uint32_t g_wv[CD * CD];
__device__ __align__(16) uint32_t g_wo[CD * CD];
__device__ __align__(16) float g_q [CM * CD];       // tf32 bits (pre-scaled)
__device__ __align__(16) float g_k [CM * CD];       // tf32 bits
__device__ __align__(16) float g_vt[CM * CD];       // tf32 bits, [b,h][d][n]
__device__ __align__(16) float g_o [CM * CD];       // tf32 bits
__device__ __align__(16) float g_e2[4 * CD];        // emb[:4] @ Wik
__device__ __align__(16) float g_m [1025 * 8];      // rows 0..1023: [M(4), mv, pad]; row 1024: biq-row
__device__ __align__(16) float g_ug[CM * 8];        // per token: U0..U3, w, pad
__device__ float g_gacc[CM];

// zero the e2 partial-sum buffer
__global__ void zero_e2_k() {
    int i = blockIdx.x * 256 + threadIdx.x;
    if (i < 4 * CD) g_e2[i] = 0.0f;
}

// ---------------------------------------------------------------------------
// helpers
// ---------------------------------------------------------------------------
__device__ __forceinline__ uint32_t f2tf32(float x) {
    uint32_t r;
    asm("cvt.rna.tf32.f32 %0, %1;" : "=r"(r) : "f"(x));
    return r;
}

__device__ __forceinline__ void mma_tf32(float* d, const uint32_t* a, const uint32_t* b) {
    asm volatile(
        "mma.sync.aligned.m16n8k8.row.col.f32.tf32.tf32.f32 "
        "{%0,%1,%2,%3}, {%4,%5,%6,%7}, {%8,%9}, {%0,%1,%2,%3};\n"
        : "+f"(d[0]), "+f"(d[1]), "+f"(d[2]), "+f"(d[3])
        : "r"(a[0]), "r"(a[1]), "r"(a[2]), "r"(a[3]), "r"(b[0]), "r"(b[1]));
}

__device__ __forceinline__ void ldsm_x4(uint32_t* r, uint32_t saddr) {
    asm volatile("ldmatrix.sync.aligned.m8n8.x4.shared.b16 {%0,%1,%2,%3}, [%4];\n"
        : "=r"(r[0]), "=r"(r[1]), "=r"(r[2]), "=r"(r[3]) : "r"(saddr));
}

__device__ __forceinline__ void cp16(uint32_t dst, const void* src) {
    asm volatile("cp.async.cg.shared.global [%0], [%1], 16;\n" :: "r"(dst), "l"(src));
}
#define CP_COMMIT() asm volatile("cp.async.commit_group;\n")
#define CP_WAIT0()  asm volatile("cp.async.wait_group 0;\n")

// x -> tf32 bits (no transpose)
__global__ void cvt_x_k(const float* __restrict__ x, uint32_t* __restrict__ xt) {
    int i = blockIdx.x * 256 + threadIdx.x;
    float4 v = ((const float4*)x)[i];
    uint4 o = {f2tf32(v.x), f2tf32(v.y), f2tf32(v.z), f2tf32(v.w)};
    ((uint4*)xt)[i] = o;
}

// 4 weights: cvt to tf32 bits AND transpose -> Wt[n][k]
__global__ void wtr_k(const float* __restrict__ w0, const float* __restrict__ w1,
                      const float* __restrict__ w2, const float* __restrict__ w3,
                      uint32_t* __restrict__ o0, uint32_t* __restrict__ o1,
                      uint32_t* __restrict__ o2, uint32_t* __restrict__ o3)
{
    __shared__ uint32_t ts[32][33];
    const int z = blockIdx.z;
    const float* src = (z == 0) ? w0 : (z == 1) ? w1 : (z == 2) ? w2 : w3;
    uint32_t*    dst = (z == 0) ? o0 : (z == 1) ? o1 : (z == 2) ? o2 : o3;
    const int n0 = blockIdx.x * 32;
    const int k0 = blockIdx.y * 32;
    const int c  = threadIdx.x & 31;
    const int r8 = threadIdx.x >> 5;
#pragma unroll
    for (int i = 0; i < 4; i++) {
        int r = r8 + i * 8;
        ts[r][c] = f2tf32(src[(size_t)(k0 + r) * CD + n0 + c]);
    }
    __syncthreads();
#pragma unroll
    for (int i = 0; i < 4; i++) {
        int r = r8 + i * 8;
        dst[(size_t)(n0 + r) * CD + k0 + c] = ts[c][r];
    }
}

// ---------------------------------------------------------------------------
// E2 = emb[:4] @ Wik, k-split 32 ways with atomic accumulation
// ---------------------------------------------------------------------------
__global__ void e2_k(const float* __restrict__ emb, const float* __restrict__ Wik) {
    int idx = blockIdx.x * 256 + threadIdx.x;   // 0..131071
    int out = idx & 4095;
    int kc  = idx >> 12;                         // 0..31
    int i = out >> 10;
    int c = out & 1023;
    const float* ep = emb + i * 1024 + kc * 32;
    const float* wp = Wik + (size_t)(kc * 32) * 1024 + c;
    float acc = 0.0f;
#pragma unroll
    for (int kk = 0; kk < 32; kk++)
        acc = fmaf(ep[kk], wp[(size_t)kk * 1024], acc);
    atomicAdd(&g_e2[out], acc);
}

// ---------------------------------------------------------------------------
// prep: g_m[k][i<4] = Wiq[k,:]·E2[i,:],  g_m[k][4] = Wiq[k,:]·bik
// row 1024 uses biq instead of Wiq[k,:]  (fp32, exact small GEMM)
// one warp per row; 8 warps/block, 129 blocks (last block row>=1025 idle)
// ---------------------------------------------------------------------------
__global__ void prep_k(const float* __restrict__ Wiq, const float* __restrict__ biq,
                       const float* __restrict__ bik) {
    int w    = blockIdx.x * 8 + (threadIdx.x >> 5);
    int lane = threadIdx.x & 31;
    if (w > 1024) return;
    const float* row = (w < 1024) ? (Wiq + (size_t)w * CD) : biq;
    float a0 = 0.0f, a1 = 0.0f, a2 = 0.0f, a3 = 0.0f, a4 = 0.0f;
    for (int d = lane; d < CD; d += 32) {
        float r = row[d];
        a0 = fmaf(r, g_e2[d],        a0);
        a1 = fmaf(r, g_e2[1024 + d], a1);
        a2 = fmaf(r, g_e2[2048 + d], a2);
        a3 = fmaf(r, g_e2[3072 + d], a3);
        a4 = fmaf(r, bik[d],         a4);
    }
#pragma unroll
    for (int off = 16; off; off >>= 1) {
        a0 += __shfl_xor_sync(0xffffffffu, a0, off);
        a1 += __shfl_xor_sync(0xffffffffu, a1, off);
        a2 += __shfl_xor_sync(0xffffffffu, a2, off);
        a3 += __shfl_xor_sync(0xffffffffu, a3, off);
        a4 += __shfl_xor_sync(0xffffffffu, a4, off);
    }
    if (lane == 0) {
        float* mp = g_m + w * 8;
        mp[0] = a0; mp[1] = a1; mp[2] = a2; mp[3] = a3; mp[4] = a4;
    }
}

// ---------------------------------------------------------------------------
// uvw: per token n: U[n][i] = o[n,:]·M[:,i] + u0[i] (i<4), w = o[n,:]·mv + w0
// one warp per row (4096 warps)
// ---------------------------------------------------------------------------
__global__ void uvw_k(const float* __restrict__ o) {
    int n    = blockIdx.x * 8 + (threadIdx.x >> 5);
    int lane = threadIdx.x & 31;
    const float* op = o + (size_t)n * CD;
    float a0 = 0.0f, a1 = 0.0f, a2 = 0.0f, a3 = 0.0f, a4 = 0.0f;
    for (int d = lane; d < CD; d += 32) {
        float ov = op[d];
        const float* mp = g_m + d * 8;
        float4 m4 = *(const float4*)mp;
        a0 = fmaf(ov, m4.x, a0);
        a1 = fmaf(ov, m4.y, a1);
        a2 = fmaf(ov, m4.z, a2);
        a3 = fmaf(ov, m4.w, a3);
        a4 = fmaf(ov, mp[4], a4);
    }
#pragma unroll
    for (int off = 16; off; off >>= 1) {
        a0 += __shfl_xor_sync(0xffffffffu, a0, off);
        a1 += __shfl_xor_sync(0xffffffffu, a1, off);
        a2 += __shfl_xor_sync(0xffffffffu, a2, off);
        a3 += __shfl_xor_sync(0xffffffffu, a3, off);
        a4 += __shfl_xor_sync(0xffffffffu, a4, off);
    }
    if (lane == 0) {
        const float* u0 = g_m + 1024 * 8;   // biq row
        float* up = g_ug + n * 8;
        up[0] = a0 + u0[0];
        up[1] = a1 + u0[1];
        up[2] = a2 + u0[2];
        up[3] = a3 + u0[3];
        up[4] = a4 + u0[4];
    }
}

// ---------------------------------------------------------------------------
// gate: gacc[b,n] = sum_m sigmoid((U[n]·mask[b,m] + w[n]) * INST_SCALE)
// one warp per token (4096 warps); direct store (no atomics)
// ---------------------------------------------------------------------------
__global__ void gate_k(const float* __restrict__ mask) {
    int n    = blockIdx.x * 8 + (threadIdx.x >> 5);
    int lane = threadIdx.x & 31;
    int b    = n >> 9;
    const float* up = g_ug + n * 8;       // broadcast loads
    float u0 = up[0], u1 = up[1], u2 = up[2], u3 = up[3], wv = up[4];
    const float4* mp = (const float4*)(mask + (size_t)b * CN * 4);
    float acc = 0.0f;
#pragma unroll 4
    for (int m = lane; m < CN; m += 32) {
        float4 mk = mp[m];
        float s = wv;
        s = fmaf(u0, mk.x, s);
        s = fmaf(u1, mk.y, s);
        s = fmaf(u2, mk.z, s);
        s = fmaf(u3, mk.w, s);
        acc += 1.0f / (1.0f + __expf(-s * INST_SCALE));
    }
#pragma unroll
    for (int off = 16; off; off >>= 1)
        acc += __shfl_xor_sync(0xffffffffu, acc, off);
    if (lane == 0) g_gacc[n] = acc;
}

// ---------------------------------------------------------------------------
// fused QKV projection: z selects {Wq,Wk,Wv} (transposed). z<2 -> fused
// per-head RMSNorm (Q pre-scaled by ATT_SCALE). z==2 -> V stored transposed.
// ---------------------------------------------------------------------------
__global__ __launch_bounds__(256, 2) void gemm_qkv(
    const uint32_t* __restrict__ A,
    const uint32_t* __restrict__ Wq_, const uint32_t* __restrict__ Wk_,
    const uint32_t* __restrict__ Wv_,
    const float* __restrict__ bq_, const float* __restrict__ bk_,
    const float* __restrict__ bv_,
    const float* __restrict__ qw_, const float* __restrict__ kw_,
    float* __restrict__ oq_, float* __restrict__ ok_, float* __restrict__ ov_)
{
    extern __shared__ uint32_t sm[];
    const int z = blockIdx.z;
    const uint32_t* W   = (z == 0) ? Wq_ : (z == 1) ? Wk_ : Wv_;
    const float* bias   = (z == 0) ? bq_ : (z == 1) ? bk_ : bv_;
    const float* normw  = (z == 0) ? qw_ : kw_;
    float* C            = (z == 0) ? oq_ : (z == 1) ? ok_ : ov_;
    const float qsc     = (z == 0) ? ATT_SCALE : 1.0f;

    const int tid  = threadIdx.x;
    const int lane = tid & 31;
    const int warp = tid >> 5;
    const int wm   = warp >> 2;
    const int wn   = warp & 3;
    const int bm   = blockIdx.y * 128;
    const int bn   = blockIdx.x * 128;
    const int g    = lane >> 2;
    const int t    = lane & 3;
    const int lrow = lane & 7;
    const int lmat = lane >> 3;
    const uint32_t sb = (uint32_t)__cvta_generic_to_shared(sm);
    const int a_loff = ((lmat & 1) * 8 + lrow) * APAD + (lmat >> 1) * 4;
    const int b_loff = ((lmat >> 1) * 8 + lrow) * APAD + (lmat & 1) * 4;

    float acc[4][4][4];
#pragma unroll
    for (int i = 0; i < 4; i++)
#pragma unroll
        for (int j = 0; j < 4; j++)
#pragma unroll
            for (int r = 0; r < 4; r++) acc[i][j][r] = 0.0f;

    auto load_stage = [&](int kt, int st) {
        uint32_t as = sb + (uint32_t)(st * GA_STAGE) * 4u;
        uint32_t bs = as + GA_AW * 4u;
#pragma unroll
        for (int p = 0; p < 4; p++) {
            int idx = p * 256 + tid;
            int r = idx >> 3, c4 = (idx & 7) << 2;
            cp16(as + (uint32_t)(r * APAD + c4) * 4u,
                 A + (size_t)(bm + r) * CD + kt + c4);
            cp16(bs + (uint32_t)(r * APAD + c4) * 4u,
                 W + (size_t)(bn + r) * CD + kt + c4);
        }
        CP_COMMIT();
    };

    load_stage(0, 0);
    int st = 0;
    for (int it = 0; it < 32; it++) {
        CP_WAIT0();
        __syncthreads();
        if (it < 31) load_stage((it + 1) * 32, st ^ 1);
        const uint32_t as_b = sb + (uint32_t)(st * GA_STAGE) * 4u;
        const uint32_t bs_b = as_b + GA_AW * 4u;
#pragma unroll
        for (int ks = 0; ks < 4; ks++) {
            const int kc = ks * 8;
            uint32_t af[4][4], bq4[2][4];
#pragma unroll
            for (int mt = 0; mt < 4; mt++)
                ldsm_x4(af[mt], as_b + (uint32_t)((wm * 64 + mt * 16) * APAD + kc + a_loff) * 4u);
#pragma unroll
            for (int h2 = 0; h2 < 2; h2++)
                ldsm_x4(bq4[h2], bs_b + (uint32_t)((wn * 32 + h2 * 16) * APAD + kc + b_loff) * 4u);
#pragma unroll
            for (int mt = 0; mt < 4; mt++)
#pragma unroll
                for (int nt = 0; nt < 4; nt++)
                    mma_tf32(acc[mt][nt], af[mt], &bq4[nt >> 1][(nt & 1) * 2]);
        }
        st ^= 1;
    }
    __syncthreads();

    float2 bb[4];
#pragma unroll
    for (int nt = 0; nt < 4; nt++)
        bb[nt] = *(const float2*)(bias + bn + wn * 32 + nt * 8 + t * 2);

    uint32_t* Cu = (uint32_t*)C;
    if (z < 2) {
        float ssA[4], ssB[4];
#pragma unroll
        for (int mt = 0; mt < 4; mt++) {
            float s0 = 0.0f, s1 = 0.0f;
#pragma unroll
            for (int nt = 0; nt < 4; nt++) {
                float v0 = acc[mt][nt][0] + bb[nt].x;
                float v1 = acc[mt][nt][1] + bb[nt].y;
                float v2 = acc[mt][nt][2] + bb[nt].x;
                float v3 = acc[mt][nt][3] + bb[nt].y;
                s0 = fmaf(v0, v0, s0); s0 = fmaf(v1, v1, s0);
                s1 = fmaf(v2, v2, s1); s1 = fmaf(v3, v3, s1);
            }
            s0 += __shfl_xor_sync(0xffffffffu, s0, 1);
            s0 += __shfl_xor_sync(0xffffffffu, s0, 2);
            s1 += __shfl_xor_sync(0xffffffffu, s1, 1);
            s1 += __shfl_xor_sync(0xffffffffu, s1, 2);
            ssA[mt] = s0; ssB[mt] = s1;
        }
        float* S = (float*)sm;
        if (t == 0) {
#pragma unroll
            for (int mt = 0; mt < 4; mt++) {
                int r0 = wm * 64 + mt * 16 + g;
                S[r0 * 4 + wn]       = ssA[mt];
                S[(r0 + 8) * 4 + wn] = ssB[mt];
            }
        }
        __syncthreads();
        const int pi = wn & ~1;
#pragma unroll
        for (int mt = 0; mt < 4; mt++) {
            int r0 = wm * 64 + mt * 16 + g;
            float sc0 = rsqrtf((S[r0 * 4 + pi] + S[r0 * 4 + pi + 1]) * (1.0f / 64.0f) + 1e-6f) * qsc;
            float sc1 = rsqrtf((S[(r0 + 8) * 4 + pi] + S[(r0 + 8) * 4 + pi + 1]) * (1.0f / 64.0f) + 1e-6f) * qsc;
#pragma unroll
            for (int nt = 0; nt < 4; nt++) {
                int cl = wn * 32 + nt * 8 + t * 2;
                float2 ww = *(const float2*)(normw + (cl & 63));
                float v0 = acc[mt][nt][0] + bb[nt].x;
                float v1 = acc[mt][nt][1] + bb[nt].y;
                float v2 = acc[mt][nt][2] + bb[nt].x;
                float v3 = acc[mt][nt][3] + bb[nt].y;
                uint2 o0 = {f2tf32(v0 * sc0 * ww.x), f2tf32(v1 * sc0 * ww.y)};
                uint2 o1 = {f2tf32(v2 * sc1 * ww.x), f2tf32(v3 * sc1 * ww.y)};
                *(uint2*)(Cu + (size_t)(bm + r0) * CD + bn + cl)     = o0;
                *(uint2*)(Cu + (size_t)(bm + r0 + 8) * CD + bn + cl) = o1;
            }
        }
    } else {
        // V: store TRANSPOSED tf32 bits: vt[((b*16+h)*64+hd)*512 + n]
#pragma unroll
        for (int mt = 0; mt < 4; mt++) {
            int m0 = bm + wm * 64 + mt * 16 + g;
#pragma unroll
            for (int nt = 0; nt < 4; nt++) {
                int d0 = bn + wn * 32 + nt * 8 + t * 2;
                float v00 = acc[mt][nt][0] + bb[nt].x;
                float v01 = acc[mt][nt][1] + bb[nt].y;
                float v10 = acc[mt][nt][2] + bb[nt].x;
                float v11 = acc[mt][nt][3] + bb[nt].y;
                size_t ib = ((size_t)((m0 >> 9) * CH + (d0 >> 6)) * CHD + (d0 & 63)) * CN
                          + (m0 & 511);
                Cu[ib]            = f2tf32(v00);
                Cu[ib + CN]       = f2tf32(v01);
                Cu[ib + 8]        = f2tf32(v10);
                Cu[ib + CN + 8]   = f2tf32(v11);
            }
        }
    }
}

// ---------------------------------------------------------------------------
// final GEMM: out = (gate*o) @ Wo + bo  (gate applied post-mma, exact)
// ---------------------------------------------------------------------------
__global__ __launch_bounds__(256, 2) void gemm_o(
    const uint32_t* __restrict__ A, const uint32_t* __restrict__ W,
    const float* __restrict__ bias, float* __restrict__ C)
{
    extern __shared__ uint32_t sm[];
    const int tid  = threadIdx.x;
    const int lane = tid & 31;
    const int warp = tid >> 5;
    const int wm   = warp >> 2;
    const int wn   = warp & 3;
    const int bm   = blockIdx.y * 128;
    const int bn   = blockIdx.x * 128;
    const int g    = lane >> 2;
    const int t    = lane & 3;
    const int lrow = lane & 7;
    const int lmat = lane >> 3;
    const uint32_t sb = (uint32_t)__cvta_generic_to_shared(sm);
    const int a_loff = ((lmat & 1) * 8 + lrow) * APAD + (lmat >> 1) * 4;
    const int b_loff = ((lmat >> 1) * 8 + lrow) * APAD + (lmat & 1) * 4;

    float acc[4][4][4];
#pragma unroll
    for (int i = 0; i < 4; i++)
#pragma unroll
        for (int j = 0; j < 4; j++)
#pragma unroll
            for (int r = 0; r < 4; r++) acc[i][j][r] = 0.0f;

    auto load_stage = [&](int kt, int st) {
        uint32_t as = sb + (uint32_t)(st * GA_STAGE) * 4u;
        uint32_t bs = as + GA_AW * 4u;
#pragma unroll
        for (int p = 0; p < 4; p++) {
            int idx = p * 256 + tid;
            int r = idx >> 3, c4 = (idx & 7) << 2;
            cp16(as + (uint32_t)(r * APAD + c4) * 4u,
                 A + (size_t)(bm + r) * CD + kt + c4);
            cp16(bs + (uint32_t)(r * APAD + c4) * 4u,
                 W + (size_t)(bn + r) * CD + kt + c4);
        }
        CP_COMMIT();
    };

    load_stage(0, 0);
    int st = 0;
    for (int it = 0; it < 32; it++) {
        CP_WAIT0();
        __syncthreads();
        if (it < 31) load_stage((it + 1) * 32, st ^ 1);
        const uint32_t as_b = sb + (uint32_t)(st * GA_STAGE) * 4u;
        const uint32_t bs_b = as_b + GA_AW * 4u;
#pragma unroll
        for (int ks = 0; ks < 4; ks++) {
            const int kc = ks * 8;
            uint32_t af[4][4], bq4[2][4];
#pragma unroll
            for (int mt = 0; mt < 4; mt++)
                ldsm_x4(af[mt], as_b + (uint32_t)((wm * 64 + mt * 16) * APAD + kc + a_loff) * 4u);
#pragma unroll
            for (int h2 = 0; h2 < 2; h2++)
                ldsm_x4(bq4[h2], bs_b + (uint32_t)((wn * 32 + h2 * 16) * APAD + kc + b_loff) * 4u);
#pragma unroll
            for (int mt = 0; mt < 4; mt++)
#pragma unroll
                for (int nt = 0; nt < 4; nt++)
                    mma_tf32(acc[mt][nt], af[mt], &bq4[nt >> 1][(nt & 1) * 2]);
        }
        st ^= 1;
    }

    float2 bb[4];
#pragma unroll
    for (int nt = 0; nt < 4; nt++)
        bb[nt] = *(const float2*)(bias + bn + wn * 32 + nt * 8 + t * 2);

#pragma unroll
    for (int mt = 0; mt < 4; mt++) {
        int r0 = bm + wm * 64 + mt * 16 + g;
        float ga0 = 1.0f + g_gacc[r0]     * (1.0f / 512.0f);
        float ga1 = 1.0f + g_gacc[r0 + 8] * (1.0f / 512.0f);
#pragma unroll
        for (int nt = 0; nt < 4; nt++) {
            int col = bn + wn * 32 + nt * 8 + t * 2;
            float2 w0 = {acc[mt][nt][0] * ga0 + bb[nt].x, acc[mt][nt][1] * ga0 + bb[nt].y};
            float2 w1 = {acc[mt][nt][2] * ga1 + bb[nt].x, acc[mt][nt][3] * ga1 + bb[nt].y};
            *(float2*)(C + (size_t)r0 * CD + col)       = w0;
            *(float2*)(C + (size_t)(r0 + 8) * CD + col) = w1;
        }
    }
}

// ---------------------------------------------------------------------------
// tf32 flash attention: fixed-bound softmax + ldmatrix fragments.
// 4 warps x 32 q-rows (two m16 tiles per warp)  (R15-validated)
// ---------------------------------------------------------------------------
__global__ __launch_bounds__(128, 2) void attn_t(
    const uint32_t* __restrict__ q, const uint32_t* __restrict__ k,
    const uint32_t* __restrict__ vt, float* __restrict__ o)
{
    extern __shared__ uint32_t sm[];

    const int tid  = threadIdx.x;
    const int lane = tid & 31;
    const int warp = tid >> 5;
    const int g    = lane >> 2;
    const int t    = lane & 3;
    const int bq   = blockIdx.y;
    const int h    = blockIdx.z;
    const int n0   = blockIdx.x * 128;
    const int gb   = bq & ~3;
    const int qrow = n0 + warp * 32;
    const uint32_t sb = (uint32_t)__cvta_generic_to_shared(sm);

    uint32_t qf[2][8][4];
#pragma unroll
    for (int u = 0; u < 2; u++) {
        const uint32_t* qb = q + ((size_t)(bq * CN + qrow + u * 16)) * CD + h * CHD;
#pragma unroll
        for (int ks = 0; ks < 8; ks++) {
            int c = ks * 8 + t;
            qf[u][ks][0] = qb[(size_t)g * CD + c];
            qf[u][ks][1] = qb[(size_t)(g + 8) * CD + c];
            qf[u][ks][2] = qb[(size_t)g * CD + c + 4];
            qf[u][ks][3] = qb[(size_t)(g + 8) * CD + c + 4];
        }
    }

    float oa[2][8][4];
#pragma unroll
    for (int u = 0; u < 2; u++)
#pragma unroll
        for (int nt = 0; nt < 8; nt++)
#pragma unroll
            for (int r = 0; r < 4; r++) oa[u][nt][r] = 0.0f;
    float li[2][2] = {{0.0f, 0.0f}, {0.0f, 0.0f}};

    uint32_t* Pw = sm + 2 * AT_STAGE + warp * 32 * PPAD;
    const uint32_t pw_sb = sb + (uint32_t)(2 * AT_STAGE + warp * 32 * PPAD) * 4u;
    const int lrow = lane & 7;
    const int lmat = lane >> 3;
    const uint32_t kv_off = (uint32_t)(lrow * KPAD + lmat * 4) * 4u;
    const uint32_t p_off = (uint32_t)(((lmat & 1) * 8 + lrow) * PPAD + (lmat >> 1) * 4) * 4u;

    auto load_kv = [&](int kc, int stg) {
        const int m0 = kc * 64;
        const int kb = gb + (m0 >> 9);
        const int kn = m0 & 511;
        uint32_t ksm = sb + (uint32_t)(stg * AT_STAGE) * 4u;
        uint32_t vsm = ksm + AT_KV * 4u;
#pragma unroll
        for (int p = 0; p < 8; p++) {
            int idx = p * 128 + tid;
            int r   = idx >> 4;
            int c4  = (idx & 15) << 2;
            uint32_t off = (uint32_t)(r * KPAD + c4) * 4u;
            cp16(ksm + off, k + ((size_t)(kb * CN + kn + r)) * CD + h * CHD + c4);
            cp16(vsm + off, vt + ((size_t)((kb * CH + h) * CHD + r)) * CN + kn + c4);
        }
        CP_COMMIT();
    };

    load_kv(0, 0);
    int st = 0;

    for (int kc = 0; kc < 32; kc++) {
        CP_WAIT0();
        __syncthreads();
        if (kc < 31) load_kv(kc + 1, st ^ 1);

        const uint32_t ks_sb = sb + (uint32_t)(st * AT_STAGE) * 4u;
        const uint32_t vs_sb = ks_sb + AT_KV * 4u;

        float sacc[2][8][4];
#pragma unroll
        for (int u = 0; u < 2; u++)
#pragma unroll
            for (int nt = 0; nt < 8; nt++)
#pragma unroll
                for (int r = 0; r < 4; r++) sacc[u][nt][r] = 0.0f;
#pragma unroll
        for (int nt = 0; nt < 8; nt++) {
            uint32_t rowa = ks_sb + (uint32_t)(nt * 8 * KPAD) * 4u + kv_off;
#pragma unroll
            for (int kp = 0; kp < 4; kp++) {
                uint32_t kb4[4];
                ldsm_x4(kb4, rowa + (uint32_t)(kp * 16) * 4u);
                mma_tf32(sacc[0][nt], qf[0][2 * kp],     kb4);
                mma_tf32(sacc[0][nt], qf[0][2 * kp + 1], kb4 + 2);
                mma_tf32(sacc[1][nt], qf[1][2 * kp],     kb4);
                mma_tf32(sacc[1][nt], qf[1][2 * kp + 1], kb4 + 2);
            }
        }

#pragma unroll
        for (int u = 0; u < 2; u++) {
#pragma unroll
            for (int nt = 0; nt < 8; nt++) {
                float p0 = __expf(sacc[u][nt][0] - SOFT_SHIFT);
                float p1 = __expf(sacc[u][nt][1] - SOFT_SHIFT);
                float p2 = __expf(sacc[u][nt][2] - SOFT_SHIFT);
                float p3 = __expf(sacc[u][nt][3] - SOFT_SHIFT);
                li[u][0] += p0 + p1;
                li[u][1] += p2 + p3;
                int col = nt * 8 + 2 * t;
                uint2 w0 = {f2tf32(p0), f2tf32(p1)};
                uint2 w1 = {f2tf32(p2), f2tf32(p3)};
                *(uint2*)&Pw[(u * 16 + g) * PPAD + col]       = w0;
                *(uint2*)&Pw[(u * 16 + g + 8) * PPAD + col]   = w1;
            }
        }
        __syncwarp();

        uint32_t pf[2][8][4];
#pragma unroll
        for (int u = 0; u < 2; u++)
#pragma unroll
            for (int ks = 0; ks < 8; ks++)
                ldsm_x4(pf[u][ks],
                        pw_sb + (uint32_t)(u * 16 * PPAD) * 4u + p_off + (uint32_t)(ks * 8) * 4u);

#pragma unroll
        for (int nt = 0; nt < 8; nt++) {
            uint32_t rowv = vs_sb + (uint32_t)(nt * 8 * KPAD) * 4u + kv_off;
#pragma unroll
            for (int kp = 0; kp < 4; kp++) {
                uint32_t vb4[4];
                ldsm_x4(vb4, rowv + (uint32_t)(kp * 16) * 4u);
                mma_tf32(oa[0][nt], pf[0][2 * kp],     vb4);
                mma_tf32(oa[0][nt], pf[0][2 * kp + 1], vb4 + 2);
                mma_tf32(oa[1][nt], pf[1][2 * kp],     vb4);
                mma_tf32(oa[1][nt], pf[1][2 * kp + 1], vb4 + 2);
            }
        }
        __syncwarp();
        st ^= 1;
    }

#pragma unroll
    for (int u = 0; u < 2; u++) {
        float l0 = li[u][0], l1 = li[u][1];
        l0 += __shfl_xor_sync(0xffffffffu, l0, 1);
        l0 += __shfl_xor_sync(0xffffffffu, l0, 2);
        l1 += __shfl_xor_sync(0xffffffffu, l1, 1);
        l1 += __shfl_xor_sync(0xffffffffu, l1, 2);
        float inv0 = 1.0f / l0, inv1 = 1.0f / l1;
        uint32_t* ob = (uint32_t*)(o + ((size_t)(bq * CN + qrow + u * 16)) * CD + h * CHD);
#pragma unroll
        for (int nt = 0; nt < 8; nt++) {
            int col = nt * 8 + 2 * t;
            uint2 r0 = {f2tf32(oa[u][nt][0] * inv0), f2tf32(oa[u][nt][1] * inv0)};
            uint2 r1 = {f2tf32(oa[u][nt][2] * inv1), f2tf32(oa[u][nt][3] * inv1)};
            *(uint2*)(ob + (size_t)g * CD + col)       = r0;
            *(uint2*)(ob + (size_t)(g + 8) * CD + col) = r1;
        }
    }
}

// ---------------------------------------------------------------------------
// launch
// ---------------------------------------------------------------------------
extern "C" void kernel_launch(void* const* d_in, const int* in_sizes, int n_in,
                              void* d_out, int out_size)
{
    (void)in_sizes; (void)n_in; (void)out_size;
    const float* x    = (const float*)d_in[0];
    const float* mask = (const float*)d_in[1];
    const float* Wq   = (const float*)d_in[2];
    const float* bq   = (const float*)d_in[3];
    const float* Wk   = (const float*)d_in[4];
    const float* bk   = (const float*)d_in[5];
    const float* Wv   = (const float*)d_in[6];
    const float* bv   = (const float*)d_in[7];
    const float* Wo   = (const float*)d_in[8];
    const float* bo   = (const float*)d_in[9];
    const float* Wiq  = (const float*)d_in[10];
    const float* biq  = (const float*)d_in[11];
    const float* Wik  = (const float*)d_in[12];
    const float* bik  = (const float*)d_in[13];
    const float* emb  = (const float*)d_in[14];
    const float* qw   = (const float*)d_in[15];
    const float* kw   = (const float*)d_in[16];
    float* out = (float*)d_out;

    float *qp, *kp, *vtp, *op;
    uint32_t *xt, *wq, *wk, *wv, *wo;
    cudaGetSymbolAddress((void**)&qp,  g_q);
    cudaGetSymbolAddress((void**)&kp,  g_k);
    cudaGetSymbolAddress((void**)&vtp, g_vt);
    cudaGetSymbolAddress((void**)&op,  g_o);
    cudaGetSymbolAddress((void**)&xt,  g_xt);
    cudaGetSymbolAddress((void**)&wq,  g_wq);
    cudaGetSymbolAddress((void**)&wk,  g_wk);
    cudaGetSymbolAddress((void**)&wv,  g_wv);
    cudaGetSymbolAddress((void**)&wo,  g_wo);

    static bool attr_done = false;
    if (!attr_done) {
        cudaFuncSetAttribute(gemm_qkv, cudaFuncAttributeMaxDynamicSharedMemorySize, SMEM_GEMM);
        cudaFuncSetAttribute(gemm_o,   cudaFuncAttributeMaxDynamicSharedMemorySize, SMEM_GEMM);
        cudaFuncSetAttribute(attn_t,   cudaFuncAttributeMaxDynamicSharedMemorySize, SMEM_ATTN);
        attr_done = true;
    }

    dim3 gemm_grid(8, 32);

    zero_e2_k<<<16, 256>>>();

    cvt_x_k<<<4096, 256>>>(x, xt);
    wtr_k<<<dim3(32, 32, 4), 256>>>(Wq, Wk, Wv, Wo, wq, wk, wv, wo);

    // instance-gate precompute (rank-5 factorization), off the critical tail
    e2_k<<<512, 256>>>(emb, Wik);
    prep_k<<<129, 256>>>(Wiq, biq, bik);

    gemm_qkv<<<dim3(8, 32, 3), 256, SMEM_GEMM>>>(xt, wq, wk, wv, bq, bk, bv,
                                                 qw, kw, qp, kp, vtp);

    attn_t<<<dim3(4, 8, 16), 128, SMEM_ATTN>>>((const uint32_t*)qp, (const uint32_t*)kp,
                                               (const uint32_t*)vtp, op);

    uvw_k<<<512, 256>>>(op);
    gate_k<<<512, 256>>>(mask);

    gemm_o<<<gemm_grid, 256, SMEM_GEMM>>>((const uint32_t*)op, wo, bo, out);
}